// round 6
// baseline (speedup 1.0000x reference)
#include <cuda_runtime.h>
#include <cuda_bf16.h>
#include <math.h>
#include <stdint.h>

// Problem constants
#define BB   2
#define SS   2048
#define DIM  4096
#define NH   32
#define NKV  8
#define HD   128
#define NT   (BB*SS)          // 4096 tokens
#define QDIM (NH*HD)          // 4096
#define KDIM (NKV*HD)         // 1024

// ---------------- scratch (device globals; no allocation allowed) ----------
__device__ float g_Q[NT * QDIM];     // fp32 Q; reused as fp32 attention output
__device__ float g_K[NT * KDIM];
__device__ float g_V[NT * KDIM];
// bf16 attention operands
__device__ __nv_bfloat16 g_Qh[NT * QDIM];
__device__ __nv_bfloat16 g_Ql[NT * QDIM];
__device__ __nv_bfloat16 g_Kh[NT * KDIM];
__device__ __nv_bfloat16 g_Kl[NT * KDIM];
__device__ __nv_bfloat16 g_Vth[BB * NKV * HD * SS];  // [b][g][d][s]
__device__ __nv_bfloat16 g_Vtl[BB * NKV * HD * SS];
// int8 GEMM operands (16-bit fixed-point split: hi*256 + lo)
__device__ int8_t g_X1[NT * DIM];
__device__ int8_t g_X0[NT * DIM];
__device__ int8_t g_Wq1[QDIM * DIM];
__device__ int8_t g_Wq0[QDIM * DIM];
__device__ int8_t g_Wk1[KDIM * DIM];
__device__ int8_t g_Wk0[KDIM * DIM];
__device__ int8_t g_Wv1[KDIM * DIM];
__device__ int8_t g_Wv0[KDIM * DIM];
__device__ int8_t g_Wo1[DIM * QDIM];   // transposed [N=DIM][K=QDIM]
__device__ int8_t g_Wo0[DIM * QDIM];
__device__ int8_t g_A1[NT * QDIM];
__device__ int8_t g_A0[NT * QDIM];
// per-tensor maxabs (float bits in unsigned): 0=x 1=wq 2=wk 3=wv 4=wo 5=attn
__device__ unsigned g_max[8];

// ======================= PTX helpers =======================
__device__ __forceinline__ uint32_t smem_u32(const void* p) {
    uint32_t a;
    asm("{ .reg .u64 t; cvta.to.shared.u64 t, %1; cvt.u32.u64 %0, t; }" : "=r"(a) : "l"(p));
    return a;
}
__device__ __forceinline__ void cp_async16(uint32_t dst, const void* src) {
    asm volatile("cp.async.cg.shared.global [%0], [%1], 16;" :: "r"(dst), "l"(src));
}
#define CP_COMMIT() asm volatile("cp.async.commit_group;" ::: "memory")

__device__ __forceinline__ uint32_t sw128(uint32_t b) { return b ^ ((b >> 3) & 0x70); }

__device__ __forceinline__ float exp2a(float x) {
    float r;
    asm("ex2.approx.f32 %0, %1;" : "=f"(r) : "f"(x));
    return r;
}

#define LDSM4(r, addr) \
    asm volatile("ldmatrix.sync.aligned.m8n8.x4.shared.b16 {%0,%1,%2,%3}, [%4];" \
        : "=r"((r)[0]), "=r"((r)[1]), "=r"((r)[2]), "=r"((r)[3]) : "r"(addr))

#define MMA16816(c, a, b0, b1) \
    asm volatile("mma.sync.aligned.m16n8k16.row.col.f32.bf16.bf16.f32 " \
        "{%0,%1,%2,%3}, {%4,%5,%6,%7}, {%8,%9}, {%0,%1,%2,%3};" \
        : "+f"((c)[0]), "+f"((c)[1]), "+f"((c)[2]), "+f"((c)[3]) \
        : "r"((a)[0]), "r"((a)[1]), "r"((a)[2]), "r"((a)[3]), "r"(b0), "r"(b1))

#define IMMA16832(c, a, b0_, b1_) \
    asm volatile("mma.sync.aligned.m16n8k32.row.col.s32.s8.s8.s32 " \
        "{%0,%1,%2,%3}, {%4,%5,%6,%7}, {%8,%9}, {%0,%1,%2,%3};" \
        : "+r"((c)[0]), "+r"((c)[1]), "+r"((c)[2]), "+r"((c)[3]) \
        : "r"((a)[0]), "r"((a)[1]), "r"((a)[2]), "r"((a)[3]), "r"(b0_), "r"(b1_))

// =============== scale reduction / quantization ===============
__global__ void init_scales(unsigned* p) { if (threadIdx.x < 8) p[threadIdx.x] = 0; }

__global__ void maxabs_kernel(const float* __restrict__ X, int total4, unsigned* out)
{
    __shared__ unsigned sm[8];
    unsigned m = 0;
    for (int i = blockIdx.x * blockDim.x + threadIdx.x; i < total4; i += gridDim.x * blockDim.x) {
        float4 v = ((const float4*)X)[i];
        m = max(m, (unsigned)(__float_as_int(fabsf(v.x))));
        m = max(m, (unsigned)(__float_as_int(fabsf(v.y))));
        m = max(m, (unsigned)(__float_as_int(fabsf(v.z))));
        m = max(m, (unsigned)(__float_as_int(fabsf(v.w))));
    }
    #pragma unroll
    for (int o = 16; o; o >>= 1) m = max(m, __shfl_xor_sync(0xffffffffu, m, o));
    if ((threadIdx.x & 31) == 0) sm[threadIdx.x >> 5] = m;
    __syncthreads();
    if (threadIdx.x < 32) {
        unsigned v = (threadIdx.x < (blockDim.x >> 5)) ? sm[threadIdx.x] : 0;
        #pragma unroll
        for (int o = 4; o; o >>= 1) v = max(v, __shfl_xor_sync(0xffffffffu, v, o));
        if (threadIdx.x == 0) atomicMax(out, v);
    }
}

__device__ __forceinline__ void q16(float x, float inv, int8_t& hi, int8_t& lo)
{
    int q = __float2int_rn(x * inv);
    q = max(-32512, min(32512, q));
    int h = (q + 128) >> 8;
    hi = (int8_t)h;
    lo = (int8_t)(q - (h << 8));
}

__global__ void quant_rows(const float* __restrict__ X,
                           int8_t* __restrict__ X1, int8_t* __restrict__ X0,
                           int total4, const unsigned* __restrict__ mx)
{
    int i = blockIdx.x * blockDim.x + threadIdx.x;
    if (i >= total4) return;
    const float inv = 32512.f / __uint_as_float(*mx);
    float4 v = ((const float4*)X)[i];
    char4 h, l;
    int8_t a, b;
    q16(v.x, inv, a, b); h.x = a; l.x = b;
    q16(v.y, inv, a, b); h.y = a; l.y = b;
    q16(v.z, inv, a, b); h.z = a; l.z = b;
    q16(v.w, inv, a, b); h.w = a; l.w = b;
    ((char4*)X1)[i] = h;
    ((char4*)X0)[i] = l;
}

// W[K,N] fp32 -> transposed int8 pairs [N][K]
__global__ void quant_transpose(const float* __restrict__ W,
                                int8_t* __restrict__ T1, int8_t* __restrict__ T0,
                                int Kd, int Nd, const unsigned* __restrict__ mx)
{
    __shared__ float t[32][33];
    const int n0 = blockIdx.x * 32, k0 = blockIdx.y * 32;
    const int tx = threadIdx.x, ty = threadIdx.y;
    t[ty][tx] = W[(size_t)(k0 + ty) * Nd + n0 + tx];
    __syncthreads();
    const float inv = 32512.f / __uint_as_float(*mx);
    int8_t h, l;
    q16(t[tx][ty], inv, h, l);
    T1[(size_t)(n0 + ty) * Kd + k0 + tx] = h;
    T0[(size_t)(n0 + ty) * Kd + k0 + tx] = l;
}

// =============== int8 split-fixed-point IMMA GEMM ===============
// C[M,N] = sA*sB*(65536*ΣA1B1 + 256*Σ(A1B0+A0B1)); BK=128 int8 (128B rows).
#define GSMEM_BYTES (2 * 4 * 16384)

__device__ __forceinline__ void load_stage_i8(
    uint32_t buf, const int8_t* A1, const int8_t* A0,
    const int8_t* B1, const int8_t* B0,
    int row0, int col0, int K, int it, int tid)
{
    #pragma unroll 4
    for (int c = tid; c < 4096; c += 256) {
        const int t = c >> 10;            // 0:A1 1:A0 2:B1 3:B0
        const int idx = c & 1023;
        const int r = idx >> 3;           // 128 rows
        const int sg = idx & 7;           // 8 x 16B = 128B/row
        const int8_t* base = (t == 0) ? A1 : (t == 1) ? A0 : (t == 2) ? B1 : B0;
        const int grow = ((t < 2) ? row0 : col0) + r;
        const void* src = base + (size_t)grow * K + it * 128 + sg * 16;
        const uint32_t dst = buf + t * 16384 + sw128(r * 128 + sg * 16);
        cp_async16(dst, src);
    }
    CP_COMMIT();
}

__global__ __launch_bounds__(256) void gemm_i8(
    const int8_t* __restrict__ A1, const int8_t* __restrict__ A0,
    const int8_t* __restrict__ B1, const int8_t* __restrict__ B0,
    float* __restrict__ C, int M, int N, int K,
    const unsigned* __restrict__ mA, const unsigned* __restrict__ mB)
{
    extern __shared__ char smc[];
    const uint32_t sb = smem_u32(smc);
    const int tid = threadIdx.x;
    const int wid = tid >> 5;
    const int lane = tid & 31;
    const int row0 = blockIdx.y * 128;
    const int col0 = blockIdx.x * 128;
    const int wm0 = (wid >> 2) * 64;
    const int wn0 = (wid & 3) * 32;

    int acc1[4][4][4], acc2[4][4][4];
    #pragma unroll
    for (int i = 0; i < 4; i++)
        #pragma unroll
        for (int j = 0; j < 4; j++)
            #pragma unroll
            for (int r = 0; r < 4; r++) { acc1[i][j][r] = 0; acc2[i][j][r] = 0; }

    const int KT = K / 128;
    load_stage_i8(sb, A1, A0, B1, B0, row0, col0, K, 0, tid);

    for (int it = 0; it < KT; it++) {
        const uint32_t buf = sb + (it & 1) * 65536;
        if (it + 1 < KT) {
            load_stage_i8(sb + ((it + 1) & 1) * 65536, A1, A0, B1, B0, row0, col0, K, it + 1, tid);
            asm volatile("cp.async.wait_group 1;" ::: "memory");
        } else {
            asm volatile("cp.async.wait_group 0;" ::: "memory");
        }
        __syncthreads();

        const uint32_t a1b = buf;
        const uint32_t a0b = buf + 16384;
        const uint32_t b1b = buf + 32768;
        const uint32_t b0b = buf + 49152;

        #pragma unroll
        for (int kb = 0; kb < 4; kb++) {
            const int colb = kb * 32 + (lane >> 4) * 16;
            uint32_t a1f[4][4], a0f[4][4], b1f[2][4], b0f[2][4];
            #pragma unroll
            for (int mi = 0; mi < 4; mi++) {
                const uint32_t off = sw128((wm0 + mi * 16 + (lane & 15)) * 128 + colb);
                LDSM4(a1f[mi], a1b + off);
                LDSM4(a0f[mi], a0b + off);
            }
            #pragma unroll
            for (int np = 0; np < 2; np++) {
                const uint32_t off = sw128((wn0 + np * 16 + (lane & 15)) * 128 + colb);
                LDSM4(b1f[np], b1b + off);
                LDSM4(b0f[np], b0b + off);
            }
            #pragma unroll
            for (int mi = 0; mi < 4; mi++)
                #pragma unroll
                for (int nj = 0; nj < 4; nj++) {
                    const int np = nj >> 1, h = nj & 1;
                    IMMA16832(acc1[mi][nj], a1f[mi], b1f[np][h], b1f[np][2 + h]);
                }
            #pragma unroll
            for (int mi = 0; mi < 4; mi++)
                #pragma unroll
                for (int nj = 0; nj < 4; nj++) {
                    const int np = nj >> 1, h = nj & 1;
                    IMMA16832(acc2[mi][nj], a1f[mi], b0f[np][h], b0f[np][2 + h]);
                }
            #pragma unroll
            for (int mi = 0; mi < 4; mi++)
                #pragma unroll
                for (int nj = 0; nj < 4; nj++) {
                    const int np = nj >> 1, h = nj & 1;
                    IMMA16832(acc2[mi][nj], a0f[mi], b1f[np][h], b1f[np][2 + h]);
                }
        }
        __syncthreads();
    }

    const float sc = (__uint_as_float(*mA) * __uint_as_float(*mB)) / (32512.f * 32512.f);
    #pragma unroll
    for (int mi = 0; mi < 4; mi++) {
        #pragma unroll
        for (int nj = 0; nj < 4; nj++) {
            const int row = row0 + wm0 + mi * 16 + (lane >> 2);
            const int col = col0 + wn0 + nj * 8 + (lane & 3) * 2;
            float e0 = sc * (65536.f * (float)acc1[mi][nj][0] + 256.f * (float)acc2[mi][nj][0]);
            float e1 = sc * (65536.f * (float)acc1[mi][nj][1] + 256.f * (float)acc2[mi][nj][1]);
            float e2 = sc * (65536.f * (float)acc1[mi][nj][2] + 256.f * (float)acc2[mi][nj][2]);
            float e3 = sc * (65536.f * (float)acc1[mi][nj][3] + 256.f * (float)acc2[mi][nj][3]);
            *(float2*)(C + (size_t)row * N + col)       = make_float2(e0, e1);
            *(float2*)(C + (size_t)(row + 8) * N + col) = make_float2(e2, e3);
        }
    }
}

// =============== RoPE + bf16 hi/lo split =====================================
__global__ void rope_split(const float* __restrict__ X,
                           const float* __restrict__ cosT,
                           const float* __restrict__ sinT,
                           __nv_bfloat16* __restrict__ Xh,
                           __nv_bfloat16* __restrict__ Xl, int nHeads)
{
    int idx = blockIdx.x * blockDim.x + threadIdx.x;
    int total = NT * nHeads * 32;
    if (idx >= total) return;
    int j = idx & 31;
    int hh = (idx >> 5) % nHeads;
    int t = idx / (32 * nHeads);
    int s = t & (SS - 1);
    int d = 2 * j;

    const float* p = X + (size_t)t * (nHeads * HD) + hh * HD;
    float x0 = p[d], x1 = p[d + 1], y0 = p[d + 64], y1 = p[d + 65];
    const float* cp = cosT + s * HD;
    const float* sp = sinT + s * HD;
    float r0 = x0 * cp[d]      - y0 * sp[d];
    float r1 = x1 * cp[d + 1]  - y1 * sp[d + 1];
    float r2 = y0 * cp[d + 64] + x0 * sp[d + 64];
    float r3 = y1 * cp[d + 65] + x1 * sp[d + 65];

    size_t o0 = (size_t)t * (nHeads * HD) + hh * HD + d;
    __nv_bfloat16 h0 = __float2bfloat16(r0), h1 = __float2bfloat16(r1);
    __nv_bfloat16 h2 = __float2bfloat16(r2), h3 = __float2bfloat16(r3);
    __nv_bfloat16 q0 = __float2bfloat16(r0 - __bfloat162float(h0));
    __nv_bfloat16 q1 = __float2bfloat16(r1 - __bfloat162float(h1));
    __nv_bfloat16 q2 = __float2bfloat16(r2 - __bfloat162float(h2));
    __nv_bfloat16 q3 = __float2bfloat16(r3 - __bfloat162float(h3));
    __nv_bfloat16 hp[2] = {h0, h1}; *(uint32_t*)(Xh + o0) = *(uint32_t*)hp;
    __nv_bfloat16 lp[2] = {q0, q1}; *(uint32_t*)(Xl + o0) = *(uint32_t*)lp;
    __nv_bfloat16 hp2[2] = {h2, h3}; *(uint32_t*)(Xh + o0 + 64) = *(uint32_t*)hp2;
    __nv_bfloat16 lp2[2] = {q2, q3}; *(uint32_t*)(Xl + o0 + 64) = *(uint32_t*)lp2;
}

// =============== V: fp32 [NT][KDIM] -> transposed bf16 hi/lo [b][g][d][s] ====
__global__ void v_split_t(const float* __restrict__ V,
                          __nv_bfloat16* __restrict__ Vth,
                          __nv_bfloat16* __restrict__ Vtl)
{
    __shared__ float t[32][33];
    const int c0 = blockIdx.x * 32;
    const int r0 = blockIdx.y * 32;
    const int tx = threadIdx.x, ty = threadIdx.y;
    t[ty][tx] = V[(size_t)(r0 + ty) * KDIM + c0 + tx];
    __syncthreads();
    float v = t[tx][ty];              // V[r0+tx][c0+ty]
    int tok = r0 + tx;
    int b = tok >> 11;
    int s = tok & (SS - 1);
    int col = c0 + ty;
    int g = col >> 7;
    int d = col & 127;
    size_t oidx = ((size_t)((b * NKV + g) * HD) + d) * SS + s;
    __nv_bfloat16 hi = __float2bfloat16(v);
    Vth[oidx] = hi;
    Vtl[oidx] = __float2bfloat16(v - __bfloat162float(hi));
}

// ---------------- HMMA flash attention (3-term split, causal, GQA) ----------
#define ASMEM_BYTES (196608)

__device__ __forceinline__ void attn_load_kv(
    uint32_t st, const __nv_bfloat16* Kh, const __nv_bfloat16* Kl,
    const __nv_bfloat16* Vth, const __nv_bfloat16* Vtl,
    int b, int g, int kt, int tid)
{
    const int tk0 = b * SS + kt * 64;
    #pragma unroll 4
    for (int c = tid; c < 2048; c += 256) {
        int hl = c >> 10, cc = c & 1023;
        int r = cc >> 4, sg = cc & 15, half = sg >> 3, sgi = sg & 7;
        const __nv_bfloat16* base = hl ? Kl : Kh;
        const void* src = base + (size_t)(tk0 + r) * KDIM + g * HD + half * 64 + sgi * 8;
        uint32_t dst = st + hl * 16384 + half * 8192 + sw128(r * 128 + sgi * 16);
        cp_async16(dst, src);
    }
    const size_t vrow0 = (size_t)((b * NKV + g) * HD) * SS;
    #pragma unroll 4
    for (int c = tid; c < 2048; c += 256) {
        int hl = c >> 10, cc = c & 1023;
        int d = cc >> 3, sg = cc & 7;
        const __nv_bfloat16* base = hl ? Vtl : Vth;
        const void* src = base + vrow0 + (size_t)d * SS + kt * 64 + sg * 8;
        uint32_t dst = st + 32768 + hl * 16384 + sw128(d * 128 + sg * 16);
        cp_async16(dst, src);
    }
    CP_COMMIT();
}

__global__ __launch_bounds__(256, 1) void attn_mma(
    const __nv_bfloat16* __restrict__ Qh, const __nv_bfloat16* __restrict__ Ql,
    const __nv_bfloat16* __restrict__ Kh, const __nv_bfloat16* __restrict__ Kl,
    const __nv_bfloat16* __restrict__ Vth, const __nv_bfloat16* __restrict__ Vtl,
    float* __restrict__ AO)
{
    extern __shared__ char smc[];
    const uint32_t sb = smem_u32(smc);
    const int tid = threadIdx.x, wid = tid >> 5, lane = tid & 31;
    const int bid = blockIdx.x;
    const int qb = 15 - (bid >> 6);     // heavy-first
    const int bh = bid & 63;
    const int b = bh >> 5, h = bh & 31, g = h >> 2;
    const int tok0 = b * SS + qb * 128;
    const int KT = 2 * qb + 2;
    const float SCL = 0.08838834764831845f * 1.4426950408889634f;

    // Q load: hi/lo x 128 rows x 16 chunks(8 bf16) = 4096 chunks
    #pragma unroll 4
    for (int c = tid; c < 4096; c += 256) {
        int hl = c >> 11, cc = c & 2047;
        int r = cc >> 4, sg = cc & 15, half = sg >> 3, sgi = sg & 7;
        const __nv_bfloat16* base = hl ? Ql : Qh;
        const void* src = base + (size_t)(tok0 + r) * QDIM + h * HD + half * 64 + sgi * 8;
        uint32_t dst = sb + hl * 32768 + half * 16384 + sw128(r * 128 + sgi * 16);
        cp_async16(dst, src);
    }
    attn_load_kv(sb + 65536, Kh, Kl, Vth, Vtl, b, g, 0, tid);

    float o[16][4];
    #pragma unroll
    for (int nd = 0; nd < 16; nd++)
        #pragma unroll
        for (int e = 0; e < 4; e++) o[nd][e] = 0.f;
    float m0 = -1e30f, m1 = -1e30f, l0 = 0.f, l1 = 0.f;

    const int qg0 = qb * 128 + wid * 16 + (lane >> 2);
    const int qg1 = qg0 + 8;

    for (int kt = 0; kt < KT; kt++) {
        if (kt + 1 < KT) {
            attn_load_kv(sb + 65536 + ((kt + 1) & 1) * 65536, Kh, Kl, Vth, Vtl, b, g, kt + 1, tid);
            asm volatile("cp.async.wait_group 1;" ::: "memory");
        } else {
            asm volatile("cp.async.wait_group 0;" ::: "memory");
        }
        __syncthreads();

        const uint32_t st = sb + 65536 + (kt & 1) * 65536;
        const bool skip = kt * 64 > qb * 128 + wid * 16 + 15;

        if (!skip) {
            float s[8][4];
            #pragma unroll
            for (int nj = 0; nj < 8; nj++)
                #pragma unroll
                for (int e = 0; e < 4; e++) s[nj][e] = 0.f;

            #pragma unroll
            for (int k16 = 0; k16 < 8; k16++) {
                const int half = k16 >> 2;
                const int cb = (k16 & 3) * 32 + (lane >> 4) * 16;
                const uint32_t qoff = sw128((wid * 16 + (lane & 15)) * 128 + cb);
                uint32_t ah[4], al[4];
                LDSM4(ah, sb + half * 16384 + qoff);
                LDSM4(al, sb + 32768 + half * 16384 + qoff);
                uint32_t bhf[4][4], blf[4][4];
                #pragma unroll
                for (int c = 0; c < 4; c++) {
                    const uint32_t koff = sw128((c * 16 + (lane & 15)) * 128 + cb);
                    LDSM4(bhf[c], st + half * 8192 + koff);
                    LDSM4(blf[c], st + 16384 + half * 8192 + koff);
                }
                #pragma unroll
                for (int nj = 0; nj < 8; nj++) {
                    const int np = nj >> 1, h2 = nj & 1;
                    MMA16816(s[nj], ah, bhf[np][h2], bhf[np][2 + h2]);
                }
                #pragma unroll
                for (int nj = 0; nj < 8; nj++) {
                    const int np = nj >> 1, h2 = nj & 1;
                    MMA16816(s[nj], al, bhf[np][h2], bhf[np][2 + h2]);
                }
                #pragma unroll
                for (int nj = 0; nj < 8; nj++) {
                    const int np = nj >> 1, h2 = nj & 1;
                    MMA16816(s[nj], ah, blf[np][h2], blf[np][2 + h2]);
                }
            }

            const bool domask = (kt * 64 + 63) > qg0;
            #pragma unroll
            for (int nj = 0; nj < 8; nj++) {
                #pragma unroll
                for (int e = 0; e < 4; e++) s[nj][e] *= SCL;
                if (domask) {
                    const int kc = kt * 64 + nj * 8 + (lane & 3) * 2;
                    if (kc     > qg0) s[nj][0] = -1e30f;
                    if (kc + 1 > qg0) s[nj][1] = -1e30f;
                    if (kc     > qg1) s[nj][2] = -1e30f;
                    if (kc + 1 > qg1) s[nj][3] = -1e30f;
                }
            }
            float mx0 = -1e30f, mx1 = -1e30f;
            #pragma unroll
            for (int nj = 0; nj < 8; nj++) {
                mx0 = fmaxf(mx0, fmaxf(s[nj][0], s[nj][1]));
                mx1 = fmaxf(mx1, fmaxf(s[nj][2], s[nj][3]));
            }
            mx0 = fmaxf(mx0, __shfl_xor_sync(0xffffffffu, mx0, 1));
            mx0 = fmaxf(mx0, __shfl_xor_sync(0xffffffffu, mx0, 2));
            mx1 = fmaxf(mx1, __shfl_xor_sync(0xffffffffu, mx1, 1));
            mx1 = fmaxf(mx1, __shfl_xor_sync(0xffffffffu, mx1, 2));
            const float nm0 = fmaxf(m0, mx0), nm1 = fmaxf(m1, mx1);
            const float c0 = exp2a(m0 - nm0), c1 = exp2a(m1 - nm1);
            float rs0 = 0.f, rs1 = 0.f;
            #pragma unroll
            for (int nj = 0; nj < 8; nj++) {
                s[nj][0] = exp2a(s[nj][0] - nm0);
                s[nj][1] = exp2a(s[nj][1] - nm0);
                s[nj][2] = exp2a(s[nj][2] - nm1);
                s[nj][3] = exp2a(s[nj][3] - nm1);
                rs0 += s[nj][0] + s[nj][1];
                rs1 += s[nj][2] + s[nj][3];
            }
            rs0 += __shfl_xor_sync(0xffffffffu, rs0, 1);
            rs0 += __shfl_xor_sync(0xffffffffu, rs0, 2);
            rs1 += __shfl_xor_sync(0xffffffffu, rs1, 1);
            rs1 += __shfl_xor_sync(0xffffffffu, rs1, 2);
            m0 = nm0; m1 = nm1;
            l0 = l0 * c0 + rs0;
            l1 = l1 * c1 + rs1;
            #pragma unroll
            for (int nd = 0; nd < 16; nd++) {
                o[nd][0] *= c0; o[nd][1] *= c0;
                o[nd][2] *= c1; o[nd][3] *= c1;
            }

            #pragma unroll
            for (int j2 = 0; j2 < 4; j2++) {
                const int n0 = 2 * j2, n1 = 2 * j2 + 1;
                uint32_t aPh[4], aPl[4];
                __nv_bfloat162 t0 = __floats2bfloat162_rn(s[n0][0], s[n0][1]);
                __nv_bfloat162 t1 = __floats2bfloat162_rn(s[n0][2], s[n0][3]);
                __nv_bfloat162 t2 = __floats2bfloat162_rn(s[n1][0], s[n1][1]);
                __nv_bfloat162 t3 = __floats2bfloat162_rn(s[n1][2], s[n1][3]);
                aPh[0] = *(uint32_t*)&t0; aPh[1] = *(uint32_t*)&t1;
                aPh[2] = *(uint32_t*)&t2; aPh[3] = *(uint32_t*)&t3;
                __nv_bfloat162 u0 = __floats2bfloat162_rn(s[n0][0] - __bfloat162float(t0.x),
                                                          s[n0][1] - __bfloat162float(t0.y));
                __nv_bfloat162 u1 = __floats2bfloat162_rn(s[n0][2] - __bfloat162float(t1.x),
                                                          s[n0][3] - __bfloat162float(t1.y));
                __nv_bfloat162 u2 = __floats2bfloat162_rn(s[n1][0] - __bfloat162float(t2.x),
                                                          s[n1][1] - __bfloat162float(t2.y));
                __nv_bfloat162 u3 = __floats2bfloat162_rn(s[n1][2] - __bfloat162float(t3.x),
                                                          s[n1][3] - __bfloat162float(t3.y));
                aPl[0] = *(uint32_t*)&u0; aPl[1] = *(uint32_t*)&u1;
                aPl[2] = *(uint32_t*)&u2; aPl[3] = *(uint32_t*)&u3;

                #pragma unroll
                for (int c = 0; c < 8; c++) {
                    const uint32_t voff = sw128((c * 16 + (lane & 15)) * 128 + j2 * 32 + (lane >> 4) * 16);
                    uint32_t vh[4], vl[4];
                    LDSM4(vh, st + 32768 + voff);
                    LDSM4(vl, st + 49152 + voff);
                    MMA16816(o[2 * c],     aPh, vh[0], vh[2]);
                    MMA16816(o[2 * c + 1], aPh, vh[1], vh[3]);
                    MMA16816(o[2 * c],     aPl, vh[0], vh[2]);
                    MMA16816(o[2 * c + 1], aPl, vh[1], vh[3]);
                    MMA16816(o[2 * c],     aPh, vl[0], vl[2]);
                    MMA16816(o[2 * c + 1], aPh, vl[1], vl[3]);
                }
            }
        }
        __syncthreads();
    }

    // epilogue: normalize, write fp32 (quantized later for Wo IMMA GEMM)
    const float il0 = 1.f / l0, il1 = 1.f / l1;
    const int row0g = tok0 + wid * 16 + (lane >> 2);
    #pragma unroll
    for (int nd = 0; nd < 16; nd++) {
        const int col = h * HD + nd * 8 + (lane & 3) * 2;
        *(float2*)(AO + (size_t)row0g * QDIM + col) =
            make_float2(o[nd][0] * il0, o[nd][1] * il0);
        *(float2*)(AO + (size_t)(row0g + 8) * QDIM + col) =
            make_float2(o[nd][2] * il1, o[nd][3] * il1);
    }
}

// ---------------- launcher ---------------------------------------------------
extern "C" void kernel_launch(void* const* d_in, const int* in_sizes, int n_in,
                              void* d_out, int out_size)
{
    const float* x    = (const float*)d_in[0];
    const float* cosT = (const float*)d_in[1];
    const float* sinT = (const float*)d_in[2];
    const float* Wq   = (const float*)d_in[3];
    const float* Wk   = (const float*)d_in[4];
    const float* Wv   = (const float*)d_in[5];
    const float* Wo   = (const float*)d_in[6];
    float* out = (float*)d_out;

    float *Q, *K, *V;
    __nv_bfloat16 *Qh, *Ql, *Khb, *Klb, *Vth, *Vtl;
    int8_t *X1, *X0, *Wq1, *Wq0, *Wk1, *Wk0, *Wv1, *Wv0, *Wo1, *Wo0, *A1, *A0;
    unsigned* mx;
    cudaGetSymbolAddress((void**)&Q, g_Q);
    cudaGetSymbolAddress((void**)&K, g_K);
    cudaGetSymbolAddress((void**)&V, g_V);
    cudaGetSymbolAddress((void**)&Qh, g_Qh);
    cudaGetSymbolAddress((void**)&Ql, g_Ql);
    cudaGetSymbolAddress((void**)&Khb, g_Kh);
    cudaGetSymbolAddress((void**)&Klb, g_Kl);
    cudaGetSymbolAddress((void**)&Vth, g_Vth);
    cudaGetSymbolAddress((void**)&Vtl, g_Vtl);
    cudaGetSymbolAddress((void**)&X1, g_X1);
    cudaGetSymbolAddress((void**)&X0, g_X0);
    cudaGetSymbolAddress((void**)&Wq1, g_Wq1);
    cudaGetSymbolAddress((void**)&Wq0, g_Wq0);
    cudaGetSymbolAddress((void**)&Wk1, g_Wk1);
    cudaGetSymbolAddress((void**)&Wk0, g_Wk0);
    cudaGetSymbolAddress((void**)&Wv1, g_Wv1);
    cudaGetSymbolAddress((void**)&Wv0, g_Wv0);
    cudaGetSymbolAddress((void**)&Wo1, g_Wo1);
    cudaGetSymbolAddress((void**)&Wo0, g_Wo0);
    cudaGetSymbolAddress((void**)&A1, g_A1);
    cudaGetSymbolAddress((void**)&A0, g_A0);
    cudaGetSymbolAddress((void**)&mx, g_max);

    cudaFuncSetAttribute(gemm_i8, cudaFuncAttributeMaxDynamicSharedMemorySize, GSMEM_BYTES);
    cudaFuncSetAttribute(attn_mma, cudaFuncAttributeMaxDynamicSharedMemorySize, ASMEM_BYTES);

    // scales
    init_scales<<<1, 32>>>(mx);
    maxabs_kernel<<<512, 256>>>(x,  NT * DIM / 4,   mx + 0);
    maxabs_kernel<<<512, 256>>>(Wq, DIM * QDIM / 4, mx + 1);
    maxabs_kernel<<<512, 256>>>(Wk, DIM * KDIM / 4, mx + 2);
    maxabs_kernel<<<512, 256>>>(Wv, DIM * KDIM / 4, mx + 3);
    maxabs_kernel<<<512, 256>>>(Wo, QDIM * DIM / 4, mx + 4);

    // quantize operands
    quant_rows<<<NT * DIM / 4 / 256, 256>>>(x, X1, X0, NT * DIM / 4, mx + 0);
    quant_transpose<<<dim3(QDIM / 32, DIM / 32), dim3(32, 32)>>>(Wq, Wq1, Wq0, DIM, QDIM, mx + 1);
    quant_transpose<<<dim3(KDIM / 32, DIM / 32), dim3(32, 32)>>>(Wk, Wk1, Wk0, DIM, KDIM, mx + 2);
    quant_transpose<<<dim3(KDIM / 32, DIM / 32), dim3(32, 32)>>>(Wv, Wv1, Wv0, DIM, KDIM, mx + 3);
    quant_transpose<<<dim3(DIM / 32, QDIM / 32), dim3(32, 32)>>>(Wo, Wo1, Wo0, QDIM, DIM, mx + 4);

    // QKV projections (IMMA int8 split)
    gemm_i8<<<dim3(QDIM / 128, NT / 128), 256, GSMEM_BYTES>>>(X1, X0, Wq1, Wq0, Q, NT, QDIM, DIM, mx + 0, mx + 1);
    gemm_i8<<<dim3(KDIM / 128, NT / 128), 256, GSMEM_BYTES>>>(X1, X0, Wk1, Wk0, K, NT, KDIM, DIM, mx + 0, mx + 2);
    gemm_i8<<<dim3(KDIM / 128, NT / 128), 256, GSMEM_BYTES>>>(X1, X0, Wv1, Wv0, V, NT, KDIM, DIM, mx + 0, mx + 3);

    // RoPE + split to bf16 operands
    rope_split<<<(NT * NH * 32 + 255) / 256, 256>>>(Q, cosT, sinT, Qh, Ql, NH);
    rope_split<<<(NT * NKV * 32 + 255) / 256, 256>>>(K, cosT, sinT, Khb, Klb, NKV);
    v_split_t<<<dim3(KDIM / 32, NT / 32), dim3(32, 32)>>>(V, Vth, Vtl);

    // HMMA flash attention -> fp32 output (reuses g_Q)
    attn_mma<<<1024, 256, ASMEM_BYTES>>>(Qh, Ql, Khb, Klb, Vth, Vtl, Q);

    // quantize attention output, then Wo projection (IMMA)
    maxabs_kernel<<<512, 256>>>(Q, NT * QDIM / 4, mx + 5);
    quant_rows<<<NT * QDIM / 4 / 256, 256>>>(Q, A1, A0, NT * QDIM / 4, mx + 5);
    gemm_i8<<<dim3(DIM / 128, NT / 128), 256, GSMEM_BYTES>>>(A1, A0, Wo1, Wo0, out, NT, DIM, QDIM, mx + 5, mx + 4);
}

// round 7
// speedup vs baseline: 2.0831x; 2.0831x over previous
#include <cuda_runtime.h>
#include <cuda_bf16.h>
#include <math.h>
#include <stdint.h>

// Problem constants
#define BB   2
#define SS   2048
#define DIM  4096
#define NH   32
#define NKV  8
#define HD   128
#define NT   (BB*SS)          // 4096 tokens
#define QDIM (NH*HD)          // 4096
#define KDIM (NKV*HD)         // 1024

// ---------------- scratch (device globals; no allocation allowed) ----------
__device__ float g_Q[NT * QDIM];
__device__ float g_K[NT * KDIM];
__device__ float g_V[NT * KDIM];
__device__ __nv_bfloat16 g_xh[NT * DIM];
__device__ __nv_bfloat16 g_xl[NT * DIM];
__device__ __nv_bfloat16 g_Wqh[QDIM * DIM];
__device__ __nv_bfloat16 g_Wql[QDIM * DIM];
__device__ __nv_bfloat16 g_Wkh[KDIM * DIM];
__device__ __nv_bfloat16 g_Wkl[KDIM * DIM];
__device__ __nv_bfloat16 g_Wvh[KDIM * DIM];
__device__ __nv_bfloat16 g_Wvl[KDIM * DIM];
__device__ __nv_bfloat16 g_Woh[DIM * QDIM];   // transposed: [N=DIM rows][K=QDIM]
__device__ __nv_bfloat16 g_Wol[DIM * QDIM];
__device__ __nv_bfloat16 g_Ah[NT * QDIM];     // attention out hi
__device__ __nv_bfloat16 g_Al[NT * QDIM];     // attention out lo
// bf16 attention operands
__device__ __nv_bfloat16 g_Qh[NT * QDIM];
__device__ __nv_bfloat16 g_Ql[NT * QDIM];
__device__ __nv_bfloat16 g_Kh[NT * KDIM];
__device__ __nv_bfloat16 g_Kl[NT * KDIM];
__device__ __nv_bfloat16 g_Vth[BB * NKV * HD * SS];  // [b][g][d][s]
__device__ __nv_bfloat16 g_Vtl[BB * NKV * HD * SS];

// ======================= PTX helpers =======================
__device__ __forceinline__ uint32_t smem_u32(const void* p) {
    uint32_t a;
    asm("{ .reg .u64 t; cvta.to.shared.u64 t, %1; cvt.u32.u64 %0, t; }" : "=r"(a) : "l"(p));
    return a;
}
__device__ __forceinline__ void cp_async16(uint32_t dst, const void* src) {
    asm volatile("cp.async.cg.shared.global [%0], [%1], 16;" :: "r"(dst), "l"(src));
}
#define CP_COMMIT() asm volatile("cp.async.commit_group;" ::: "memory")

__device__ __forceinline__ uint32_t sw128(uint32_t b) { return b ^ ((b >> 3) & 0x70); }

__device__ __forceinline__ float exp2a(float x) {
    float r;
    asm("ex2.approx.f32 %0, %1;" : "=f"(r) : "f"(x));
    return r;
}

#define LDSM4(r, addr) \
    asm volatile("ldmatrix.sync.aligned.m8n8.x4.shared.b16 {%0,%1,%2,%3}, [%4];" \
        : "=r"((r)[0]), "=r"((r)[1]), "=r"((r)[2]), "=r"((r)[3]) : "r"(addr))

#define MMA16816(c, a, b0, b1) \
    asm volatile("mma.sync.aligned.m16n8k16.row.col.f32.bf16.bf16.f32 " \
        "{%0,%1,%2,%3}, {%4,%5,%6,%7}, {%8,%9}, {%0,%1,%2,%3};" \
        : "+f"((c)[0]), "+f"((c)[1]), "+f"((c)[2]), "+f"((c)[3]) \
        : "r"((a)[0]), "r"((a)[1]), "r"((a)[2]), "r"((a)[3]), "r"(b0), "r"(b1))

// =============== split-precision HMMA GEMM, 128x256 tile ===============
// C[M,N] = (Ah+Al)[M,K] * (Bh+Bl)^T, B tensors [N,K] row-major bf16.
// 3-term: Ah*Bh + Al*Bh + Ah*Bl, fp32 accumulation.
// CTA tile 128x256, warp tile 64x64 (8 warps 2x4), BK=64, double buffer.
// smem/stage: Ah 16K | Al 16K | Bh 32K | Bl 32K = 96KB; 2 stages = 192KB.
#define GSMEM_BYTES (2 * 98304)

__device__ __forceinline__ void load_stage(
    uint32_t buf, const __nv_bfloat16* Ah, const __nv_bfloat16* Al,
    const __nv_bfloat16* Bh, const __nv_bfloat16* Bl,
    int row0, int col0, int K, int it, int tid)
{
    #pragma unroll 8
    for (int c = tid; c < 6144; c += 256) {
        const __nv_bfloat16* base;
        int grow;
        uint32_t dst;
        if (c < 2048) {
            const int pl = c >> 10;           // 0:Ah 1:Al
            const int idx = c & 1023;
            const int r = idx >> 3;           // 0..127
            const int sg = idx & 7;
            base = pl ? Al : Ah;
            grow = row0 + r;
            dst = buf + pl * 16384 + sw128(r * 128 + sg * 16);
            cp_async16(dst, base + (size_t)grow * K + it * 64 + sg * 8);
        } else {
            const int cb = c - 2048;
            const int pl = cb >> 11;          // 0:Bh 1:Bl
            const int idx = cb & 2047;
            const int r = idx >> 3;           // 0..255
            const int sg = idx & 7;
            base = pl ? Bl : Bh;
            grow = col0 + r;
            dst = buf + 32768 + pl * 32768 + sw128(r * 128 + sg * 16);
            cp_async16(dst, base + (size_t)grow * K + it * 64 + sg * 8);
        }
    }
    CP_COMMIT();
}

__global__ __launch_bounds__(256, 1) void gemm_bf16x3(
    const __nv_bfloat16* __restrict__ Ah, const __nv_bfloat16* __restrict__ Al,
    const __nv_bfloat16* __restrict__ Bh, const __nv_bfloat16* __restrict__ Bl,
    float* __restrict__ C, int M, int N, int K)
{
    extern __shared__ char smc[];
    const uint32_t sb = smem_u32(smc);
    const int tid = threadIdx.x;
    const int wid = tid >> 5;
    const int lane = tid & 31;
    const int row0 = blockIdx.y * 128;
    const int col0 = blockIdx.x * 256;

    const int wm0 = (wid >> 2) * 64;   // 0 or 64
    const int wn0 = (wid & 3) * 64;    // 0,64,128,192

    float acc[4][8][4];
    #pragma unroll
    for (int i = 0; i < 4; i++)
        #pragma unroll
        for (int j = 0; j < 8; j++)
            #pragma unroll
            for (int r = 0; r < 4; r++) acc[i][j][r] = 0.f;

    const int KT = K / 64;
    load_stage(sb, Ah, Al, Bh, Bl, row0, col0, K, 0, tid);

    for (int it = 0; it < KT; it++) {
        const uint32_t buf = sb + (it & 1) * 98304;
        if (it + 1 < KT) {
            load_stage(sb + ((it + 1) & 1) * 98304, Ah, Al, Bh, Bl, row0, col0, K, it + 1, tid);
            asm volatile("cp.async.wait_group 1;" ::: "memory");
        } else {
            asm volatile("cp.async.wait_group 0;" ::: "memory");
        }
        __syncthreads();

        const uint32_t aHb = buf;
        const uint32_t aLb = buf + 16384;
        const uint32_t bHb = buf + 32768;
        const uint32_t bLb = buf + 65536;

        #pragma unroll
        for (int k16 = 0; k16 < 4; k16++) {
            const int colb = k16 * 32 + (lane >> 4) * 16;
            uint32_t ah[4][4], al[4][4];
            #pragma unroll
            for (int mi = 0; mi < 4; mi++) {
                const uint32_t off = sw128((wm0 + mi * 16 + (lane & 15)) * 128 + colb);
                LDSM4(ah[mi], aHb + off);
                LDSM4(al[mi], aLb + off);
            }
            #pragma unroll
            for (int hb = 0; hb < 2; hb++) {
                uint32_t bh[2][4], bl[2][4];
                #pragma unroll
                for (int np = 0; np < 2; np++) {
                    const uint32_t off =
                        sw128((wn0 + hb * 32 + np * 16 + (lane & 15)) * 128 + colb);
                    LDSM4(bh[np], bHb + off);
                    LDSM4(bl[np], bLb + off);
                }
                #pragma unroll
                for (int mi = 0; mi < 4; mi++)
                    #pragma unroll
                    for (int nj = 0; nj < 4; nj++) {
                        const int np = nj >> 1, h = nj & 1;
                        MMA16816(acc[mi][hb * 4 + nj], ah[mi], bh[np][h], bh[np][2 + h]);
                    }
                #pragma unroll
                for (int mi = 0; mi < 4; mi++)
                    #pragma unroll
                    for (int nj = 0; nj < 4; nj++) {
                        const int np = nj >> 1, h = nj & 1;
                        MMA16816(acc[mi][hb * 4 + nj], al[mi], bh[np][h], bh[np][2 + h]);
                    }
                #pragma unroll
                for (int mi = 0; mi < 4; mi++)
                    #pragma unroll
                    for (int nj = 0; nj < 4; nj++) {
                        const int np = nj >> 1, h = nj & 1;
                        MMA16816(acc[mi][hb * 4 + nj], ah[mi], bl[np][h], bl[np][2 + h]);
                    }
            }
        }
        __syncthreads();
    }

    #pragma unroll
    for (int mi = 0; mi < 4; mi++) {
        #pragma unroll
        for (int nj = 0; nj < 8; nj++) {
            const int row = row0 + wm0 + mi * 16 + (lane >> 2);
            const int col = col0 + wn0 + nj * 8 + (lane & 3) * 2;
            *(float2*)(C + (size_t)row * N + col)       = make_float2(acc[mi][nj][0], acc[mi][nj][1]);
            *(float2*)(C + (size_t)(row + 8) * N + col) = make_float2(acc[mi][nj][2], acc[mi][nj][3]);
        }
    }
}

// =============== fp32 -> bf16 hi/lo split (row-major) ===========
__global__ void split_rows(const float* __restrict__ X,
                           __nv_bfloat16* __restrict__ Xh,
                           __nv_bfloat16* __restrict__ Xl, int total4)
{
    int i = blockIdx.x * blockDim.x + threadIdx.x;
    if (i >= total4) return;
    float4 v = *(const float4*)(X + (size_t)i * 4);
    __nv_bfloat16 h[4], l[4];
    float vv[4] = {v.x, v.y, v.z, v.w};
    #pragma unroll
    for (int j = 0; j < 4; j++) {
        h[j] = __float2bfloat16(vv[j]);
        l[j] = __float2bfloat16(vv[j] - __bfloat162float(h[j]));
    }
    *(uint2*)(Xh + (size_t)i * 4) = *(uint2*)h;
    *(uint2*)(Xl + (size_t)i * 4) = *(uint2*)l;
}

// =============== transpose + split: W[K,N] fp32 -> T_hi/lo [N,K] bf16 ========
__global__ void transpose_split(const float* __restrict__ W,
                                __nv_bfloat16* __restrict__ Th,
                                __nv_bfloat16* __restrict__ Tl, int Kd, int Nd)
{
    __shared__ float t[32][33];
    const int n0 = blockIdx.x * 32, k0 = blockIdx.y * 32;
    const int tx = threadIdx.x, ty = threadIdx.y;
    t[ty][tx] = W[(size_t)(k0 + ty) * Nd + n0 + tx];
    __syncthreads();
    float v = t[tx][ty];
    __nv_bfloat16 hi = __float2bfloat16(v);
    float lo = v - __bfloat162float(hi);
    Th[(size_t)(n0 + ty) * Kd + k0 + tx] = hi;
    Tl[(size_t)(n0 + ty) * Kd + k0 + tx] = __float2bfloat16(lo);
}

// =============== RoPE + bf16 hi/lo split =====================================
__global__ void rope_split(const float* __restrict__ X,
                           const float* __restrict__ cosT,
                           const float* __restrict__ sinT,
                           __nv_bfloat16* __restrict__ Xh,
                           __nv_bfloat16* __restrict__ Xl, int nHeads)
{
    int idx = blockIdx.x * blockDim.x + threadIdx.x;
    int total = NT * nHeads * 32;
    if (idx >= total) return;
    int j = idx & 31;
    int hh = (idx >> 5) % nHeads;
    int t = idx / (32 * nHeads);
    int s = t & (SS - 1);
    int d = 2 * j;

    const float* p = X + (size_t)t * (nHeads * HD) + hh * HD;
    float x0 = p[d], x1 = p[d + 1], y0 = p[d + 64], y1 = p[d + 65];
    const float* cp = cosT + s * HD;
    const float* sp = sinT + s * HD;
    float r0 = x0 * cp[d]      - y0 * sp[d];
    float r1 = x1 * cp[d + 1]  - y1 * sp[d + 1];
    float r2 = y0 * cp[d + 64] + x0 * sp[d + 64];
    float r3 = y1 * cp[d + 65] + x1 * sp[d + 65];

    size_t o0 = (size_t)t * (nHeads * HD) + hh * HD + d;
    __nv_bfloat16 h0 = __float2bfloat16(r0), h1 = __float2bfloat16(r1);
    __nv_bfloat16 h2 = __float2bfloat16(r2), h3 = __float2bfloat16(r3);
    __nv_bfloat16 q0 = __float2bfloat16(r0 - __bfloat162float(h0));
    __nv_bfloat16 q1 = __float2bfloat16(r1 - __bfloat162float(h1));
    __nv_bfloat16 q2 = __float2bfloat16(r2 - __bfloat162float(h2));
    __nv_bfloat16 q3 = __float2bfloat16(r3 - __bfloat162float(h3));
    __nv_bfloat16 hp[2] = {h0, h1}; *(uint32_t*)(Xh + o0) = *(uint32_t*)hp;
    __nv_bfloat16 lp[2] = {q0, q1}; *(uint32_t*)(Xl + o0) = *(uint32_t*)lp;
    __nv_bfloat16 hp2[2] = {h2, h3}; *(uint32_t*)(Xh + o0 + 64) = *(uint32_t*)hp2;
    __nv_bfloat16 lp2[2] = {q2, q3}; *(uint32_t*)(Xl + o0 + 64) = *(uint32_t*)lp2;
}

// =============== V: fp32 [NT][KDIM] -> transposed bf16 hi/lo [b][g][d][s] ====
__global__ void v_split_t(const float* __restrict__ V,
                          __nv_bfloat16* __restrict__ Vth,
                          __nv_bfloat16* __restrict__ Vtl)
{
    __shared__ float t[32][33];
    const int c0 = blockIdx.x * 32;
    const int r0 = blockIdx.y * 32;
    const int tx = threadIdx.x, ty = threadIdx.y;
    t[ty][tx] = V[(size_t)(r0 + ty) * KDIM + c0 + tx];
    __syncthreads();
    float v = t[tx][ty];              // V[r0+tx][c0+ty]
    int tok = r0 + tx;
    int b = tok >> 11;
    int s = tok & (SS - 1);
    int col = c0 + ty;
    int g = col >> 7;
    int d = col & 127;
    size_t oidx = ((size_t)((b * NKV + g) * HD) + d) * SS + s;
    __nv_bfloat16 hi = __float2bfloat16(v);
    Vth[oidx] = hi;
    Vtl[oidx] = __float2bfloat16(v - __bfloat162float(hi));
}

// ---------------- HMMA flash attention (3-term split, causal, GQA) ----------
#define ASMEM_BYTES (196608)

__device__ __forceinline__ void attn_load_kv(
    uint32_t st, const __nv_bfloat16* Kh, const __nv_bfloat16* Kl,
    const __nv_bfloat16* Vth, const __nv_bfloat16* Vtl,
    int b, int g, int kt, int tid)
{
    const int tk0 = b * SS + kt * 64;
    #pragma unroll 4
    for (int c = tid; c < 2048; c += 256) {
        int hl = c >> 10, cc = c & 1023;
        int r = cc >> 4, sg = cc & 15, half = sg >> 3, sgi = sg & 7;
        const __nv_bfloat16* base = hl ? Kl : Kh;
        const void* src = base + (size_t)(tk0 + r) * KDIM + g * HD + half * 64 + sgi * 8;
        uint32_t dst = st + hl * 16384 + half * 8192 + sw128(r * 128 + sgi * 16);
        cp_async16(dst, src);
    }
    const size_t vrow0 = (size_t)((b * NKV + g) * HD) * SS;
    #pragma unroll 4
    for (int c = tid; c < 2048; c += 256) {
        int hl = c >> 10, cc = c & 1023;
        int d = cc >> 3, sg = cc & 7;
        const __nv_bfloat16* base = hl ? Vtl : Vth;
        const void* src = base + vrow0 + (size_t)d * SS + kt * 64 + sg * 8;
        uint32_t dst = st + 32768 + hl * 16384 + sw128(d * 128 + sg * 16);
        cp_async16(dst, src);
    }
    CP_COMMIT();
}

__global__ __launch_bounds__(256, 1) void attn_mma(
    const __nv_bfloat16* __restrict__ Qh, const __nv_bfloat16* __restrict__ Ql,
    const __nv_bfloat16* __restrict__ Kh, const __nv_bfloat16* __restrict__ Kl,
    const __nv_bfloat16* __restrict__ Vth, const __nv_bfloat16* __restrict__ Vtl,
    __nv_bfloat16* __restrict__ Oh, __nv_bfloat16* __restrict__ Ol)
{
    extern __shared__ char smc[];
    const uint32_t sb = smem_u32(smc);
    const int tid = threadIdx.x, wid = tid >> 5, lane = tid & 31;
    const int bid = blockIdx.x;
    const int qb = 15 - (bid >> 6);     // heavy-first
    const int bh = bid & 63;
    const int b = bh >> 5, h = bh & 31, g = h >> 2;
    const int tok0 = b * SS + qb * 128;
    const int KT = 2 * qb + 2;
    const float SCL = 0.08838834764831845f * 1.4426950408889634f;

    // Q load: hi/lo x 128 rows x 16 chunks(8 bf16) = 4096 chunks
    #pragma unroll 4
    for (int c = tid; c < 4096; c += 256) {
        int hl = c >> 11, cc = c & 2047;
        int r = cc >> 4, sg = cc & 15, half = sg >> 3, sgi = sg & 7;
        const __nv_bfloat16* base = hl ? Ql : Qh;
        const void* src = base + (size_t)(tok0 + r) * QDIM + h * HD + half * 64 + sgi * 8;
        uint32_t dst = sb + hl * 32768 + half * 16384 + sw128(r * 128 + sgi * 16);
        cp_async16(dst, src);
    }
    attn_load_kv(sb + 65536, Kh, Kl, Vth, Vtl, b, g, 0, tid);

    float o[16][4];
    #pragma unroll
    for (int nd = 0; nd < 16; nd++)
        #pragma unroll
        for (int e = 0; e < 4; e++) o[nd][e] = 0.f;
    float m0 = -1e30f, m1 = -1e30f, l0 = 0.f, l1 = 0.f;

    const int qg0 = qb * 128 + wid * 16 + (lane >> 2);
    const int qg1 = qg0 + 8;

    for (int kt = 0; kt < KT; kt++) {
        if (kt + 1 < KT) {
            attn_load_kv(sb + 65536 + ((kt + 1) & 1) * 65536, Kh, Kl, Vth, Vtl, b, g, kt + 1, tid);
            asm volatile("cp.async.wait_group 1;" ::: "memory");
        } else {
            asm volatile("cp.async.wait_group 0;" ::: "memory");
        }
        __syncthreads();

        const uint32_t st = sb + 65536 + (kt & 1) * 65536;
        const bool skip = kt * 64 > qb * 128 + wid * 16 + 15;

        if (!skip) {
            float s[8][4];
            #pragma unroll
            for (int nj = 0; nj < 8; nj++)
                #pragma unroll
                for (int e = 0; e < 4; e++) s[nj][e] = 0.f;

            #pragma unroll
            for (int k16 = 0; k16 < 8; k16++) {
                const int half = k16 >> 2;
                const int cb = (k16 & 3) * 32 + (lane >> 4) * 16;
                const uint32_t qoff = sw128((wid * 16 + (lane & 15)) * 128 + cb);
                uint32_t ah[4], al[4];
                LDSM4(ah, sb + half * 16384 + qoff);
                LDSM4(al, sb + 32768 + half * 16384 + qoff);
                uint32_t bhf[4][4], blf[4][4];
                #pragma unroll
                for (int c = 0; c < 4; c++) {
                    const uint32_t koff = sw128((c * 16 + (lane & 15)) * 128 + cb);
                    LDSM4(bhf[c], st + half * 8192 + koff);
                    LDSM4(blf[c], st + 16384 + half * 8192 + koff);
                }
                #pragma unroll
                for (int nj = 0; nj < 8; nj++) {
                    const int np = nj >> 1, h2 = nj & 1;
                    MMA16816(s[nj], ah, bhf[np][h2], bhf[np][2 + h2]);
                }
                #pragma unroll
                for (int nj = 0; nj < 8; nj++) {
                    const int np = nj >> 1, h2 = nj & 1;
                    MMA16816(s[nj], al, bhf[np][h2], bhf[np][2 + h2]);
                }
                #pragma unroll
                for (int nj = 0; nj < 8; nj++) {
                    const int np = nj >> 1, h2 = nj & 1;
                    MMA16816(s[nj], ah, blf[np][h2], blf[np][2 + h2]);
                }
            }

            const bool domask = (kt * 64 + 63) > qg0;
            #pragma unroll
            for (int nj = 0; nj < 8; nj++) {
                #pragma unroll
                for (int e = 0; e < 4; e++) s[nj][e] *= SCL;
                if (domask) {
                    const int kc = kt * 64 + nj * 8 + (lane & 3) * 2;
                    if (kc     > qg0) s[nj][0] = -1e30f;
                    if (kc + 1 > qg0) s[nj][1] = -1e30f;
                    if (kc     > qg1) s[nj][2] = -1e30f;
                    if (kc + 1 > qg1) s[nj][3] = -1e30f;
                }
            }
            float mx0 = -1e30f, mx1 = -1e30f;
            #pragma unroll
            for (int nj = 0; nj < 8; nj++) {
                mx0 = fmaxf(mx0, fmaxf(s[nj][0], s[nj][1]));
                mx1 = fmaxf(mx1, fmaxf(s[nj][2], s[nj][3]));
            }
            mx0 = fmaxf(mx0, __shfl_xor_sync(0xffffffffu, mx0, 1));
            mx0 = fmaxf(mx0, __shfl_xor_sync(0xffffffffu, mx0, 2));
            mx1 = fmaxf(mx1, __shfl_xor_sync(0xffffffffu, mx1, 1));
            mx1 = fmaxf(mx1, __shfl_xor_sync(0xffffffffu, mx1, 2));
            const float nm0 = fmaxf(m0, mx0), nm1 = fmaxf(m1, mx1);
            const float c0 = exp2a(m0 - nm0), c1 = exp2a(m1 - nm1);
            float rs0 = 0.f, rs1 = 0.f;
            #pragma unroll
            for (int nj = 0; nj < 8; nj++) {
                s[nj][0] = exp2a(s[nj][0] - nm0);
                s[nj][1] = exp2a(s[nj][1] - nm0);
                s[nj][2] = exp2a(s[nj][2] - nm1);
                s[nj][3] = exp2a(s[nj][3] - nm1);
                rs0 += s[nj][0] + s[nj][1];
                rs1 += s[nj][2] + s[nj][3];
            }
            rs0 += __shfl_xor_sync(0xffffffffu, rs0, 1);
            rs0 += __shfl_xor_sync(0xffffffffu, rs0, 2);
            rs1 += __shfl_xor_sync(0xffffffffu, rs1, 1);
            rs1 += __shfl_xor_sync(0xffffffffu, rs1, 2);
            m0 = nm0; m1 = nm1;
            l0 = l0 * c0 + rs0;
            l1 = l1 * c1 + rs1;
            #pragma unroll
            for (int nd = 0; nd < 16; nd++) {
                o[nd][0] *= c0; o[nd][1] *= c0;
                o[nd][2] *= c1; o[nd][3] *= c1;
            }

            #pragma unroll
            for (int j2 = 0; j2 < 4; j2++) {
                const int n0 = 2 * j2, n1 = 2 * j2 + 1;
                uint32_t aPh[4], aPl[4];
                __nv_bfloat162 t0 = __floats2bfloat162_rn(s[n0][0], s[n0][1]);
                __nv_bfloat162 t1 = __floats2bfloat162_rn(s[n0][2], s[n0][3]);
                __nv_bfloat162 t2 = __floats2bfloat162_rn(s[n1][0], s[n1][1]);
                __nv_bfloat162 t3 = __floats2bfloat162_rn(s[n1][2], s[n1][3]);
                aPh[0] = *(uint32_t*)&t0; aPh[1] = *(uint32_t*)&t1;
                aPh[2] = *(uint32_t*)&t2; aPh[3] = *(uint32_t*)&t3;
                __nv_bfloat162 u0 = __floats2bfloat162_rn(s[n0][0] - __bfloat162float(t0.x),
                                                          s[n0][1] - __bfloat162float(t0.y));
                __nv_bfloat162 u1 = __floats2bfloat162_rn(s[n0][2] - __bfloat162float(t1.x),
                                                          s[n0][3] - __bfloat162float(t1.y));
                __nv_bfloat162 u2 = __floats2bfloat162_rn(s[n1][0] - __bfloat162float(t2.x),
                                                          s[n1][1] - __bfloat162float(t2.y));
                __nv_bfloat162 u3 = __floats2bfloat162_rn(s[n1][2] - __bfloat162float(t3.x),
                                                          s[n1][3] - __bfloat162float(t3.y));
                aPl[0] = *(uint32_t*)&u0; aPl[1] = *(uint32_t*)&u1;
                aPl[2] = *(uint32_t*)&u2; aPl[3] = *(uint32_t*)&u3;

                #pragma unroll
                for (int c = 0; c < 8; c++) {
                    const uint32_t voff = sw128((c * 16 + (lane & 15)) * 128 + j2 * 32 + (lane >> 4) * 16);
                    uint32_t vh[4], vl[4];
                    LDSM4(vh, st + 32768 + voff);
                    LDSM4(vl, st + 49152 + voff);
                    MMA16816(o[2 * c],     aPh, vh[0], vh[2]);
                    MMA16816(o[2 * c + 1], aPh, vh[1], vh[3]);
                    MMA16816(o[2 * c],     aPl, vh[0], vh[2]);
                    MMA16816(o[2 * c + 1], aPl, vh[1], vh[3]);
                    MMA16816(o[2 * c],     aPh, vl[0], vl[2]);
                    MMA16816(o[2 * c + 1], aPh, vl[1], vl[3]);
                }
            }
        }
        __syncthreads();
    }

    const float il0 = 1.f / l0, il1 = 1.f / l1;
    const int row0g = tok0 + wid * 16 + (lane >> 2);
    #pragma unroll
    for (int nd = 0; nd < 16; nd++) {
        const int col = h * HD + nd * 8 + (lane & 3) * 2;
        float v00 = o[nd][0] * il0, v01 = o[nd][1] * il0;
        float v10 = o[nd][2] * il1, v11 = o[nd][3] * il1;
        __nv_bfloat162 h0 = __floats2bfloat162_rn(v00, v01);
        __nv_bfloat162 h1 = __floats2bfloat162_rn(v10, v11);
        __nv_bfloat162 q0 = __floats2bfloat162_rn(v00 - __bfloat162float(h0.x),
                                                  v01 - __bfloat162float(h0.y));
        __nv_bfloat162 q1 = __floats2bfloat162_rn(v10 - __bfloat162float(h1.x),
                                                  v11 - __bfloat162float(h1.y));
        *(uint32_t*)(Oh + (size_t)row0g * QDIM + col)       = *(uint32_t*)&h0;
        *(uint32_t*)(Ol + (size_t)row0g * QDIM + col)       = *(uint32_t*)&q0;
        *(uint32_t*)(Oh + (size_t)(row0g + 8) * QDIM + col) = *(uint32_t*)&h1;
        *(uint32_t*)(Ol + (size_t)(row0g + 8) * QDIM + col) = *(uint32_t*)&q1;
    }
}

// ---------------- launcher ---------------------------------------------------
extern "C" void kernel_launch(void* const* d_in, const int* in_sizes, int n_in,
                              void* d_out, int out_size)
{
    const float* x    = (const float*)d_in[0];
    const float* cosT = (const float*)d_in[1];
    const float* sinT = (const float*)d_in[2];
    const float* Wq   = (const float*)d_in[3];
    const float* Wk   = (const float*)d_in[4];
    const float* Wv   = (const float*)d_in[5];
    const float* Wo   = (const float*)d_in[6];
    float* out = (float*)d_out;

    float *Q, *K, *V;
    __nv_bfloat16 *xh, *xl, *Wqh, *Wql, *Wkh, *Wkl, *Wvh, *Wvl, *Woh, *Wol, *Ah, *Al;
    __nv_bfloat16 *Qh, *Ql, *Khb, *Klb, *Vth, *Vtl;
    cudaGetSymbolAddress((void**)&Q, g_Q);
    cudaGetSymbolAddress((void**)&K, g_K);
    cudaGetSymbolAddress((void**)&V, g_V);
    cudaGetSymbolAddress((void**)&xh, g_xh);
    cudaGetSymbolAddress((void**)&xl, g_xl);
    cudaGetSymbolAddress((void**)&Wqh, g_Wqh);
    cudaGetSymbolAddress((void**)&Wql, g_Wql);
    cudaGetSymbolAddress((void**)&Wkh, g_Wkh);
    cudaGetSymbolAddress((void**)&Wkl, g_Wkl);
    cudaGetSymbolAddress((void**)&Wvh, g_Wvh);
    cudaGetSymbolAddress((void**)&Wvl, g_Wvl);
    cudaGetSymbolAddress((void**)&Woh, g_Woh);
    cudaGetSymbolAddress((void**)&Wol, g_Wol);
    cudaGetSymbolAddress((void**)&Ah, g_Ah);
    cudaGetSymbolAddress((void**)&Al, g_Al);
    cudaGetSymbolAddress((void**)&Qh, g_Qh);
    cudaGetSymbolAddress((void**)&Ql, g_Ql);
    cudaGetSymbolAddress((void**)&Khb, g_Kh);
    cudaGetSymbolAddress((void**)&Klb, g_Kl);
    cudaGetSymbolAddress((void**)&Vth, g_Vth);
    cudaGetSymbolAddress((void**)&Vtl, g_Vtl);

    cudaFuncSetAttribute(gemm_bf16x3, cudaFuncAttributeMaxDynamicSharedMemorySize, GSMEM_BYTES);
    cudaFuncSetAttribute(attn_mma, cudaFuncAttributeMaxDynamicSharedMemorySize, ASMEM_BYTES);

    // conversions
    split_rows<<<(NT * DIM / 4 + 255) / 256, 256>>>(x, xh, xl, NT * DIM / 4);
    transpose_split<<<dim3(QDIM / 32, DIM / 32), dim3(32, 32)>>>(Wq, Wqh, Wql, DIM, QDIM);
    transpose_split<<<dim3(KDIM / 32, DIM / 32), dim3(32, 32)>>>(Wk, Wkh, Wkl, DIM, KDIM);
    transpose_split<<<dim3(KDIM / 32, DIM / 32), dim3(32, 32)>>>(Wv, Wvh, Wvl, DIM, KDIM);
    transpose_split<<<dim3(DIM / 32, QDIM / 32), dim3(32, 32)>>>(Wo, Woh, Wol, QDIM, DIM);

    // QKV projections (HMMA, 128x256 tile)
    gemm_bf16x3<<<dim3(QDIM / 256, NT / 128), 256, GSMEM_BYTES>>>(xh, xl, Wqh, Wql, Q, NT, QDIM, DIM);
    gemm_bf16x3<<<dim3(KDIM / 256, NT / 128), 256, GSMEM_BYTES>>>(xh, xl, Wkh, Wkl, K, NT, KDIM, DIM);
    gemm_bf16x3<<<dim3(KDIM / 256, NT / 128), 256, GSMEM_BYTES>>>(xh, xl, Wvh, Wvl, V, NT, KDIM, DIM);

    // RoPE + split to bf16 operands
    rope_split<<<(NT * NH * 32 + 255) / 256, 256>>>(Q, cosT, sinT, Qh, Ql, NH);
    rope_split<<<(NT * NKV * 32 + 255) / 256, 256>>>(K, cosT, sinT, Khb, Klb, NKV);
    v_split_t<<<dim3(KDIM / 32, NT / 32), dim3(32, 32)>>>(V, Vth, Vtl);

    // HMMA flash attention
    attn_mma<<<1024, 256, ASMEM_BYTES>>>(Qh, Ql, Khb, Klb, Vth, Vtl, Ah, Al);

    // Output projection (HMMA, 128x256 tile)
    gemm_bf16x3<<<dim3(DIM / 256, NT / 128), 256, GSMEM_BYTES>>>(Ah, Al, Woh, Wol, out, NT, DIM, QDIM);
}

// round 8
// speedup vs baseline: 2.2796x; 1.0943x over previous
#include <cuda_runtime.h>
#include <cuda_bf16.h>
#include <math.h>
#include <stdint.h>

// Problem constants
#define BB   2
#define SS   2048
#define DIM  4096
#define NH   32
#define NKV  8
#define HD   128
#define NT   (BB*SS)          // 4096 tokens
#define QDIM (NH*HD)          // 4096
#define KDIM (NKV*HD)         // 1024

// ---------------- scratch (device globals; no allocation allowed) ----------
__device__ float g_Q[NT * QDIM];
__device__ float g_K[NT * KDIM];
__device__ float g_V[NT * KDIM];
__device__ __nv_bfloat16 g_xh[NT * DIM];
__device__ __nv_bfloat16 g_xl[NT * DIM];
__device__ __nv_bfloat16 g_Wqh[QDIM * DIM];
__device__ __nv_bfloat16 g_Wql[QDIM * DIM];
__device__ __nv_bfloat16 g_Wkh[KDIM * DIM];
__device__ __nv_bfloat16 g_Wkl[KDIM * DIM];
__device__ __nv_bfloat16 g_Wvh[KDIM * DIM];
__device__ __nv_bfloat16 g_Wvl[KDIM * DIM];
__device__ __nv_bfloat16 g_Woh[DIM * QDIM];   // transposed: [N=DIM rows][K=QDIM]
__device__ __nv_bfloat16 g_Wol[DIM * QDIM];
__device__ __nv_bfloat16 g_Ah[NT * QDIM];     // attention out hi
__device__ __nv_bfloat16 g_Al[NT * QDIM];     // attention out lo
// bf16 attention operands
__device__ __nv_bfloat16 g_Qh[NT * QDIM];
__device__ __nv_bfloat16 g_Ql[NT * QDIM];
__device__ __nv_bfloat16 g_Kh[NT * KDIM];
__device__ __nv_bfloat16 g_Kl[NT * KDIM];
__device__ __nv_bfloat16 g_Vth[BB * NKV * HD * SS];  // [b][g][d][s]
__device__ __nv_bfloat16 g_Vtl[BB * NKV * HD * SS];

// ======================= PTX helpers =======================
__device__ __forceinline__ uint32_t smem_u32(const void* p) {
    uint32_t a;
    asm("{ .reg .u64 t; cvta.to.shared.u64 t, %1; cvt.u32.u64 %0, t; }" : "=r"(a) : "l"(p));
    return a;
}
__device__ __forceinline__ void cp_async16(uint32_t dst, const void* src) {
    asm volatile("cp.async.cg.shared.global [%0], [%1], 16;" :: "r"(dst), "l"(src));
}
#define CP_COMMIT() asm volatile("cp.async.commit_group;" ::: "memory")

__device__ __forceinline__ uint32_t sw128(uint32_t b) { return b ^ ((b >> 3) & 0x70); }

__device__ __forceinline__ float exp2a(float x) {
    float r;
    asm("ex2.approx.f32 %0, %1;" : "=f"(r) : "f"(x));
    return r;
}

#define LDSM4(r, addr) \
    asm volatile("ldmatrix.sync.aligned.m8n8.x4.shared.b16 {%0,%1,%2,%3}, [%4];" \
        : "=r"((r)[0]), "=r"((r)[1]), "=r"((r)[2]), "=r"((r)[3]) : "r"(addr))

#define MMA16816(c, a, b0, b1) \
    asm volatile("mma.sync.aligned.m16n8k16.row.col.f32.bf16.bf16.f32 " \
        "{%0,%1,%2,%3}, {%4,%5,%6,%7}, {%8,%9}, {%0,%1,%2,%3};" \
        : "+f"((c)[0]), "+f"((c)[1]), "+f"((c)[2]), "+f"((c)[3]) \
        : "r"((a)[0]), "r"((a)[1]), "r"((a)[2]), "r"((a)[3]), "r"(b0), "r"(b1))

// =============== split-precision HMMA GEMM, 128x256 tile, optional split-K ===
// C[M,N] = (Ah+Al)[M,K] * (Bh+Bl)^T, B tensors [N,K] row-major bf16.
// 3-term: Ah*Bh + Al*Bh + Ah*Bl, fp32 accumulation.
// CTA tile 128x256, warp tile 64x64 (8 warps 2x4), BK=64, double buffer.
// gridDim.z = 2 -> each CTA does K/2 and atomicAdds into zero-init C
// (exactly 2 fp32 contributors on a zeroed cell -> order-independent result).
#define GSMEM_BYTES (2 * 98304)

__device__ __forceinline__ void load_stage(
    uint32_t buf, const __nv_bfloat16* Ah, const __nv_bfloat16* Al,
    const __nv_bfloat16* Bh, const __nv_bfloat16* Bl,
    int row0, int col0, int K, int kchunk, int tid)
{
    #pragma unroll 8
    for (int c = tid; c < 6144; c += 256) {
        const __nv_bfloat16* base;
        int grow;
        uint32_t dst;
        if (c < 2048) {
            const int pl = c >> 10;           // 0:Ah 1:Al
            const int idx = c & 1023;
            const int r = idx >> 3;           // 0..127
            const int sg = idx & 7;
            base = pl ? Al : Ah;
            grow = row0 + r;
            dst = buf + pl * 16384 + sw128(r * 128 + sg * 16);
            cp_async16(dst, base + (size_t)grow * K + kchunk * 64 + sg * 8);
        } else {
            const int cb = c - 2048;
            const int pl = cb >> 11;          // 0:Bh 1:Bl
            const int idx = cb & 2047;
            const int r = idx >> 3;           // 0..255
            const int sg = idx & 7;
            base = pl ? Bl : Bh;
            grow = col0 + r;
            dst = buf + 32768 + pl * 32768 + sw128(r * 128 + sg * 16);
            cp_async16(dst, base + (size_t)grow * K + kchunk * 64 + sg * 8);
        }
    }
    CP_COMMIT();
}

__global__ __launch_bounds__(256, 1) void gemm_bf16x3(
    const __nv_bfloat16* __restrict__ Ah, const __nv_bfloat16* __restrict__ Al,
    const __nv_bfloat16* __restrict__ Bh, const __nv_bfloat16* __restrict__ Bl,
    float* __restrict__ C, int M, int N, int K)
{
    extern __shared__ char smc[];
    const uint32_t sb = smem_u32(smc);
    const int tid = threadIdx.x;
    const int wid = tid >> 5;
    const int lane = tid & 31;
    const int row0 = blockIdx.y * 128;
    const int col0 = blockIdx.x * 256;
    const int nz = gridDim.z;
    const int K2 = K / nz;
    const int kb = blockIdx.z * (K2 / 64);   // base k-chunk

    const int wm0 = (wid >> 2) * 64;   // 0 or 64
    const int wn0 = (wid & 3) * 64;    // 0,64,128,192

    float acc[4][8][4];
    #pragma unroll
    for (int i = 0; i < 4; i++)
        #pragma unroll
        for (int j = 0; j < 8; j++)
            #pragma unroll
            for (int r = 0; r < 4; r++) acc[i][j][r] = 0.f;

    const int KT = K2 / 64;
    load_stage(sb, Ah, Al, Bh, Bl, row0, col0, K, kb, tid);

    for (int it = 0; it < KT; it++) {
        const uint32_t buf = sb + (it & 1) * 98304;
        if (it + 1 < KT) {
            load_stage(sb + ((it + 1) & 1) * 98304, Ah, Al, Bh, Bl, row0, col0, K, kb + it + 1, tid);
            asm volatile("cp.async.wait_group 1;" ::: "memory");
        } else {
            asm volatile("cp.async.wait_group 0;" ::: "memory");
        }
        __syncthreads();

        const uint32_t aHb = buf;
        const uint32_t aLb = buf + 16384;
        const uint32_t bHb = buf + 32768;
        const uint32_t bLb = buf + 65536;

        #pragma unroll
        for (int k16 = 0; k16 < 4; k16++) {
            const int colb = k16 * 32 + (lane >> 4) * 16;
            uint32_t ah[4][4], al[4][4];
            #pragma unroll
            for (int mi = 0; mi < 4; mi++) {
                const uint32_t off = sw128((wm0 + mi * 16 + (lane & 15)) * 128 + colb);
                LDSM4(ah[mi], aHb + off);
                LDSM4(al[mi], aLb + off);
            }
            #pragma unroll
            for (int hb = 0; hb < 2; hb++) {
                uint32_t bh[2][4], bl[2][4];
                #pragma unroll
                for (int np = 0; np < 2; np++) {
                    const uint32_t off =
                        sw128((wn0 + hb * 32 + np * 16 + (lane & 15)) * 128 + colb);
                    LDSM4(bh[np], bHb + off);
                    LDSM4(bl[np], bLb + off);
                }
                #pragma unroll
                for (int mi = 0; mi < 4; mi++)
                    #pragma unroll
                    for (int nj = 0; nj < 4; nj++) {
                        const int np = nj >> 1, h = nj & 1;
                        MMA16816(acc[mi][hb * 4 + nj], ah[mi], bh[np][h], bh[np][2 + h]);
                    }
                #pragma unroll
                for (int mi = 0; mi < 4; mi++)
                    #pragma unroll
                    for (int nj = 0; nj < 4; nj++) {
                        const int np = nj >> 1, h = nj & 1;
                        MMA16816(acc[mi][hb * 4 + nj], al[mi], bh[np][h], bh[np][2 + h]);
                    }
                #pragma unroll
                for (int mi = 0; mi < 4; mi++)
                    #pragma unroll
                    for (int nj = 0; nj < 4; nj++) {
                        const int np = nj >> 1, h = nj & 1;
                        MMA16816(acc[mi][hb * 4 + nj], ah[mi], bl[np][h], bl[np][2 + h]);
                    }
            }
        }
        __syncthreads();
    }

    if (nz > 1) {
        #pragma unroll
        for (int mi = 0; mi < 4; mi++) {
            #pragma unroll
            for (int nj = 0; nj < 8; nj++) {
                const int row = row0 + wm0 + mi * 16 + (lane >> 2);
                const int col = col0 + wn0 + nj * 8 + (lane & 3) * 2;
                float* p0 = C + (size_t)row * N + col;
                float* p1 = C + (size_t)(row + 8) * N + col;
                atomicAdd(p0,     acc[mi][nj][0]);
                atomicAdd(p0 + 1, acc[mi][nj][1]);
                atomicAdd(p1,     acc[mi][nj][2]);
                atomicAdd(p1 + 1, acc[mi][nj][3]);
            }
        }
    } else {
        #pragma unroll
        for (int mi = 0; mi < 4; mi++) {
            #pragma unroll
            for (int nj = 0; nj < 8; nj++) {
                const int row = row0 + wm0 + mi * 16 + (lane >> 2);
                const int col = col0 + wn0 + nj * 8 + (lane & 3) * 2;
                *(float2*)(C + (size_t)row * N + col)       = make_float2(acc[mi][nj][0], acc[mi][nj][1]);
                *(float2*)(C + (size_t)(row + 8) * N + col) = make_float2(acc[mi][nj][2], acc[mi][nj][3]);
            }
        }
    }
}

// =============== fp32 -> bf16 hi/lo split (row-major) ===========
__global__ void split_rows(const float* __restrict__ X,
                           __nv_bfloat16* __restrict__ Xh,
                           __nv_bfloat16* __restrict__ Xl, int total4)
{
    int i = blockIdx.x * blockDim.x + threadIdx.x;
    if (i >= total4) return;
    float4 v = *(const float4*)(X + (size_t)i * 4);
    __nv_bfloat16 h[4], l[4];
    float vv[4] = {v.x, v.y, v.z, v.w};
    #pragma unroll
    for (int j = 0; j < 4; j++) {
        h[j] = __float2bfloat16(vv[j]);
        l[j] = __float2bfloat16(vv[j] - __bfloat162float(h[j]));
    }
    *(uint2*)(Xh + (size_t)i * 4) = *(uint2*)h;
    *(uint2*)(Xl + (size_t)i * 4) = *(uint2*)l;
}

// =============== transpose + split: W[K,N] fp32 -> T_hi/lo [N,K] bf16 ========
// 64x64 tiles, float4 reads, 8B vectorized writes (128B coalesced segments).
__global__ __launch_bounds__(256) void transpose_split(
    const float* __restrict__ W,
    __nv_bfloat16* __restrict__ Th,
    __nv_bfloat16* __restrict__ Tl, int Kd, int Nd)
{
    __shared__ float t[64][65];
    const int n0 = blockIdx.x * 64, k0 = blockIdx.y * 64;
    const int tid = threadIdx.x;
    #pragma unroll
    for (int i = 0; i < 4; i++) {
        int it = tid + i * 256;
        int r = it >> 4;            // k row 0..63
        int c4 = (it & 15) * 4;     // n col
        float4 v = *(const float4*)(W + (size_t)(k0 + r) * Nd + n0 + c4);
        t[r][c4] = v.x; t[r][c4 + 1] = v.y; t[r][c4 + 2] = v.z; t[r][c4 + 3] = v.w;
    }
    __syncthreads();
    #pragma unroll
    for (int i = 0; i < 4; i++) {
        int it = tid + i * 256;
        int n = it >> 4;            // n row 0..63
        int kc = (it & 15) * 4;     // k col
        __nv_bfloat16 h[4], l[4];
        #pragma unroll
        for (int j = 0; j < 4; j++) {
            float v = t[kc + j][n];
            h[j] = __float2bfloat16(v);
            l[j] = __float2bfloat16(v - __bfloat162float(h[j]));
        }
        size_t o = (size_t)(n0 + n) * Kd + k0 + kc;
        *(uint2*)(Th + o) = *(uint2*)h;
        *(uint2*)(Tl + o) = *(uint2*)l;
    }
}

// =============== RoPE + bf16 hi/lo split =====================================
__global__ void rope_split(const float* __restrict__ X,
                           const float* __restrict__ cosT,
                           const float* __restrict__ sinT,
                           __nv_bfloat16* __restrict__ Xh,
                           __nv_bfloat16* __restrict__ Xl, int nHeads)
{
    int idx = blockIdx.x * blockDim.x + threadIdx.x;
    int total = NT * nHeads * 32;
    if (idx >= total) return;
    int j = idx & 31;
    int hh = (idx >> 5) % nHeads;
    int t = idx / (32 * nHeads);
    int s = t & (SS - 1);
    int d = 2 * j;

    const float* p = X + (size_t)t * (nHeads * HD) + hh * HD;
    float x0 = p[d], x1 = p[d + 1], y0 = p[d + 64], y1 = p[d + 65];
    const float* cp = cosT + s * HD;
    const float* sp = sinT + s * HD;
    float r0 = x0 * cp[d]      - y0 * sp[d];
    float r1 = x1 * cp[d + 1]  - y1 * sp[d + 1];
    float r2 = y0 * cp[d + 64] + x0 * sp[d + 64];
    float r3 = y1 * cp[d + 65] + x1 * sp[d + 65];

    size_t o0 = (size_t)t * (nHeads * HD) + hh * HD + d;
    __nv_bfloat16 h0 = __float2bfloat16(r0), h1 = __float2bfloat16(r1);
    __nv_bfloat16 h2 = __float2bfloat16(r2), h3 = __float2bfloat16(r3);
    __nv_bfloat16 q0 = __float2bfloat16(r0 - __bfloat162float(h0));
    __nv_bfloat16 q1 = __float2bfloat16(r1 - __bfloat162float(h1));
    __nv_bfloat16 q2 = __float2bfloat16(r2 - __bfloat162float(h2));
    __nv_bfloat16 q3 = __float2bfloat16(r3 - __bfloat162float(h3));
    __nv_bfloat16 hp[2] = {h0, h1}; *(uint32_t*)(Xh + o0) = *(uint32_t*)hp;
    __nv_bfloat16 lp[2] = {q0, q1}; *(uint32_t*)(Xl + o0) = *(uint32_t*)lp;
    __nv_bfloat16 hp2[2] = {h2, h3}; *(uint32_t*)(Xh + o0 + 64) = *(uint32_t*)hp2;
    __nv_bfloat16 lp2[2] = {q2, q3}; *(uint32_t*)(Xl + o0 + 64) = *(uint32_t*)lp2;
}

// =============== V: fp32 [NT][KDIM] -> transposed bf16 hi/lo [b][g][d][s] ====
// 64x64 tiles, vectorized both sides (2048 % 64 == 0 -> no batch crossing).
__global__ __launch_bounds__(256) void v_split_t(const float* __restrict__ V,
                                                 __nv_bfloat16* __restrict__ Vth,
                                                 __nv_bfloat16* __restrict__ Vtl)
{
    __shared__ float t[64][65];
    const int c0 = blockIdx.x * 64;   // col in KDIM
    const int r0 = blockIdx.y * 64;   // token
    const int tid = threadIdx.x;
    #pragma unroll
    for (int i = 0; i < 4; i++) {
        int it = tid + i * 256;
        int r = it >> 4;
        int c4 = (it & 15) * 4;
        float4 v = *(const float4*)(V + (size_t)(r0 + r) * KDIM + c0 + c4);
        t[r][c4] = v.x; t[r][c4 + 1] = v.y; t[r][c4 + 2] = v.z; t[r][c4 + 3] = v.w;
    }
    __syncthreads();
    const int b = r0 >> 11;
    const int sbase = r0 & (SS - 1);
    #pragma unroll
    for (int i = 0; i < 4; i++) {
        int it = tid + i * 256;
        int n = it >> 4;            // col within tile
        int kc = (it & 15) * 4;     // token sub
        int col = c0 + n;
        int g = col >> 7;
        int d = col & 127;
        __nv_bfloat16 h[4], l[4];
        #pragma unroll
        for (int j = 0; j < 4; j++) {
            float v = t[kc + j][n];
            h[j] = __float2bfloat16(v);
            l[j] = __float2bfloat16(v - __bfloat162float(h[j]));
        }
        size_t o = ((size_t)((b * NKV + g) * HD) + d) * SS + sbase + kc;
        *(uint2*)(Vth + o) = *(uint2*)h;
        *(uint2*)(Vtl + o) = *(uint2*)l;
    }
}

// ---------------- HMMA flash attention (3-term split, causal, GQA) ----------
#define ASMEM_BYTES (196608)

__device__ __forceinline__ void attn_load_kv(
    uint32_t st, const __nv_bfloat16* Kh, const __nv_bfloat16* Kl,
    const __nv_bfloat16* Vth, const __nv_bfloat16* Vtl,
    int b, int g, int kt, int tid)
{
    const int tk0 = b * SS + kt * 64;
    #pragma unroll 4
    for (int c = tid; c < 2048; c += 256) {
        int hl = c >> 10, cc = c & 1023;
        int r = cc >> 4, sg = cc & 15, half = sg >> 3, sgi = sg & 7;
        const __nv_bfloat16* base = hl ? Kl : Kh;
        const void* src = base + (size_t)(tk0 + r) * KDIM + g * HD + half * 64 + sgi * 8;
        uint32_t dst = st + hl * 16384 + half * 8192 + sw128(r * 128 + sgi * 16);
        cp_async16(dst, src);
    }
    const size_t vrow0 = (size_t)((b * NKV + g) * HD) * SS;
    #pragma unroll 4
    for (int c = tid; c < 2048; c += 256) {
        int hl = c >> 10, cc = c & 1023;
        int d = cc >> 3, sg = cc & 7;
        const __nv_bfloat16* base = hl ? Vtl : Vth;
        const void* src = base + vrow0 + (size_t)d * SS + kt * 64 + sg * 8;
        uint32_t dst = st + 32768 + hl * 16384 + sw128(d * 128 + sg * 16);
        cp_async16(dst, src);
    }
    CP_COMMIT();
}

__global__ __launch_bounds__(256, 1) void attn_mma(
    const __nv_bfloat16* __restrict__ Qh, const __nv_bfloat16* __restrict__ Ql,
    const __nv_bfloat16* __restrict__ Kh, const __nv_bfloat16* __restrict__ Kl,
    const __nv_bfloat16* __restrict__ Vth, const __nv_bfloat16* __restrict__ Vtl,
    __nv_bfloat16* __restrict__ Oh, __nv_bfloat16* __restrict__ Ol)
{
    extern __shared__ char smc[];
    const uint32_t sb = smem_u32(smc);
    const int tid = threadIdx.x, wid = tid >> 5, lane = tid & 31;
    const int bid = blockIdx.x;
    const int qb = 15 - (bid >> 6);     // heavy-first
    const int bh = bid & 63;
    const int b = bh >> 5, h = bh & 31, g = h >> 2;
    const int tok0 = b * SS + qb * 128;
    const int KT = 2 * qb + 2;
    const float SCL = 0.08838834764831845f * 1.4426950408889634f;

    #pragma unroll 4
    for (int c = tid; c < 4096; c += 256) {
        int hl = c >> 11, cc = c & 2047;
        int r = cc >> 4, sg = cc & 15, half = sg >> 3, sgi = sg & 7;
        const __nv_bfloat16* base = hl ? Ql : Qh;
        const void* src = base + (size_t)(tok0 + r) * QDIM + h * HD + half * 64 + sgi * 8;
        uint32_t dst = sb + hl * 32768 + half * 16384 + sw128(r * 128 + sgi * 16);
        cp_async16(dst, src);
    }
    attn_load_kv(sb + 65536, Kh, Kl, Vth, Vtl, b, g, 0, tid);

    float o[16][4];
    #pragma unroll
    for (int nd = 0; nd < 16; nd++)
        #pragma unroll
        for (int e = 0; e < 4; e++) o[nd][e] = 0.f;
    float m0 = -1e30f, m1 = -1e30f, l0 = 0.f, l1 = 0.f;

    const int qg0 = qb * 128 + wid * 16 + (lane >> 2);
    const int qg1 = qg0 + 8;

    for (int kt = 0; kt < KT; kt++) {
        if (kt + 1 < KT) {
            attn_load_kv(sb + 65536 + ((kt + 1) & 1) * 65536, Kh, Kl, Vth, Vtl, b, g, kt + 1, tid);
            asm volatile("cp.async.wait_group 1;" ::: "memory");
        } else {
            asm volatile("cp.async.wait_group 0;" ::: "memory");
        }
        __syncthreads();

        const uint32_t st = sb + 65536 + (kt & 1) * 65536;
        const bool skip = kt * 64 > qb * 128 + wid * 16 + 15;

        if (!skip) {
            float s[8][4];
            #pragma unroll
            for (int nj = 0; nj < 8; nj++)
                #pragma unroll
                for (int e = 0; e < 4; e++) s[nj][e] = 0.f;

            #pragma unroll
            for (int k16 = 0; k16 < 8; k16++) {
                const int half = k16 >> 2;
                const int cb = (k16 & 3) * 32 + (lane >> 4) * 16;
                const uint32_t qoff = sw128((wid * 16 + (lane & 15)) * 128 + cb);
                uint32_t ah[4], al[4];
                LDSM4(ah, sb + half * 16384 + qoff);
                LDSM4(al, sb + 32768 + half * 16384 + qoff);
                uint32_t bhf[4][4], blf[4][4];
                #pragma unroll
                for (int c = 0; c < 4; c++) {
                    const uint32_t koff = sw128((c * 16 + (lane & 15)) * 128 + cb);
                    LDSM4(bhf[c], st + half * 8192 + koff);
                    LDSM4(blf[c], st + 16384 + half * 8192 + koff);
                }
                #pragma unroll
                for (int nj = 0; nj < 8; nj++) {
                    const int np = nj >> 1, h2 = nj & 1;
                    MMA16816(s[nj], ah, bhf[np][h2], bhf[np][2 + h2]);
                }
                #pragma unroll
                for (int nj = 0; nj < 8; nj++) {
                    const int np = nj >> 1, h2 = nj & 1;
                    MMA16816(s[nj], al, bhf[np][h2], bhf[np][2 + h2]);
                }
                #pragma unroll
                for (int nj = 0; nj < 8; nj++) {
                    const int np = nj >> 1, h2 = nj & 1;
                    MMA16816(s[nj], ah, blf[np][h2], blf[np][2 + h2]);
                }
            }

            const bool domask = (kt * 64 + 63) > qg0;
            #pragma unroll
            for (int nj = 0; nj < 8; nj++) {
                #pragma unroll
                for (int e = 0; e < 4; e++) s[nj][e] *= SCL;
                if (domask) {
                    const int kc = kt * 64 + nj * 8 + (lane & 3) * 2;
                    if (kc     > qg0) s[nj][0] = -1e30f;
                    if (kc + 1 > qg0) s[nj][1] = -1e30f;
                    if (kc     > qg1) s[nj][2] = -1e30f;
                    if (kc + 1 > qg1) s[nj][3] = -1e30f;
                }
            }
            float mx0 = -1e30f, mx1 = -1e30f;
            #pragma unroll
            for (int nj = 0; nj < 8; nj++) {
                mx0 = fmaxf(mx0, fmaxf(s[nj][0], s[nj][1]));
                mx1 = fmaxf(mx1, fmaxf(s[nj][2], s[nj][3]));
            }
            mx0 = fmaxf(mx0, __shfl_xor_sync(0xffffffffu, mx0, 1));
            mx0 = fmaxf(mx0, __shfl_xor_sync(0xffffffffu, mx0, 2));
            mx1 = fmaxf(mx1, __shfl_xor_sync(0xffffffffu, mx1, 1));
            mx1 = fmaxf(mx1, __shfl_xor_sync(0xffffffffu, mx1, 2));
            const float nm0 = fmaxf(m0, mx0), nm1 = fmaxf(m1, mx1);
            const float c0 = exp2a(m0 - nm0), c1 = exp2a(m1 - nm1);
            float rs0 = 0.f, rs1 = 0.f;
            #pragma unroll
            for (int nj = 0; nj < 8; nj++) {
                s[nj][0] = exp2a(s[nj][0] - nm0);
                s[nj][1] = exp2a(s[nj][1] - nm0);
                s[nj][2] = exp2a(s[nj][2] - nm1);
                s[nj][3] = exp2a(s[nj][3] - nm1);
                rs0 += s[nj][0] + s[nj][1];
                rs1 += s[nj][2] + s[nj][3];
            }
            rs0 += __shfl_xor_sync(0xffffffffu, rs0, 1);
            rs0 += __shfl_xor_sync(0xffffffffu, rs0, 2);
            rs1 += __shfl_xor_sync(0xffffffffu, rs1, 1);
            rs1 += __shfl_xor_sync(0xffffffffu, rs1, 2);
            m0 = nm0; m1 = nm1;
            l0 = l0 * c0 + rs0;
            l1 = l1 * c1 + rs1;
            #pragma unroll
            for (int nd = 0; nd < 16; nd++) {
                o[nd][0] *= c0; o[nd][1] *= c0;
                o[nd][2] *= c1; o[nd][3] *= c1;
            }

            #pragma unroll
            for (int j2 = 0; j2 < 4; j2++) {
                const int n0 = 2 * j2, n1 = 2 * j2 + 1;
                uint32_t aPh[4], aPl[4];
                __nv_bfloat162 t0 = __floats2bfloat162_rn(s[n0][0], s[n0][1]);
                __nv_bfloat162 t1 = __floats2bfloat162_rn(s[n0][2], s[n0][3]);
                __nv_bfloat162 t2 = __floats2bfloat162_rn(s[n1][0], s[n1][1]);
                __nv_bfloat162 t3 = __floats2bfloat162_rn(s[n1][2], s[n1][3]);
                aPh[0] = *(uint32_t*)&t0; aPh[1] = *(uint32_t*)&t1;
                aPh[2] = *(uint32_t*)&t2; aPh[3] = *(uint32_t*)&t3;
                __nv_bfloat162 u0 = __floats2bfloat162_rn(s[n0][0] - __bfloat162float(t0.x),
                                                          s[n0][1] - __bfloat162float(t0.y));
                __nv_bfloat162 u1 = __floats2bfloat162_rn(s[n0][2] - __bfloat162float(t1.x),
                                                          s[n0][3] - __bfloat162float(t1.y));
                __nv_bfloat162 u2 = __floats2bfloat162_rn(s[n1][0] - __bfloat162float(t2.x),
                                                          s[n1][1] - __bfloat162float(t2.y));
                __nv_bfloat162 u3 = __floats2bfloat162_rn(s[n1][2] - __bfloat162float(t3.x),
                                                          s[n1][3] - __bfloat162float(t3.y));
                aPl[0] = *(uint32_t*)&u0; aPl[1] = *(uint32_t*)&u1;
                aPl[2] = *(uint32_t*)&u2; aPl[3] = *(uint32_t*)&u3;

                #pragma unroll
                for (int c = 0; c < 8; c++) {
                    const uint32_t voff = sw128((c * 16 + (lane & 15)) * 128 + j2 * 32 + (lane >> 4) * 16);
                    uint32_t vh[4], vl[4];
                    LDSM4(vh, st + 32768 + voff);
                    LDSM4(vl, st + 49152 + voff);
                    MMA16816(o[2 * c],     aPh, vh[0], vh[2]);
                    MMA16816(o[2 * c + 1], aPh, vh[1], vh[3]);
                    MMA16816(o[2 * c],     aPl, vh[0], vh[2]);
                    MMA16816(o[2 * c + 1], aPl, vh[1], vh[3]);
                    MMA16816(o[2 * c],     aPh, vl[0], vl[2]);
                    MMA16816(o[2 * c + 1], aPh, vl[1], vl[3]);
                }
            }
        }
        __syncthreads();
    }

    const float il0 = 1.f / l0, il1 = 1.f / l1;
    const int row0g = tok0 + wid * 16 + (lane >> 2);
    #pragma unroll
    for (int nd = 0; nd < 16; nd++) {
        const int col = h * HD + nd * 8 + (lane & 3) * 2;
        float v00 = o[nd][0] * il0, v01 = o[nd][1] * il0;
        float v10 = o[nd][2] * il1, v11 = o[nd][3] * il1;
        __nv_bfloat162 h0 = __floats2bfloat162_rn(v00, v01);
        __nv_bfloat162 h1 = __floats2bfloat162_rn(v10, v11);
        __nv_bfloat162 q0 = __floats2bfloat162_rn(v00 - __bfloat162float(h0.x),
                                                  v01 - __bfloat162float(h0.y));
        __nv_bfloat162 q1 = __floats2bfloat162_rn(v10 - __bfloat162float(h1.x),
                                                  v11 - __bfloat162float(h1.y));
        *(uint32_t*)(Oh + (size_t)row0g * QDIM + col)       = *(uint32_t*)&h0;
        *(uint32_t*)(Ol + (size_t)row0g * QDIM + col)       = *(uint32_t*)&q0;
        *(uint32_t*)(Oh + (size_t)(row0g + 8) * QDIM + col) = *(uint32_t*)&h1;
        *(uint32_t*)(Ol + (size_t)(row0g + 8) * QDIM + col) = *(uint32_t*)&q1;
    }
}

// ---------------- launcher ---------------------------------------------------
extern "C" void kernel_launch(void* const* d_in, const int* in_sizes, int n_in,
                              void* d_out, int out_size)
{
    const float* x    = (const float*)d_in[0];
    const float* cosT = (const float*)d_in[1];
    const float* sinT = (const float*)d_in[2];
    const float* Wq   = (const float*)d_in[3];
    const float* Wk   = (const float*)d_in[4];
    const float* Wv   = (const float*)d_in[5];
    const float* Wo   = (const float*)d_in[6];
    float* out = (float*)d_out;

    float *Q, *K, *V;
    __nv_bfloat16 *xh, *xl, *Wqh, *Wql, *Wkh, *Wkl, *Wvh, *Wvl, *Woh, *Wol, *Ah, *Al;
    __nv_bfloat16 *Qh, *Ql, *Khb, *Klb, *Vth, *Vtl;
    cudaGetSymbolAddress((void**)&Q, g_Q);
    cudaGetSymbolAddress((void**)&K, g_K);
    cudaGetSymbolAddress((void**)&V, g_V);
    cudaGetSymbolAddress((void**)&xh, g_xh);
    cudaGetSymbolAddress((void**)&xl, g_xl);
    cudaGetSymbolAddress((void**)&Wqh, g_Wqh);
    cudaGetSymbolAddress((void**)&Wql, g_Wql);
    cudaGetSymbolAddress((void**)&Wkh, g_Wkh);
    cudaGetSymbolAddress((void**)&Wkl, g_Wkl);
    cudaGetSymbolAddress((void**)&Wvh, g_Wvh);
    cudaGetSymbolAddress((void**)&Wvl, g_Wvl);
    cudaGetSymbolAddress((void**)&Woh, g_Woh);
    cudaGetSymbolAddress((void**)&Wol, g_Wol);
    cudaGetSymbolAddress((void**)&Ah, g_Ah);
    cudaGetSymbolAddress((void**)&Al, g_Al);
    cudaGetSymbolAddress((void**)&Qh, g_Qh);
    cudaGetSymbolAddress((void**)&Ql, g_Ql);
    cudaGetSymbolAddress((void**)&Khb, g_Kh);
    cudaGetSymbolAddress((void**)&Klb, g_Kl);
    cudaGetSymbolAddress((void**)&Vth, g_Vth);
    cudaGetSymbolAddress((void**)&Vtl, g_Vtl);

    cudaFuncSetAttribute(gemm_bf16x3, cudaFuncAttributeMaxDynamicSharedMemorySize, GSMEM_BYTES);
    cudaFuncSetAttribute(attn_mma, cudaFuncAttributeMaxDynamicSharedMemorySize, ASMEM_BYTES);

    // zero-init split-K targets (exactly 2 atomic contributors -> deterministic)
    cudaMemsetAsync(Q, 0, (size_t)NT * QDIM * sizeof(float));
    cudaMemsetAsync(out, 0, (size_t)NT * DIM * sizeof(float));

    // conversions
    split_rows<<<(NT * DIM / 4 + 255) / 256, 256>>>(x, xh, xl, NT * DIM / 4);
    transpose_split<<<dim3(QDIM / 64, DIM / 64), 256>>>(Wq, Wqh, Wql, DIM, QDIM);
    transpose_split<<<dim3(KDIM / 64, DIM / 64), 256>>>(Wk, Wkh, Wkl, DIM, KDIM);
    transpose_split<<<dim3(KDIM / 64, DIM / 64), 256>>>(Wv, Wvh, Wvl, DIM, KDIM);
    transpose_split<<<dim3(DIM / 64, QDIM / 64), 256>>>(Wo, Woh, Wol, QDIM, DIM);

    // QKV projections (HMMA, 128x256 tile; Q with split-K=2)
    gemm_bf16x3<<<dim3(QDIM / 256, NT / 128, 2), 256, GSMEM_BYTES>>>(xh, xl, Wqh, Wql, Q, NT, QDIM, DIM);
    gemm_bf16x3<<<dim3(KDIM / 256, NT / 128, 1), 256, GSMEM_BYTES>>>(xh, xl, Wkh, Wkl, K, NT, KDIM, DIM);
    gemm_bf16x3<<<dim3(KDIM / 256, NT / 128, 1), 256, GSMEM_BYTES>>>(xh, xl, Wvh, Wvl, V, NT, KDIM, DIM);

    // RoPE + split to bf16 operands
    rope_split<<<(NT * NH * 32 + 255) / 256, 256>>>(Q, cosT, sinT, Qh, Ql, NH);
    rope_split<<<(NT * NKV * 32 + 255) / 256, 256>>>(K, cosT, sinT, Khb, Klb, NKV);
    v_split_t<<<dim3(KDIM / 64, NT / 64), 256>>>(V, Vth, Vtl);

    // HMMA flash attention
    attn_mma<<<1024, 256, ASMEM_BYTES>>>(Qh, Ql, Khb, Klb, Vth, Vtl, Ah, Al);

    // Output projection (HMMA, split-K=2)
    gemm_bf16x3<<<dim3(DIM / 256, NT / 128, 2), 256, GSMEM_BYTES>>>(Ah, Al, Woh, Wol, out, NT, DIM, QDIM);
}

// round 9
// speedup vs baseline: 2.5623x; 1.1240x over previous
#include <cuda_runtime.h>
#include <cuda_bf16.h>
#include <math.h>
#include <stdint.h>

// Problem constants
#define BB   2
#define SS   2048
#define DIM  4096
#define NH   32
#define NKV  8
#define HD   128
#define NT   (BB*SS)          // 4096 tokens
#define QDIM (NH*HD)          // 4096
#define KDIM (NKV*HD)         // 1024

// ---------------- scratch (device globals; no allocation allowed) ----------
__device__ float g_Q[NT * QDIM];
__device__ float g_K[NT * KDIM];
__device__ float g_V[NT * KDIM];
__device__ __nv_bfloat16 g_xh[NT * DIM];
__device__ __nv_bfloat16 g_xl[NT * DIM];
__device__ __nv_bfloat16 g_Wqh[QDIM * DIM];
__device__ __nv_bfloat16 g_Wql[QDIM * DIM];
__device__ __nv_bfloat16 g_Wkh[KDIM * DIM];
__device__ __nv_bfloat16 g_Wkl[KDIM * DIM];
__device__ __nv_bfloat16 g_Wvh[KDIM * DIM];
__device__ __nv_bfloat16 g_Wvl[KDIM * DIM];
__device__ __nv_bfloat16 g_Woh[DIM * QDIM];   // transposed: [N=DIM rows][K=QDIM]
__device__ __nv_bfloat16 g_Wol[DIM * QDIM];
__device__ __nv_bfloat16 g_Ah[NT * QDIM];     // attention out hi
__device__ __nv_bfloat16 g_Al[NT * QDIM];     // attention out lo
// bf16 attention operands
__device__ __nv_bfloat16 g_Qh[NT * QDIM];
__device__ __nv_bfloat16 g_Ql[NT * QDIM];
__device__ __nv_bfloat16 g_Kh[NT * KDIM];
__device__ __nv_bfloat16 g_Kl[NT * KDIM];
__device__ __nv_bfloat16 g_Vth[BB * NKV * HD * SS];  // [b][g][d][s]
__device__ __nv_bfloat16 g_Vtl[BB * NKV * HD * SS];

// ======================= PTX helpers =======================
__device__ __forceinline__ uint32_t smem_u32(const void* p) {
    uint32_t a;
    asm("{ .reg .u64 t; cvta.to.shared.u64 t, %1; cvt.u32.u64 %0, t; }" : "=r"(a) : "l"(p));
    return a;
}
__device__ __forceinline__ void cp_async16(uint32_t dst, const void* src) {
    asm volatile("cp.async.cg.shared.global [%0], [%1], 16;" :: "r"(dst), "l"(src));
}
#define CP_COMMIT() asm volatile("cp.async.commit_group;" ::: "memory")
#define CP_WAIT_ALL() asm volatile("cp.async.wait_group 0;" ::: "memory")

__device__ __forceinline__ uint32_t sw128(uint32_t b) { return b ^ ((b >> 3) & 0x70); }

__device__ __forceinline__ float exp2a(float x) {
    float r;
    asm("ex2.approx.f32 %0, %1;" : "=f"(r) : "f"(x));
    return r;
}

#define LDSM4(r, addr) \
    asm volatile("ldmatrix.sync.aligned.m8n8.x4.shared.b16 {%0,%1,%2,%3}, [%4];" \
        : "=r"((r)[0]), "=r"((r)[1]), "=r"((r)[2]), "=r"((r)[3]) : "r"(addr))

#define MMA16816(c, a, b0, b1) \
    asm volatile("mma.sync.aligned.m16n8k16.row.col.f32.bf16.bf16.f32 " \
        "{%0,%1,%2,%3}, {%4,%5,%6,%7}, {%8,%9}, {%0,%1,%2,%3};" \
        : "+f"((c)[0]), "+f"((c)[1]), "+f"((c)[2]), "+f"((c)[3]) \
        : "r"((a)[0]), "r"((a)[1]), "r"((a)[2]), "r"((a)[3]), "r"(b0), "r"(b1))

// =============== split-precision HMMA GEMM, 128x256 tile, optional split-K ===
// C[M,N] = (Ah+Al)[M,K] * (Bh+Bl)^T, B tensors [N,K] row-major bf16.
// 3-term: Ah*Bh + Al*Bh + Ah*Bl, fp32 accumulation.
// CTA tile 128x256, warp tile 64x64 (8 warps 2x4), BK=64, double buffer.
// Single-sync pipeline: wait -> sync -> issue next (interleaved) -> compute.
#define GSMEM_BYTES (2 * 98304)

__device__ __forceinline__ void load_stage_part(
    uint32_t buf, const __nv_bfloat16* Ah, const __nv_bfloat16* Al,
    const __nv_bfloat16* Bh, const __nv_bfloat16* Bl,
    int row0, int col0, int K, int kchunk, int tid, int part)
{
    #pragma unroll
    for (int j = 0; j < 6; j++) {
        const int c = tid + part * 1536 + j * 256;
        if (c < 2048) {
            const int pl = c >> 10;           // 0:Ah 1:Al
            const int idx = c & 1023;
            const int r = idx >> 3;           // 0..127
            const int sg = idx & 7;
            const __nv_bfloat16* base = pl ? Al : Ah;
            const uint32_t dst = buf + pl * 16384 + sw128(r * 128 + sg * 16);
            cp_async16(dst, base + (size_t)(row0 + r) * K + kchunk * 64 + sg * 8);
        } else {
            const int cb = c - 2048;
            const int pl = cb >> 11;          // 0:Bh 1:Bl
            const int idx = cb & 2047;
            const int r = idx >> 3;           // 0..255
            const int sg = idx & 7;
            const __nv_bfloat16* base = pl ? Bl : Bh;
            const uint32_t dst = buf + 32768 + pl * 32768 + sw128(r * 128 + sg * 16);
            cp_async16(dst, base + (size_t)(col0 + r) * K + kchunk * 64 + sg * 8);
        }
    }
}

__global__ __launch_bounds__(256, 1) void gemm_bf16x3(
    const __nv_bfloat16* __restrict__ Ah, const __nv_bfloat16* __restrict__ Al,
    const __nv_bfloat16* __restrict__ Bh, const __nv_bfloat16* __restrict__ Bl,
    float* __restrict__ C, int M, int N, int K)
{
    extern __shared__ char smc[];
    const uint32_t sb = smem_u32(smc);
    const int tid = threadIdx.x;
    const int wid = tid >> 5;
    const int lane = tid & 31;
    const int row0 = blockIdx.y * 128;
    const int col0 = blockIdx.x * 256;
    const int nz = gridDim.z;
    const int K2 = K / nz;
    const int kb = blockIdx.z * (K2 / 64);   // base k-chunk

    const int wm0 = (wid >> 2) * 64;   // 0 or 64
    const int wn0 = (wid & 3) * 64;    // 0,64,128,192

    float acc[4][8][4];
    #pragma unroll
    for (int i = 0; i < 4; i++)
        #pragma unroll
        for (int j = 0; j < 8; j++)
            #pragma unroll
            for (int r = 0; r < 4; r++) acc[i][j][r] = 0.f;

    const int KT = K2 / 64;
    #pragma unroll
    for (int p = 0; p < 4; p++)
        load_stage_part(sb, Ah, Al, Bh, Bl, row0, col0, K, kb, tid, p);
    CP_COMMIT();

    for (int it = 0; it < KT; it++) {
        CP_WAIT_ALL();
        __syncthreads();
        const uint32_t buf = sb + (it & 1) * 98304;
        const uint32_t nbuf = sb + ((it + 1) & 1) * 98304;
        const bool more = (it + 1 < KT);

        const uint32_t aHb = buf;
        const uint32_t aLb = buf + 16384;
        const uint32_t bHb = buf + 32768;
        const uint32_t bLb = buf + 65536;

        #pragma unroll
        for (int k16 = 0; k16 < 4; k16++) {
            // interleave next-stage load issue (part k16) with compute
            if (more) {
                load_stage_part(nbuf, Ah, Al, Bh, Bl, row0, col0, K, kb + it + 1, tid, k16);
                if (k16 == 3) CP_COMMIT();
            }
            const int colb = k16 * 32 + (lane >> 4) * 16;
            uint32_t ah[4][4], al[4][4];
            #pragma unroll
            for (int mi = 0; mi < 4; mi++) {
                const uint32_t off = sw128((wm0 + mi * 16 + (lane & 15)) * 128 + colb);
                LDSM4(ah[mi], aHb + off);
                LDSM4(al[mi], aLb + off);
            }
            #pragma unroll
            for (int hb = 0; hb < 2; hb++) {
                uint32_t bh[2][4], bl[2][4];
                #pragma unroll
                for (int np = 0; np < 2; np++) {
                    const uint32_t off =
                        sw128((wn0 + hb * 32 + np * 16 + (lane & 15)) * 128 + colb);
                    LDSM4(bh[np], bHb + off);
                    LDSM4(bl[np], bLb + off);
                }
                #pragma unroll
                for (int mi = 0; mi < 4; mi++)
                    #pragma unroll
                    for (int nj = 0; nj < 4; nj++) {
                        const int np = nj >> 1, h = nj & 1;
                        MMA16816(acc[mi][hb * 4 + nj], ah[mi], bh[np][h], bh[np][2 + h]);
                    }
                #pragma unroll
                for (int mi = 0; mi < 4; mi++)
                    #pragma unroll
                    for (int nj = 0; nj < 4; nj++) {
                        const int np = nj >> 1, h = nj & 1;
                        MMA16816(acc[mi][hb * 4 + nj], al[mi], bh[np][h], bh[np][2 + h]);
                    }
                #pragma unroll
                for (int mi = 0; mi < 4; mi++)
                    #pragma unroll
                    for (int nj = 0; nj < 4; nj++) {
                        const int np = nj >> 1, h = nj & 1;
                        MMA16816(acc[mi][hb * 4 + nj], ah[mi], bl[np][h], bl[np][2 + h]);
                    }
            }
        }
    }

    if (nz > 1) {
        #pragma unroll
        for (int mi = 0; mi < 4; mi++) {
            #pragma unroll
            for (int nj = 0; nj < 8; nj++) {
                const int row = row0 + wm0 + mi * 16 + (lane >> 2);
                const int col = col0 + wn0 + nj * 8 + (lane & 3) * 2;
                float* p0 = C + (size_t)row * N + col;
                float* p1 = C + (size_t)(row + 8) * N + col;
                atomicAdd(p0,     acc[mi][nj][0]);
                atomicAdd(p0 + 1, acc[mi][nj][1]);
                atomicAdd(p1,     acc[mi][nj][2]);
                atomicAdd(p1 + 1, acc[mi][nj][3]);
            }
        }
    } else {
        #pragma unroll
        for (int mi = 0; mi < 4; mi++) {
            #pragma unroll
            for (int nj = 0; nj < 8; nj++) {
                const int row = row0 + wm0 + mi * 16 + (lane >> 2);
                const int col = col0 + wn0 + nj * 8 + (lane & 3) * 2;
                *(float2*)(C + (size_t)row * N + col)       = make_float2(acc[mi][nj][0], acc[mi][nj][1]);
                *(float2*)(C + (size_t)(row + 8) * N + col) = make_float2(acc[mi][nj][2], acc[mi][nj][3]);
            }
        }
    }
}

// =============== fp32 -> bf16 hi/lo split (row-major) ===========
__global__ void split_rows(const float* __restrict__ X,
                           __nv_bfloat16* __restrict__ Xh,
                           __nv_bfloat16* __restrict__ Xl, int total4)
{
    int i = blockIdx.x * blockDim.x + threadIdx.x;
    if (i >= total4) return;
    float4 v = *(const float4*)(X + (size_t)i * 4);
    __nv_bfloat16 h[4], l[4];
    float vv[4] = {v.x, v.y, v.z, v.w};
    #pragma unroll
    for (int j = 0; j < 4; j++) {
        h[j] = __float2bfloat16(vv[j]);
        l[j] = __float2bfloat16(vv[j] - __bfloat162float(h[j]));
    }
    *(uint2*)(Xh + (size_t)i * 4) = *(uint2*)h;
    *(uint2*)(Xl + (size_t)i * 4) = *(uint2*)l;
}

// =============== transpose + split: W[K,N] fp32 -> T_hi/lo [N,K] bf16 ========
__global__ __launch_bounds__(256) void transpose_split(
    const float* __restrict__ W,
    __nv_bfloat16* __restrict__ Th,
    __nv_bfloat16* __restrict__ Tl, int Kd, int Nd)
{
    __shared__ float t[64][65];
    const int n0 = blockIdx.x * 64, k0 = blockIdx.y * 64;
    const int tid = threadIdx.x;
    #pragma unroll
    for (int i = 0; i < 4; i++) {
        int it = tid + i * 256;
        int r = it >> 4;            // k row 0..63
        int c4 = (it & 15) * 4;     // n col
        float4 v = *(const float4*)(W + (size_t)(k0 + r) * Nd + n0 + c4);
        t[r][c4] = v.x; t[r][c4 + 1] = v.y; t[r][c4 + 2] = v.z; t[r][c4 + 3] = v.w;
    }
    __syncthreads();
    #pragma unroll
    for (int i = 0; i < 4; i++) {
        int it = tid + i * 256;
        int n = it >> 4;            // n row 0..63
        int kc = (it & 15) * 4;     // k col
        __nv_bfloat16 h[4], l[4];
        #pragma unroll
        for (int j = 0; j < 4; j++) {
            float v = t[kc + j][n];
            h[j] = __float2bfloat16(v);
            l[j] = __float2bfloat16(v - __bfloat162float(h[j]));
        }
        size_t o = (size_t)(n0 + n) * Kd + k0 + kc;
        *(uint2*)(Th + o) = *(uint2*)h;
        *(uint2*)(Tl + o) = *(uint2*)l;
    }
}

// =============== RoPE + bf16 hi/lo split =====================================
__global__ void rope_split(const float* __restrict__ X,
                           const float* __restrict__ cosT,
                           const float* __restrict__ sinT,
                           __nv_bfloat16* __restrict__ Xh,
                           __nv_bfloat16* __restrict__ Xl, int nHeads)
{
    int idx = blockIdx.x * blockDim.x + threadIdx.x;
    int total = NT * nHeads * 32;
    if (idx >= total) return;
    int j = idx & 31;
    int hh = (idx >> 5) % nHeads;
    int t = idx / (32 * nHeads);
    int s = t & (SS - 1);
    int d = 2 * j;

    const float* p = X + (size_t)t * (nHeads * HD) + hh * HD;
    float x0 = p[d], x1 = p[d + 1], y0 = p[d + 64], y1 = p[d + 65];
    const float* cp = cosT + s * HD;
    const float* sp = sinT + s * HD;
    float r0 = x0 * cp[d]      - y0 * sp[d];
    float r1 = x1 * cp[d + 1]  - y1 * sp[d + 1];
    float r2 = y0 * cp[d + 64] + x0 * sp[d + 64];
    float r3 = y1 * cp[d + 65] + x1 * sp[d + 65];

    size_t o0 = (size_t)t * (nHeads * HD) + hh * HD + d;
    __nv_bfloat16 h0 = __float2bfloat16(r0), h1 = __float2bfloat16(r1);
    __nv_bfloat16 h2 = __float2bfloat16(r2), h3 = __float2bfloat16(r3);
    __nv_bfloat16 q0 = __float2bfloat16(r0 - __bfloat162float(h0));
    __nv_bfloat16 q1 = __float2bfloat16(r1 - __bfloat162float(h1));
    __nv_bfloat16 q2 = __float2bfloat16(r2 - __bfloat162float(h2));
    __nv_bfloat16 q3 = __float2bfloat16(r3 - __bfloat162float(h3));
    __nv_bfloat16 hp[2] = {h0, h1}; *(uint32_t*)(Xh + o0) = *(uint32_t*)hp;
    __nv_bfloat16 lp[2] = {q0, q1}; *(uint32_t*)(Xl + o0) = *(uint32_t*)lp;
    __nv_bfloat16 hp2[2] = {h2, h3}; *(uint32_t*)(Xh + o0 + 64) = *(uint32_t*)hp2;
    __nv_bfloat16 lp2[2] = {q2, q3}; *(uint32_t*)(Xl + o0 + 64) = *(uint32_t*)lp2;
}

// =============== V: fp32 [NT][KDIM] -> transposed bf16 hi/lo [b][g][d][s] ====
__global__ __launch_bounds__(256) void v_split_t(const float* __restrict__ V,
                                                 __nv_bfloat16* __restrict__ Vth,
                                                 __nv_bfloat16* __restrict__ Vtl)
{
    __shared__ float t[64][65];
    const int c0 = blockIdx.x * 64;   // col in KDIM
    const int r0 = blockIdx.y * 64;   // token
    const int tid = threadIdx.x;
    #pragma unroll
    for (int i = 0; i < 4; i++) {
        int it = tid + i * 256;
        int r = it >> 4;
        int c4 = (it & 15) * 4;
        float4 v = *(const float4*)(V + (size_t)(r0 + r) * KDIM + c0 + c4);
        t[r][c4] = v.x; t[r][c4 + 1] = v.y; t[r][c4 + 2] = v.z; t[r][c4 + 3] = v.w;
    }
    __syncthreads();
    const int b = r0 >> 11;
    const int sbase = r0 & (SS - 1);
    #pragma unroll
    for (int i = 0; i < 4; i++) {
        int it = tid + i * 256;
        int n = it >> 4;            // col within tile
        int kc = (it & 15) * 4;     // token sub
        int col = c0 + n;
        int g = col >> 7;
        int d = col & 127;
        __nv_bfloat16 h[4], l[4];
        #pragma unroll
        for (int j = 0; j < 4; j++) {
            float v = t[kc + j][n];
            h[j] = __float2bfloat16(v);
            l[j] = __float2bfloat16(v - __bfloat162float(h[j]));
        }
        size_t o = ((size_t)((b * NKV + g) * HD) + d) * SS + sbase + kc;
        *(uint2*)(Vth + o) = *(uint2*)h;
        *(uint2*)(Vtl + o) = *(uint2*)l;
    }
}

// ---------------- HMMA flash attention (3-term split, causal, GQA) ----------
// Single-sync pipeline per key tile.
#define ASMEM_BYTES (196608)

__device__ __forceinline__ void attn_load_kv(
    uint32_t st, const __nv_bfloat16* Kh, const __nv_bfloat16* Kl,
    const __nv_bfloat16* Vth, const __nv_bfloat16* Vtl,
    int b, int g, int kt, int tid)
{
    const int tk0 = b * SS + kt * 64;
    #pragma unroll 4
    for (int c = tid; c < 2048; c += 256) {
        int hl = c >> 10, cc = c & 1023;
        int r = cc >> 4, sg = cc & 15, half = sg >> 3, sgi = sg & 7;
        const __nv_bfloat16* base = hl ? Kl : Kh;
        const void* src = base + (size_t)(tk0 + r) * KDIM + g * HD + half * 64 + sgi * 8;
        uint32_t dst = st + hl * 16384 + half * 8192 + sw128(r * 128 + sgi * 16);
        cp_async16(dst, src);
    }
    const size_t vrow0 = (size_t)((b * NKV + g) * HD) * SS;
    #pragma unroll 4
    for (int c = tid; c < 2048; c += 256) {
        int hl = c >> 10, cc = c & 1023;
        int d = cc >> 3, sg = cc & 7;
        const __nv_bfloat16* base = hl ? Vtl : Vth;
        const void* src = base + vrow0 + (size_t)d * SS + kt * 64 + sg * 8;
        uint32_t dst = st + 32768 + hl * 16384 + sw128(d * 128 + sg * 16);
        cp_async16(dst, src);
    }
    CP_COMMIT();
}

__global__ __launch_bounds__(256, 1) void attn_mma(
    const __nv_bfloat16* __restrict__ Qh, const __nv_bfloat16* __restrict__ Ql,
    const __nv_bfloat16* __restrict__ Kh, const __nv_bfloat16* __restrict__ Kl,
    const __nv_bfloat16* __restrict__ Vth, const __nv_bfloat16* __restrict__ Vtl,
    __nv_bfloat16* __restrict__ Oh, __nv_bfloat16* __restrict__ Ol)
{
    extern __shared__ char smc[];
    const uint32_t sb = smem_u32(smc);
    const int tid = threadIdx.x, wid = tid >> 5, lane = tid & 31;
    const int bid = blockIdx.x;
    const int qb = 15 - (bid >> 6);     // heavy-first
    const int bh = bid & 63;
    const int b = bh >> 5, h = bh & 31, g = h >> 2;
    const int tok0 = b * SS + qb * 128;
    const int KT = 2 * qb + 2;
    const float SCL = 0.08838834764831845f * 1.4426950408889634f;

    // Q load issues (committed together with kv(0)'s commit below)
    #pragma unroll 4
    for (int c = tid; c < 4096; c += 256) {
        int hl = c >> 11, cc = c & 2047;
        int r = cc >> 4, sg = cc & 15, half = sg >> 3, sgi = sg & 7;
        const __nv_bfloat16* base = hl ? Ql : Qh;
        const void* src = base + (size_t)(tok0 + r) * QDIM + h * HD + half * 64 + sgi * 8;
        uint32_t dst = sb + hl * 32768 + half * 16384 + sw128(r * 128 + sgi * 16);
        cp_async16(dst, src);
    }
    attn_load_kv(sb + 65536, Kh, Kl, Vth, Vtl, b, g, 0, tid);

    float o[16][4];
    #pragma unroll
    for (int nd = 0; nd < 16; nd++)
        #pragma unroll
        for (int e = 0; e < 4; e++) o[nd][e] = 0.f;
    float m0 = -1e30f, m1 = -1e30f, l0 = 0.f, l1 = 0.f;

    const int qg0 = qb * 128 + wid * 16 + (lane >> 2);
    const int qg1 = qg0 + 8;

    for (int kt = 0; kt < KT; kt++) {
        CP_WAIT_ALL();
        __syncthreads();
        if (kt + 1 < KT)
            attn_load_kv(sb + 65536 + ((kt + 1) & 1) * 65536, Kh, Kl, Vth, Vtl, b, g, kt + 1, tid);

        const uint32_t st = sb + 65536 + (kt & 1) * 65536;
        const bool skip = kt * 64 > qb * 128 + wid * 16 + 15;

        if (!skip) {
            float s[8][4];
            #pragma unroll
            for (int nj = 0; nj < 8; nj++)
                #pragma unroll
                for (int e = 0; e < 4; e++) s[nj][e] = 0.f;

            #pragma unroll
            for (int k16 = 0; k16 < 8; k16++) {
                const int half = k16 >> 2;
                const int cb = (k16 & 3) * 32 + (lane >> 4) * 16;
                const uint32_t qoff = sw128((wid * 16 + (lane & 15)) * 128 + cb);
                uint32_t ah[4], al[4];
                LDSM4(ah, sb + half * 16384 + qoff);
                LDSM4(al, sb + 32768 + half * 16384 + qoff);
                uint32_t bhf[4][4], blf[4][4];
                #pragma unroll
                for (int c = 0; c < 4; c++) {
                    const uint32_t koff = sw128((c * 16 + (lane & 15)) * 128 + cb);
                    LDSM4(bhf[c], st + half * 8192 + koff);
                    LDSM4(blf[c], st + 16384 + half * 8192 + koff);
                }
                #pragma unroll
                for (int nj = 0; nj < 8; nj++) {
                    const int np = nj >> 1, h2 = nj & 1;
                    MMA16816(s[nj], ah, bhf[np][h2], bhf[np][2 + h2]);
                }
                #pragma unroll
                for (int nj = 0; nj < 8; nj++) {
                    const int np = nj >> 1, h2 = nj & 1;
                    MMA16816(s[nj], al, bhf[np][h2], bhf[np][2 + h2]);
                }
                #pragma unroll
                for (int nj = 0; nj < 8; nj++) {
                    const int np = nj >> 1, h2 = nj & 1;
                    MMA16816(s[nj], ah, blf[np][h2], blf[np][2 + h2]);
                }
            }

            const bool domask = (kt * 64 + 63) > qg0;
            #pragma unroll
            for (int nj = 0; nj < 8; nj++) {
                #pragma unroll
                for (int e = 0; e < 4; e++) s[nj][e] *= SCL;
                if (domask) {
                    const int kc = kt * 64 + nj * 8 + (lane & 3) * 2;
                    if (kc     > qg0) s[nj][0] = -1e30f;
                    if (kc + 1 > qg0) s[nj][1] = -1e30f;
                    if (kc     > qg1) s[nj][2] = -1e30f;
                    if (kc + 1 > qg1) s[nj][3] = -1e30f;
                }
            }
            float mx0 = -1e30f, mx1 = -1e30f;
            #pragma unroll
            for (int nj = 0; nj < 8; nj++) {
                mx0 = fmaxf(mx0, fmaxf(s[nj][0], s[nj][1]));
                mx1 = fmaxf(mx1, fmaxf(s[nj][2], s[nj][3]));
            }
            mx0 = fmaxf(mx0, __shfl_xor_sync(0xffffffffu, mx0, 1));
            mx0 = fmaxf(mx0, __shfl_xor_sync(0xffffffffu, mx0, 2));
            mx1 = fmaxf(mx1, __shfl_xor_sync(0xffffffffu, mx1, 1));
            mx1 = fmaxf(mx1, __shfl_xor_sync(0xffffffffu, mx1, 2));
            const float nm0 = fmaxf(m0, mx0), nm1 = fmaxf(m1, mx1);
            const float c0 = exp2a(m0 - nm0), c1 = exp2a(m1 - nm1);
            float rs0 = 0.f, rs1 = 0.f;
            #pragma unroll
            for (int nj = 0; nj < 8; nj++) {
                s[nj][0] = exp2a(s[nj][0] - nm0);
                s[nj][1] = exp2a(s[nj][1] - nm0);
                s[nj][2] = exp2a(s[nj][2] - nm1);
                s[nj][3] = exp2a(s[nj][3] - nm1);
                rs0 += s[nj][0] + s[nj][1];
                rs1 += s[nj][2] + s[nj][3];
            }
            rs0 += __shfl_xor_sync(0xffffffffu, rs0, 1);
            rs0 += __shfl_xor_sync(0xffffffffu, rs0, 2);
            rs1 += __shfl_xor_sync(0xffffffffu, rs1, 1);
            rs1 += __shfl_xor_sync(0xffffffffu, rs1, 2);
            m0 = nm0; m1 = nm1;
            l0 = l0 * c0 + rs0;
            l1 = l1 * c1 + rs1;
            #pragma unroll
            for (int nd = 0; nd < 16; nd++) {
                o[nd][0] *= c0; o[nd][1] *= c0;
                o[nd][2] *= c1; o[nd][3] *= c1;
            }

            #pragma unroll
            for (int j2 = 0; j2 < 4; j2++) {
                const int n0 = 2 * j2, n1 = 2 * j2 + 1;
                uint32_t aPh[4], aPl[4];
                __nv_bfloat162 t0 = __floats2bfloat162_rn(s[n0][0], s[n0][1]);
                __nv_bfloat162 t1 = __floats2bfloat162_rn(s[n0][2], s[n0][3]);
                __nv_bfloat162 t2 = __floats2bfloat162_rn(s[n1][0], s[n1][1]);
                __nv_bfloat162 t3 = __floats2bfloat162_rn(s[n1][2], s[n1][3]);
                aPh[0] = *(uint32_t*)&t0; aPh[1] = *(uint32_t*)&t1;
                aPh[2] = *(uint32_t*)&t2; aPh[3] = *(uint32_t*)&t3;
                __nv_bfloat162 u0 = __floats2bfloat162_rn(s[n0][0] - __bfloat162float(t0.x),
                                                          s[n0][1] - __bfloat162float(t0.y));
                __nv_bfloat162 u1 = __floats2bfloat162_rn(s[n0][2] - __bfloat162float(t1.x),
                                                          s[n0][3] - __bfloat162float(t1.y));
                __nv_bfloat162 u2 = __floats2bfloat162_rn(s[n1][0] - __bfloat162float(t2.x),
                                                          s[n1][1] - __bfloat162float(t2.y));
                __nv_bfloat162 u3 = __floats2bfloat162_rn(s[n1][2] - __bfloat162float(t3.x),
                                                          s[n1][3] - __bfloat162float(t3.y));
                aPl[0] = *(uint32_t*)&u0; aPl[1] = *(uint32_t*)&u1;
                aPl[2] = *(uint32_t*)&u2; aPl[3] = *(uint32_t*)&u3;

                #pragma unroll
                for (int c = 0; c < 8; c++) {
                    const uint32_t voff = sw128((c * 16 + (lane & 15)) * 128 + j2 * 32 + (lane >> 4) * 16);
                    uint32_t vh[4], vl[4];
                    LDSM4(vh, st + 32768 + voff);
                    LDSM4(vl, st + 49152 + voff);
                    MMA16816(o[2 * c],     aPh, vh[0], vh[2]);
                    MMA16816(o[2 * c + 1], aPh, vh[1], vh[3]);
                    MMA16816(o[2 * c],     aPl, vh[0], vh[2]);
                    MMA16816(o[2 * c + 1], aPl, vh[1], vh[3]);
                    MMA16816(o[2 * c],     aPh, vl[0], vl[2]);
                    MMA16816(o[2 * c + 1], aPh, vl[1], vl[3]);
                }
            }
        }
    }

    const float il0 = 1.f / l0, il1 = 1.f / l1;
    const int row0g = tok0 + wid * 16 + (lane >> 2);
    #pragma unroll
    for (int nd = 0; nd < 16; nd++) {
        const int col = h * HD + nd * 8 + (lane & 3) * 2;
        float v00 = o[nd][0] * il0, v01 = o[nd][1] * il0;
        float v10 = o[nd][2] * il1, v11 = o[nd][3] * il1;
        __nv_bfloat162 h0 = __floats2bfloat162_rn(v00, v01);
        __nv_bfloat162 h1 = __floats2bfloat162_rn(v10, v11);
        __nv_bfloat162 q0 = __floats2bfloat162_rn(v00 - __bfloat162float(h0.x),
                                                  v01 - __bfloat162float(h0.y));
        __nv_bfloat162 q1 = __floats2bfloat162_rn(v10 - __bfloat162float(h1.x),
                                                  v11 - __bfloat162float(h1.y));
        *(uint32_t*)(Oh + (size_t)row0g * QDIM + col)       = *(uint32_t*)&h0;
        *(uint32_t*)(Ol + (size_t)row0g * QDIM + col)       = *(uint32_t*)&q0;
        *(uint32_t*)(Oh + (size_t)(row0g + 8) * QDIM + col) = *(uint32_t*)&h1;
        *(uint32_t*)(Ol + (size_t)(row0g + 8) * QDIM + col) = *(uint32_t*)&q1;
    }
}

// ---------------- launcher ---------------------------------------------------
extern "C" void kernel_launch(void* const* d_in, const int* in_sizes, int n_in,
                              void* d_out, int out_size)
{
    const float* x    = (const float*)d_in[0];
    const float* cosT = (const float*)d_in[1];
    const float* sinT = (const float*)d_in[2];
    const float* Wq   = (const float*)d_in[3];
    const float* Wk   = (const float*)d_in[4];
    const float* Wv   = (const float*)d_in[5];
    const float* Wo   = (const float*)d_in[6];
    float* out = (float*)d_out;

    float *Q, *K, *V;
    __nv_bfloat16 *xh, *xl, *Wqh, *Wql, *Wkh, *Wkl, *Wvh, *Wvl, *Woh, *Wol, *Ah, *Al;
    __nv_bfloat16 *Qh, *Ql, *Khb, *Klb, *Vth, *Vtl;
    cudaGetSymbolAddress((void**)&Q, g_Q);
    cudaGetSymbolAddress((void**)&K, g_K);
    cudaGetSymbolAddress((void**)&V, g_V);
    cudaGetSymbolAddress((void**)&xh, g_xh);
    cudaGetSymbolAddress((void**)&xl, g_xl);
    cudaGetSymbolAddress((void**)&Wqh, g_Wqh);
    cudaGetSymbolAddress((void**)&Wql, g_Wql);
    cudaGetSymbolAddress((void**)&Wkh, g_Wkh);
    cudaGetSymbolAddress((void**)&Wkl, g_Wkl);
    cudaGetSymbolAddress((void**)&Wvh, g_Wvh);
    cudaGetSymbolAddress((void**)&Wvl, g_Wvl);
    cudaGetSymbolAddress((void**)&Woh, g_Woh);
    cudaGetSymbolAddress((void**)&Wol, g_Wol);
    cudaGetSymbolAddress((void**)&Ah, g_Ah);
    cudaGetSymbolAddress((void**)&Al, g_Al);
    cudaGetSymbolAddress((void**)&Qh, g_Qh);
    cudaGetSymbolAddress((void**)&Ql, g_Ql);
    cudaGetSymbolAddress((void**)&Khb, g_Kh);
    cudaGetSymbolAddress((void**)&Klb, g_Kl);
    cudaGetSymbolAddress((void**)&Vth, g_Vth);
    cudaGetSymbolAddress((void**)&Vtl, g_Vtl);

    cudaFuncSetAttribute(gemm_bf16x3, cudaFuncAttributeMaxDynamicSharedMemorySize, GSMEM_BYTES);
    cudaFuncSetAttribute(attn_mma, cudaFuncAttributeMaxDynamicSharedMemorySize, ASMEM_BYTES);

    // zero-init split-K targets (exactly 2 atomic contributors -> deterministic)
    cudaMemsetAsync(Q, 0, (size_t)NT * QDIM * sizeof(float));
    cudaMemsetAsync(out, 0, (size_t)NT * DIM * sizeof(float));

    // conversions
    split_rows<<<(NT * DIM / 4 + 255) / 256, 256>>>(x, xh, xl, NT * DIM / 4);
    transpose_split<<<dim3(QDIM / 64, DIM / 64), 256>>>(Wq, Wqh, Wql, DIM, QDIM);
    transpose_split<<<dim3(KDIM / 64, DIM / 64), 256>>>(Wk, Wkh, Wkl, DIM, KDIM);
    transpose_split<<<dim3(KDIM / 64, DIM / 64), 256>>>(Wv, Wvh, Wvl, DIM, KDIM);
    transpose_split<<<dim3(DIM / 64, QDIM / 64), 256>>>(Wo, Woh, Wol, QDIM, DIM);

    // QKV projections (HMMA, 128x256 tile; Q with split-K=2)
    gemm_bf16x3<<<dim3(QDIM / 256, NT / 128, 2), 256, GSMEM_BYTES>>>(xh, xl, Wqh, Wql, Q, NT, QDIM, DIM);
    gemm_bf16x3<<<dim3(KDIM / 256, NT / 128, 1), 256, GSMEM_BYTES>>>(xh, xl, Wkh, Wkl, K, NT, KDIM, DIM);
    gemm_bf16x3<<<dim3(KDIM / 256, NT / 128, 1), 256, GSMEM_BYTES>>>(xh, xl, Wvh, Wvl, V, NT, KDIM, DIM);

    // RoPE + split to bf16 operands
    rope_split<<<(NT * NH * 32 + 255) / 256, 256>>>(Q, cosT, sinT, Qh, Ql, NH);
    rope_split<<<(NT * NKV * 32 + 255) / 256, 256>>>(K, cosT, sinT, Khb, Klb, NKV);
    v_split_t<<<dim3(KDIM / 64, NT / 64), 256>>>(V, Vth, Vtl);

    // HMMA flash attention
    attn_mma<<<1024, 256, ASMEM_BYTES>>>(Qh, Ql, Khb, Klb, Vth, Vtl, Ah, Al);

    // Output projection (HMMA, split-K=2)
    gemm_bf16x3<<<dim3(DIM / 256, NT / 128, 2), 256, GSMEM_BYTES>>>(Ah, Al, Woh, Wol, out, NT, DIM, QDIM);
}

// round 10
// speedup vs baseline: 3.4638x; 1.3518x over previous
#include <cuda_runtime.h>
#include <cuda_bf16.h>
#include <cuda_fp16.h>
#include <math.h>
#include <stdint.h>

// Problem constants
#define BB   2
#define SS   2048
#define DIM  4096
#define NH   32
#define NKV  8
#define HD   128
#define NT   (BB*SS)          // 4096 tokens
#define QDIM (NH*HD)          // 4096
#define KDIM (NKV*HD)         // 1024

// ---------------- scratch (device globals; no allocation allowed) ----------
__device__ float g_Q[NT * QDIM];
__device__ float g_K[NT * KDIM];
__device__ float g_V[NT * KDIM];
// fp16 projection operands (2-term split: activations hi+lo, weights single)
__device__ __half g_xh[NT * DIM];
__device__ __half g_xl[NT * DIM];
__device__ __half g_Wqh[QDIM * DIM];     // transposed [N][K]
__device__ __half g_Wkh[KDIM * DIM];
__device__ __half g_Wvh[KDIM * DIM];
__device__ __half g_Woh[DIM * QDIM];
__device__ __half g_Ah[NT * QDIM];       // attention out hi (fp16)
__device__ __half g_Al[NT * QDIM];       // attention out lo (fp16)
// bf16 attention operands (3-term split kept for attention internals)
__device__ __nv_bfloat16 g_Qh[NT * QDIM];
__device__ __nv_bfloat16 g_Ql[NT * QDIM];
__device__ __nv_bfloat16 g_Kh[NT * KDIM];
__device__ __nv_bfloat16 g_Kl[NT * KDIM];
__device__ __nv_bfloat16 g_Vth[BB * NKV * HD * SS];  // [b][g][d][s]
__device__ __nv_bfloat16 g_Vtl[BB * NKV * HD * SS];

// ======================= PTX helpers =======================
__device__ __forceinline__ uint32_t smem_u32(const void* p) {
    uint32_t a;
    asm("{ .reg .u64 t; cvta.to.shared.u64 t, %1; cvt.u32.u64 %0, t; }" : "=r"(a) : "l"(p));
    return a;
}
__device__ __forceinline__ void cp_async16(uint32_t dst, const void* src) {
    asm volatile("cp.async.cg.shared.global [%0], [%1], 16;" :: "r"(dst), "l"(src));
}
#define CP_COMMIT() asm volatile("cp.async.commit_group;" ::: "memory")
#define CP_WAIT_ALL() asm volatile("cp.async.wait_group 0;" ::: "memory")

__device__ __forceinline__ uint32_t sw128(uint32_t b) { return b ^ ((b >> 3) & 0x70); }

__device__ __forceinline__ float exp2a(float x) {
    float r;
    asm("ex2.approx.f32 %0, %1;" : "=f"(r) : "f"(x));
    return r;
}

#define LDSM4(r, addr) \
    asm volatile("ldmatrix.sync.aligned.m8n8.x4.shared.b16 {%0,%1,%2,%3}, [%4];" \
        : "=r"((r)[0]), "=r"((r)[1]), "=r"((r)[2]), "=r"((r)[3]) : "r"(addr))

#define MMA16816(c, a, b0, b1) \
    asm volatile("mma.sync.aligned.m16n8k16.row.col.f32.bf16.bf16.f32 " \
        "{%0,%1,%2,%3}, {%4,%5,%6,%7}, {%8,%9}, {%0,%1,%2,%3};" \
        : "+f"((c)[0]), "+f"((c)[1]), "+f"((c)[2]), "+f"((c)[3]) \
        : "r"((a)[0]), "r"((a)[1]), "r"((a)[2]), "r"((a)[3]), "r"(b0), "r"(b1))

#define MMAH16816(c, a, b0, b1) \
    asm volatile("mma.sync.aligned.m16n8k16.row.col.f32.f16.f16.f32 " \
        "{%0,%1,%2,%3}, {%4,%5,%6,%7}, {%8,%9}, {%0,%1,%2,%3};" \
        : "+f"((c)[0]), "+f"((c)[1]), "+f"((c)[2]), "+f"((c)[3]) \
        : "r"((a)[0]), "r"((a)[1]), "r"((a)[2]), "r"((a)[3]), "r"(b0), "r"(b1))

// =============== fp16 2-term HMMA GEMM, 128x256 tile, optional split-K ======
// C[M,N] = (Ah+Al)[M,K] * Bh^T, B [N,K] row-major fp16.
// smem/stage: Ah 16K | Al 16K | Bh 32K = 64KB; 2 stages = 128KB.
#define GSMEM_BYTES (2 * 65536)

__device__ __forceinline__ void load_stage_part(
    uint32_t buf, const __half* Ah, const __half* Al, const __half* Bh,
    int row0, int col0, int K, int kchunk, int tid, int part)
{
    #pragma unroll
    for (int j = 0; j < 4; j++) {
        const int c = tid + part * 1024 + j * 256;
        if (c < 1024) {
            const int r = c >> 3, sg = c & 7;
            const uint32_t dst = buf + sw128(r * 128 + sg * 16);
            cp_async16(dst, Ah + (size_t)(row0 + r) * K + kchunk * 64 + sg * 8);
        } else if (c < 2048) {
            const int idx = c - 1024;
            const int r = idx >> 3, sg = idx & 7;
            const uint32_t dst = buf + 16384 + sw128(r * 128 + sg * 16);
            cp_async16(dst, Al + (size_t)(row0 + r) * K + kchunk * 64 + sg * 8);
        } else {
            const int idx = c - 2048;
            const int r = idx >> 3, sg = idx & 7;      // r 0..255
            const uint32_t dst = buf + 32768 + sw128(r * 128 + sg * 16);
            cp_async16(dst, Bh + (size_t)(col0 + r) * K + kchunk * 64 + sg * 8);
        }
    }
}

__global__ __launch_bounds__(256, 1) void gemm_fp16x2(
    const __half* __restrict__ Ah, const __half* __restrict__ Al,
    const __half* __restrict__ Bh,
    float* __restrict__ C, int M, int N, int K)
{
    extern __shared__ char smc[];
    const uint32_t sb = smem_u32(smc);
    const int tid = threadIdx.x;
    const int wid = tid >> 5;
    const int lane = tid & 31;
    const int row0 = blockIdx.y * 128;
    const int col0 = blockIdx.x * 256;
    const int nz = gridDim.z;
    const int K2 = K / nz;
    const int kb = blockIdx.z * (K2 / 64);

    const int wm0 = (wid >> 2) * 64;
    const int wn0 = (wid & 3) * 64;

    float acc[4][8][4];
    #pragma unroll
    for (int i = 0; i < 4; i++)
        #pragma unroll
        for (int j = 0; j < 8; j++)
            #pragma unroll
            for (int r = 0; r < 4; r++) acc[i][j][r] = 0.f;

    const int KT = K2 / 64;
    #pragma unroll
    for (int p = 0; p < 4; p++)
        load_stage_part(sb, Ah, Al, Bh, row0, col0, K, kb, tid, p);
    CP_COMMIT();

    for (int it = 0; it < KT; it++) {
        CP_WAIT_ALL();
        __syncthreads();
        const uint32_t buf = sb + (it & 1) * 65536;
        const uint32_t nbuf = sb + ((it + 1) & 1) * 65536;
        const bool more = (it + 1 < KT);

        const uint32_t aHb = buf;
        const uint32_t aLb = buf + 16384;
        const uint32_t bHb = buf + 32768;

        #pragma unroll
        for (int k16 = 0; k16 < 4; k16++) {
            if (more) {
                load_stage_part(nbuf, Ah, Al, Bh, row0, col0, K, kb + it + 1, tid, k16);
                if (k16 == 3) CP_COMMIT();
            }
            const int colb = k16 * 32 + (lane >> 4) * 16;
            uint32_t ah[4][4], al[4][4];
            #pragma unroll
            for (int mi = 0; mi < 4; mi++) {
                const uint32_t off = sw128((wm0 + mi * 16 + (lane & 15)) * 128 + colb);
                LDSM4(ah[mi], aHb + off);
                LDSM4(al[mi], aLb + off);
            }
            #pragma unroll
            for (int hb = 0; hb < 2; hb++) {
                uint32_t bh[2][4];
                #pragma unroll
                for (int np = 0; np < 2; np++) {
                    const uint32_t off =
                        sw128((wn0 + hb * 32 + np * 16 + (lane & 15)) * 128 + colb);
                    LDSM4(bh[np], bHb + off);
                }
                #pragma unroll
                for (int mi = 0; mi < 4; mi++)
                    #pragma unroll
                    for (int nj = 0; nj < 4; nj++) {
                        const int np = nj >> 1, h = nj & 1;
                        MMAH16816(acc[mi][hb * 4 + nj], ah[mi], bh[np][h], bh[np][2 + h]);
                    }
                #pragma unroll
                for (int mi = 0; mi < 4; mi++)
                    #pragma unroll
                    for (int nj = 0; nj < 4; nj++) {
                        const int np = nj >> 1, h = nj & 1;
                        MMAH16816(acc[mi][hb * 4 + nj], al[mi], bh[np][h], bh[np][2 + h]);
                    }
            }
        }
    }

    if (nz > 1) {
        #pragma unroll
        for (int mi = 0; mi < 4; mi++) {
            #pragma unroll
            for (int nj = 0; nj < 8; nj++) {
                const int row = row0 + wm0 + mi * 16 + (lane >> 2);
                const int col = col0 + wn0 + nj * 8 + (lane & 3) * 2;
                float* p0 = C + (size_t)row * N + col;
                float* p1 = C + (size_t)(row + 8) * N + col;
                atomicAdd(p0,     acc[mi][nj][0]);
                atomicAdd(p0 + 1, acc[mi][nj][1]);
                atomicAdd(p1,     acc[mi][nj][2]);
                atomicAdd(p1 + 1, acc[mi][nj][3]);
            }
        }
    } else {
        #pragma unroll
        for (int mi = 0; mi < 4; mi++) {
            #pragma unroll
            for (int nj = 0; nj < 8; nj++) {
                const int row = row0 + wm0 + mi * 16 + (lane >> 2);
                const int col = col0 + wn0 + nj * 8 + (lane & 3) * 2;
                *(float2*)(C + (size_t)row * N + col)       = make_float2(acc[mi][nj][0], acc[mi][nj][1]);
                *(float2*)(C + (size_t)(row + 8) * N + col) = make_float2(acc[mi][nj][2], acc[mi][nj][3]);
            }
        }
    }
}

// =============== fp32 -> fp16 hi/lo split (row-major) ===========
__global__ void split_rows_h(const float* __restrict__ X,
                             __half* __restrict__ Xh,
                             __half* __restrict__ Xl, int total4)
{
    int i = blockIdx.x * blockDim.x + threadIdx.x;
    if (i >= total4) return;
    float4 v = *(const float4*)(X + (size_t)i * 4);
    __half h[4], l[4];
    float vv[4] = {v.x, v.y, v.z, v.w};
    #pragma unroll
    for (int j = 0; j < 4; j++) {
        h[j] = __float2half_rn(vv[j]);
        l[j] = __float2half_rn(vv[j] - __half2float(h[j]));
    }
    *(uint2*)(Xh + (size_t)i * 4) = *(uint2*)h;
    *(uint2*)(Xl + (size_t)i * 4) = *(uint2*)l;
}

// =============== transpose + fp16 quantize: W[K,N] fp32 -> T [N,K] fp16 =====
__global__ __launch_bounds__(256) void transpose_h(
    const float* __restrict__ W, __half* __restrict__ Th, int Kd, int Nd)
{
    __shared__ float t[64][65];
    const int n0 = blockIdx.x * 64, k0 = blockIdx.y * 64;
    const int tid = threadIdx.x;
    #pragma unroll
    for (int i = 0; i < 4; i++) {
        int it = tid + i * 256;
        int r = it >> 4;
        int c4 = (it & 15) * 4;
        float4 v = *(const float4*)(W + (size_t)(k0 + r) * Nd + n0 + c4);
        t[r][c4] = v.x; t[r][c4 + 1] = v.y; t[r][c4 + 2] = v.z; t[r][c4 + 3] = v.w;
    }
    __syncthreads();
    #pragma unroll
    for (int i = 0; i < 4; i++) {
        int it = tid + i * 256;
        int n = it >> 4;
        int kc = (it & 15) * 4;
        __half h[4];
        #pragma unroll
        for (int j = 0; j < 4; j++) h[j] = __float2half_rn(t[kc + j][n]);
        *(uint2*)(Th + (size_t)(n0 + n) * Kd + k0 + kc) = *(uint2*)h;
    }
}

// =============== RoPE + bf16 hi/lo split =====================================
__global__ void rope_split(const float* __restrict__ X,
                           const float* __restrict__ cosT,
                           const float* __restrict__ sinT,
                           __nv_bfloat16* __restrict__ Xh,
                           __nv_bfloat16* __restrict__ Xl, int nHeads)
{
    int idx = blockIdx.x * blockDim.x + threadIdx.x;
    int total = NT * nHeads * 32;
    if (idx >= total) return;
    int j = idx & 31;
    int hh = (idx >> 5) % nHeads;
    int t = idx / (32 * nHeads);
    int s = t & (SS - 1);
    int d = 2 * j;

    const float* p = X + (size_t)t * (nHeads * HD) + hh * HD;
    float x0 = p[d], x1 = p[d + 1], y0 = p[d + 64], y1 = p[d + 65];
    const float* cp = cosT + s * HD;
    const float* sp = sinT + s * HD;
    float r0 = x0 * cp[d]      - y0 * sp[d];
    float r1 = x1 * cp[d + 1]  - y1 * sp[d + 1];
    float r2 = y0 * cp[d + 64] + x0 * sp[d + 64];
    float r3 = y1 * cp[d + 65] + x1 * sp[d + 65];

    size_t o0 = (size_t)t * (nHeads * HD) + hh * HD + d;
    __nv_bfloat16 h0 = __float2bfloat16(r0), h1 = __float2bfloat16(r1);
    __nv_bfloat16 h2 = __float2bfloat16(r2), h3 = __float2bfloat16(r3);
    __nv_bfloat16 q0 = __float2bfloat16(r0 - __bfloat162float(h0));
    __nv_bfloat16 q1 = __float2bfloat16(r1 - __bfloat162float(h1));
    __nv_bfloat16 q2 = __float2bfloat16(r2 - __bfloat162float(h2));
    __nv_bfloat16 q3 = __float2bfloat16(r3 - __bfloat162float(h3));
    __nv_bfloat16 hp[2] = {h0, h1}; *(uint32_t*)(Xh + o0) = *(uint32_t*)hp;
    __nv_bfloat16 lp[2] = {q0, q1}; *(uint32_t*)(Xl + o0) = *(uint32_t*)lp;
    __nv_bfloat16 hp2[2] = {h2, h3}; *(uint32_t*)(Xh + o0 + 64) = *(uint32_t*)hp2;
    __nv_bfloat16 lp2[2] = {q2, q3}; *(uint32_t*)(Xl + o0 + 64) = *(uint32_t*)lp2;
}

// =============== V: fp32 [NT][KDIM] -> transposed bf16 hi/lo [b][g][d][s] ====
__global__ __launch_bounds__(256) void v_split_t(const float* __restrict__ V,
                                                 __nv_bfloat16* __restrict__ Vth,
                                                 __nv_bfloat16* __restrict__ Vtl)
{
    __shared__ float t[64][65];
    const int c0 = blockIdx.x * 64;
    const int r0 = blockIdx.y * 64;
    const int tid = threadIdx.x;
    #pragma unroll
    for (int i = 0; i < 4; i++) {
        int it = tid + i * 256;
        int r = it >> 4;
        int c4 = (it & 15) * 4;
        float4 v = *(const float4*)(V + (size_t)(r0 + r) * KDIM + c0 + c4);
        t[r][c4] = v.x; t[r][c4 + 1] = v.y; t[r][c4 + 2] = v.z; t[r][c4 + 3] = v.w;
    }
    __syncthreads();
    const int b = r0 >> 11;
    const int sbase = r0 & (SS - 1);
    #pragma unroll
    for (int i = 0; i < 4; i++) {
        int it = tid + i * 256;
        int n = it >> 4;
        int kc = (it & 15) * 4;
        int col = c0 + n;
        int g = col >> 7;
        int d = col & 127;
        __nv_bfloat16 h[4], l[4];
        #pragma unroll
        for (int j = 0; j < 4; j++) {
            float v = t[kc + j][n];
            h[j] = __float2bfloat16(v);
            l[j] = __float2bfloat16(v - __bfloat162float(h[j]));
        }
        size_t o = ((size_t)((b * NKV + g) * HD) + d) * SS + sbase + kc;
        *(uint2*)(Vth + o) = *(uint2*)h;
        *(uint2*)(Vtl + o) = *(uint2*)l;
    }
}

// ---------------- HMMA flash attention (3-term bf16, causal, GQA) ----------
#define ASMEM_BYTES (196608)

__device__ __forceinline__ void attn_load_kv(
    uint32_t st, const __nv_bfloat16* Kh, const __nv_bfloat16* Kl,
    const __nv_bfloat16* Vth, const __nv_bfloat16* Vtl,
    int b, int g, int kt, int tid)
{
    const int tk0 = b * SS + kt * 64;
    #pragma unroll 4
    for (int c = tid; c < 2048; c += 256) {
        int hl = c >> 10, cc = c & 1023;
        int r = cc >> 4, sg = cc & 15, half = sg >> 3, sgi = sg & 7;
        const __nv_bfloat16* base = hl ? Kl : Kh;
        const void* src = base + (size_t)(tk0 + r) * KDIM + g * HD + half * 64 + sgi * 8;
        uint32_t dst = st + hl * 16384 + half * 8192 + sw128(r * 128 + sgi * 16);
        cp_async16(dst, src);
    }
    const size_t vrow0 = (size_t)((b * NKV + g) * HD) * SS;
    #pragma unroll 4
    for (int c = tid; c < 2048; c += 256) {
        int hl = c >> 10, cc = c & 1023;
        int d = cc >> 3, sg = cc & 7;
        const __nv_bfloat16* base = hl ? Vtl : Vth;
        const void* src = base + vrow0 + (size_t)d * SS + kt * 64 + sg * 8;
        uint32_t dst = st + 32768 + hl * 16384 + sw128(d * 128 + sg * 16);
        cp_async16(dst, src);
    }
    CP_COMMIT();
}

__global__ __launch_bounds__(256, 1) void attn_mma(
    const __nv_bfloat16* __restrict__ Qh, const __nv_bfloat16* __restrict__ Ql,
    const __nv_bfloat16* __restrict__ Kh, const __nv_bfloat16* __restrict__ Kl,
    const __nv_bfloat16* __restrict__ Vth, const __nv_bfloat16* __restrict__ Vtl,
    __half* __restrict__ Oh, __half* __restrict__ Ol)
{
    extern __shared__ char smc[];
    const uint32_t sb = smem_u32(smc);
    const int tid = threadIdx.x, wid = tid >> 5, lane = tid & 31;
    const int bid = blockIdx.x;
    const int qb = 15 - (bid >> 6);     // heavy-first
    const int bh = bid & 63;
    const int b = bh >> 5, h = bh & 31, g = h >> 2;
    const int tok0 = b * SS + qb * 128;
    const int KT = 2 * qb + 2;
    const float SCL = 0.08838834764831845f * 1.4426950408889634f;

    #pragma unroll 4
    for (int c = tid; c < 4096; c += 256) {
        int hl = c >> 11, cc = c & 2047;
        int r = cc >> 4, sg = cc & 15, half = sg >> 3, sgi = sg & 7;
        const __nv_bfloat16* base = hl ? Ql : Qh;
        const void* src = base + (size_t)(tok0 + r) * QDIM + h * HD + half * 64 + sgi * 8;
        uint32_t dst = sb + hl * 32768 + half * 16384 + sw128(r * 128 + sgi * 16);
        cp_async16(dst, src);
    }
    attn_load_kv(sb + 65536, Kh, Kl, Vth, Vtl, b, g, 0, tid);

    float o[16][4];
    #pragma unroll
    for (int nd = 0; nd < 16; nd++)
        #pragma unroll
        for (int e = 0; e < 4; e++) o[nd][e] = 0.f;
    float m0 = -1e30f, m1 = -1e30f, l0 = 0.f, l1 = 0.f;

    const int qg0 = qb * 128 + wid * 16 + (lane >> 2);
    const int qg1 = qg0 + 8;

    for (int kt = 0; kt < KT; kt++) {
        CP_WAIT_ALL();
        __syncthreads();
        if (kt + 1 < KT)
            attn_load_kv(sb + 65536 + ((kt + 1) & 1) * 65536, Kh, Kl, Vth, Vtl, b, g, kt + 1, tid);

        const uint32_t st = sb + 65536 + (kt & 1) * 65536;
        const bool skip = kt * 64 > qb * 128 + wid * 16 + 15;

        if (!skip) {
            float s[8][4];
            #pragma unroll
            for (int nj = 0; nj < 8; nj++)
                #pragma unroll
                for (int e = 0; e < 4; e++) s[nj][e] = 0.f;

            #pragma unroll
            for (int k16 = 0; k16 < 8; k16++) {
                const int half = k16 >> 2;
                const int cb = (k16 & 3) * 32 + (lane >> 4) * 16;
                const uint32_t qoff = sw128((wid * 16 + (lane & 15)) * 128 + cb);
                uint32_t ah[4], al[4];
                LDSM4(ah, sb + half * 16384 + qoff);
                LDSM4(al, sb + 32768 + half * 16384 + qoff);
                uint32_t bhf[4][4], blf[4][4];
                #pragma unroll
                for (int c = 0; c < 4; c++) {
                    const uint32_t koff = sw128((c * 16 + (lane & 15)) * 128 + cb);
                    LDSM4(bhf[c], st + half * 8192 + koff);
                    LDSM4(blf[c], st + 16384 + half * 8192 + koff);
                }
                #pragma unroll
                for (int nj = 0; nj < 8; nj++) {
                    const int np = nj >> 1, h2 = nj & 1;
                    MMA16816(s[nj], ah, bhf[np][h2], bhf[np][2 + h2]);
                }
                #pragma unroll
                for (int nj = 0; nj < 8; nj++) {
                    const int np = nj >> 1, h2 = nj & 1;
                    MMA16816(s[nj], al, bhf[np][h2], bhf[np][2 + h2]);
                }
                #pragma unroll
                for (int nj = 0; nj < 8; nj++) {
                    const int np = nj >> 1, h2 = nj & 1;
                    MMA16816(s[nj], ah, blf[np][h2], blf[np][2 + h2]);
                }
            }

            const bool domask = (kt * 64 + 63) > qg0;
            #pragma unroll
            for (int nj = 0; nj < 8; nj++) {
                #pragma unroll
                for (int e = 0; e < 4; e++) s[nj][e] *= SCL;
                if (domask) {
                    const int kc = kt * 64 + nj * 8 + (lane & 3) * 2;
                    if (kc     > qg0) s[nj][0] = -1e30f;
                    if (kc + 1 > qg0) s[nj][1] = -1e30f;
                    if (kc     > qg1) s[nj][2] = -1e30f;
                    if (kc + 1 > qg1) s[nj][3] = -1e30f;
                }
            }
            float mx0 = -1e30f, mx1 = -1e30f;
            #pragma unroll
            for (int nj = 0; nj < 8; nj++) {
                mx0 = fmaxf(mx0, fmaxf(s[nj][0], s[nj][1]));
                mx1 = fmaxf(mx1, fmaxf(s[nj][2], s[nj][3]));
            }
            mx0 = fmaxf(mx0, __shfl_xor_sync(0xffffffffu, mx0, 1));
            mx0 = fmaxf(mx0, __shfl_xor_sync(0xffffffffu, mx0, 2));
            mx1 = fmaxf(mx1, __shfl_xor_sync(0xffffffffu, mx1, 1));
            mx1 = fmaxf(mx1, __shfl_xor_sync(0xffffffffu, mx1, 2));
            const float nm0 = fmaxf(m0, mx0), nm1 = fmaxf(m1, mx1);
            const float c0 = exp2a(m0 - nm0), c1 = exp2a(m1 - nm1);
            float rs0 = 0.f, rs1 = 0.f;
            #pragma unroll
            for (int nj = 0; nj < 8; nj++) {
                s[nj][0] = exp2a(s[nj][0] - nm0);
                s[nj][1] = exp2a(s[nj][1] - nm0);
                s[nj][2] = exp2a(s[nj][2] - nm1);
                s[nj][3] = exp2a(s[nj][3] - nm1);
                rs0 += s[nj][0] + s[nj][1];
                rs1 += s[nj][2] + s[nj][3];
            }
            rs0 += __shfl_xor_sync(0xffffffffu, rs0, 1);
            rs0 += __shfl_xor_sync(0xffffffffu, rs0, 2);
            rs1 += __shfl_xor_sync(0xffffffffu, rs1, 1);
            rs1 += __shfl_xor_sync(0xffffffffu, rs1, 2);
            m0 = nm0; m1 = nm1;
            l0 = l0 * c0 + rs0;
            l1 = l1 * c1 + rs1;
            #pragma unroll
            for (int nd = 0; nd < 16; nd++) {
                o[nd][0] *= c0; o[nd][1] *= c0;
                o[nd][2] *= c1; o[nd][3] *= c1;
            }

            #pragma unroll
            for (int j2 = 0; j2 < 4; j2++) {
                const int n0 = 2 * j2, n1 = 2 * j2 + 1;
                uint32_t aPh[4], aPl[4];
                __nv_bfloat162 t0 = __floats2bfloat162_rn(s[n0][0], s[n0][1]);
                __nv_bfloat162 t1 = __floats2bfloat162_rn(s[n0][2], s[n0][3]);
                __nv_bfloat162 t2 = __floats2bfloat162_rn(s[n1][0], s[n1][1]);
                __nv_bfloat162 t3 = __floats2bfloat162_rn(s[n1][2], s[n1][3]);
                aPh[0] = *(uint32_t*)&t0; aPh[1] = *(uint32_t*)&t1;
                aPh[2] = *(uint32_t*)&t2; aPh[3] = *(uint32_t*)&t3;
                __nv_bfloat162 u0 = __floats2bfloat162_rn(s[n0][0] - __bfloat162float(t0.x),
                                                          s[n0][1] - __bfloat162float(t0.y));
                __nv_bfloat162 u1 = __floats2bfloat162_rn(s[n0][2] - __bfloat162float(t1.x),
                                                          s[n0][3] - __bfloat162float(t1.y));
                __nv_bfloat162 u2 = __floats2bfloat162_rn(s[n1][0] - __bfloat162float(t2.x),
                                                          s[n1][1] - __bfloat162float(t2.y));
                __nv_bfloat162 u3 = __floats2bfloat162_rn(s[n1][2] - __bfloat162float(t3.x),
                                                          s[n1][3] - __bfloat162float(t3.y));
                aPl[0] = *(uint32_t*)&u0; aPl[1] = *(uint32_t*)&u1;
                aPl[2] = *(uint32_t*)&u2; aPl[3] = *(uint32_t*)&u3;

                #pragma unroll
                for (int c = 0; c < 8; c++) {
                    const uint32_t voff = sw128((c * 16 + (lane & 15)) * 128 + j2 * 32 + (lane >> 4) * 16);
                    uint32_t vh[4], vl[4];
                    LDSM4(vh, st + 32768 + voff);
                    LDSM4(vl, st + 49152 + voff);
                    MMA16816(o[2 * c],     aPh, vh[0], vh[2]);
                    MMA16816(o[2 * c + 1], aPh, vh[1], vh[3]);
                    MMA16816(o[2 * c],     aPl, vh[0], vh[2]);
                    MMA16816(o[2 * c + 1], aPl, vh[1], vh[3]);
                    MMA16816(o[2 * c],     aPh, vl[0], vl[2]);
                    MMA16816(o[2 * c + 1], aPh, vl[1], vl[3]);
                }
            }
        }
    }

    // epilogue: normalize, split to fp16 hi/lo for the Wo fp16 GEMM
    const float il0 = 1.f / l0, il1 = 1.f / l1;
    const int row0g = tok0 + wid * 16 + (lane >> 2);
    #pragma unroll
    for (int nd = 0; nd < 16; nd++) {
        const int col = h * HD + nd * 8 + (lane & 3) * 2;
        float v00 = o[nd][0] * il0, v01 = o[nd][1] * il0;
        float v10 = o[nd][2] * il1, v11 = o[nd][3] * il1;
        __half2 h0 = __floats2half2_rn(v00, v01);
        __half2 h1 = __floats2half2_rn(v10, v11);
        __half2 q0 = __floats2half2_rn(v00 - __low2float(h0), v01 - __high2float(h0));
        __half2 q1 = __floats2half2_rn(v10 - __low2float(h1), v11 - __high2float(h1));
        *(uint32_t*)(Oh + (size_t)row0g * QDIM + col)       = *(uint32_t*)&h0;
        *(uint32_t*)(Ol + (size_t)row0g * QDIM + col)       = *(uint32_t*)&q0;
        *(uint32_t*)(Oh + (size_t)(row0g + 8) * QDIM + col) = *(uint32_t*)&h1;
        *(uint32_t*)(Ol + (size_t)(row0g + 8) * QDIM + col) = *(uint32_t*)&q1;
    }
}

// ---------------- launcher ---------------------------------------------------
extern "C" void kernel_launch(void* const* d_in, const int* in_sizes, int n_in,
                              void* d_out, int out_size)
{
    const float* x    = (const float*)d_in[0];
    const float* cosT = (const float*)d_in[1];
    const float* sinT = (const float*)d_in[2];
    const float* Wq   = (const float*)d_in[3];
    const float* Wk   = (const float*)d_in[4];
    const float* Wv   = (const float*)d_in[5];
    const float* Wo   = (const float*)d_in[6];
    float* out = (float*)d_out;

    float *Q, *K, *V;
    __half *xh, *xl, *Wqh, *Wkh, *Wvh, *Woh, *Ah, *Al;
    __nv_bfloat16 *Qh, *Ql, *Khb, *Klb, *Vth, *Vtl;
    cudaGetSymbolAddress((void**)&Q, g_Q);
    cudaGetSymbolAddress((void**)&K, g_K);
    cudaGetSymbolAddress((void**)&V, g_V);
    cudaGetSymbolAddress((void**)&xh, g_xh);
    cudaGetSymbolAddress((void**)&xl, g_xl);
    cudaGetSymbolAddress((void**)&Wqh, g_Wqh);
    cudaGetSymbolAddress((void**)&Wkh, g_Wkh);
    cudaGetSymbolAddress((void**)&Wvh, g_Wvh);
    cudaGetSymbolAddress((void**)&Woh, g_Woh);
    cudaGetSymbolAddress((void**)&Ah, g_Ah);
    cudaGetSymbolAddress((void**)&Al, g_Al);
    cudaGetSymbolAddress((void**)&Qh, g_Qh);
    cudaGetSymbolAddress((void**)&Ql, g_Ql);
    cudaGetSymbolAddress((void**)&Khb, g_Kh);
    cudaGetSymbolAddress((void**)&Klb, g_Kl);
    cudaGetSymbolAddress((void**)&Vth, g_Vth);
    cudaGetSymbolAddress((void**)&Vtl, g_Vtl);

    cudaFuncSetAttribute(gemm_fp16x2, cudaFuncAttributeMaxDynamicSharedMemorySize, GSMEM_BYTES);
    cudaFuncSetAttribute(attn_mma, cudaFuncAttributeMaxDynamicSharedMemorySize, ASMEM_BYTES);

    // zero-init split-K targets (exactly 2 atomic contributors -> deterministic)
    cudaMemsetAsync(Q, 0, (size_t)NT * QDIM * sizeof(float));
    cudaMemsetAsync(out, 0, (size_t)NT * DIM * sizeof(float));

    // conversions
    split_rows_h<<<(NT * DIM / 4 + 255) / 256, 256>>>(x, xh, xl, NT * DIM / 4);
    transpose_h<<<dim3(QDIM / 64, DIM / 64), 256>>>(Wq, Wqh, DIM, QDIM);
    transpose_h<<<dim3(KDIM / 64, DIM / 64), 256>>>(Wk, Wkh, DIM, KDIM);
    transpose_h<<<dim3(KDIM / 64, DIM / 64), 256>>>(Wv, Wvh, DIM, KDIM);
    transpose_h<<<dim3(DIM / 64, QDIM / 64), 256>>>(Wo, Woh, QDIM, DIM);

    // QKV projections (fp16 2-term HMMA; Q with split-K=2)
    gemm_fp16x2<<<dim3(QDIM / 256, NT / 128, 2), 256, GSMEM_BYTES>>>(xh, xl, Wqh, Q, NT, QDIM, DIM);
    gemm_fp16x2<<<dim3(KDIM / 256, NT / 128, 1), 256, GSMEM_BYTES>>>(xh, xl, Wkh, K, NT, KDIM, DIM);
    gemm_fp16x2<<<dim3(KDIM / 256, NT / 128, 1), 256, GSMEM_BYTES>>>(xh, xl, Wvh, V, NT, KDIM, DIM);

    // RoPE + split to bf16 operands
    rope_split<<<(NT * NH * 32 + 255) / 256, 256>>>(Q, cosT, sinT, Qh, Ql, NH);
    rope_split<<<(NT * NKV * 32 + 255) / 256, 256>>>(K, cosT, sinT, Khb, Klb, NKV);
    v_split_t<<<dim3(KDIM / 64, NT / 64), 256>>>(V, Vth, Vtl);

    // HMMA flash attention (bf16 3-term) -> fp16 hi/lo output
    attn_mma<<<1024, 256, ASMEM_BYTES>>>(Qh, Ql, Khb, Klb, Vth, Vtl, Ah, Al);

    // Output projection (fp16 2-term, split-K=2)
    gemm_fp16x2<<<dim3(DIM / 256, NT / 128, 2), 256, GSMEM_BYTES>>>(Ah, Al, Woh, out, NT, DIM, QDIM);
}

// round 11
// speedup vs baseline: 3.7180x; 1.0734x over previous
#include <cuda_runtime.h>
#include <cuda_bf16.h>
#include <cuda_fp16.h>
#include <math.h>
#include <stdint.h>

// Problem constants
#define BB   2
#define SS   2048
#define DIM  4096
#define NH   32
#define NKV  8
#define HD   128
#define NT   (BB*SS)          // 4096 tokens
#define QDIM (NH*HD)          // 4096
#define KDIM (NKV*HD)         // 1024

// ---------------- scratch (device globals; no allocation allowed) ----------
__device__ float g_Q[NT * QDIM];
__device__ float g_K[NT * KDIM];
__device__ float g_V[NT * KDIM];
// fp16 projection operands (2-term split: activations hi+lo, weights single)
__device__ __half g_xh[NT * DIM];
__device__ __half g_xl[NT * DIM];
__device__ __half g_Wqh[QDIM * DIM];     // transposed [N][K]
__device__ __half g_Wkh[KDIM * DIM];
__device__ __half g_Wvh[KDIM * DIM];
__device__ __half g_Woh[DIM * QDIM];
__device__ __half g_Ah[NT * QDIM];       // attention out hi (fp16)
__device__ __half g_Al[NT * QDIM];       // attention out lo (fp16)
// fp16 attention operands
__device__ __half g_Qah[NT * QDIM];      // Q hi (exact split)
__device__ __half g_Qal[NT * QDIM];      // Q lo
__device__ __half g_Kah[NT * KDIM];      // K single fp16
__device__ __half g_Vt[BB * NKV * HD * SS];  // V transposed [b][g][d][s], single fp16

// ======================= PTX helpers =======================
__device__ __forceinline__ uint32_t smem_u32(const void* p) {
    uint32_t a;
    asm("{ .reg .u64 t; cvta.to.shared.u64 t, %1; cvt.u32.u64 %0, t; }" : "=r"(a) : "l"(p));
    return a;
}
__device__ __forceinline__ void cp_async16(uint32_t dst, const void* src) {
    asm volatile("cp.async.cg.shared.global [%0], [%1], 16;" :: "r"(dst), "l"(src));
}
#define CP_COMMIT() asm volatile("cp.async.commit_group;" ::: "memory")
#define CP_WAIT_ALL() asm volatile("cp.async.wait_group 0;" ::: "memory")

__device__ __forceinline__ uint32_t sw128(uint32_t b) { return b ^ ((b >> 3) & 0x70); }

__device__ __forceinline__ float exp2a(float x) {
    float r;
    asm("ex2.approx.f32 %0, %1;" : "=f"(r) : "f"(x));
    return r;
}

#define LDSM4(r, addr) \
    asm volatile("ldmatrix.sync.aligned.m8n8.x4.shared.b16 {%0,%1,%2,%3}, [%4];" \
        : "=r"((r)[0]), "=r"((r)[1]), "=r"((r)[2]), "=r"((r)[3]) : "r"(addr))

#define MMAH16816(c, a, b0, b1) \
    asm volatile("mma.sync.aligned.m16n8k16.row.col.f32.f16.f16.f32 " \
        "{%0,%1,%2,%3}, {%4,%5,%6,%7}, {%8,%9}, {%0,%1,%2,%3};" \
        : "+f"((c)[0]), "+f"((c)[1]), "+f"((c)[2]), "+f"((c)[3]) \
        : "r"((a)[0]), "r"((a)[1]), "r"((a)[2]), "r"((a)[3]), "r"(b0), "r"(b1))

// =============== fp16 2-term HMMA GEMM, 128x256 tile, optional split-K ======
#define GSMEM_BYTES (2 * 65536)

__device__ __forceinline__ void load_stage_part(
    uint32_t buf, const __half* Ah, const __half* Al, const __half* Bh,
    int row0, int col0, int K, int kchunk, int tid, int part)
{
    #pragma unroll
    for (int j = 0; j < 4; j++) {
        const int c = tid + part * 1024 + j * 256;
        if (c < 1024) {
            const int r = c >> 3, sg = c & 7;
            const uint32_t dst = buf + sw128(r * 128 + sg * 16);
            cp_async16(dst, Ah + (size_t)(row0 + r) * K + kchunk * 64 + sg * 8);
        } else if (c < 2048) {
            const int idx = c - 1024;
            const int r = idx >> 3, sg = idx & 7;
            const uint32_t dst = buf + 16384 + sw128(r * 128 + sg * 16);
            cp_async16(dst, Al + (size_t)(row0 + r) * K + kchunk * 64 + sg * 8);
        } else {
            const int idx = c - 2048;
            const int r = idx >> 3, sg = idx & 7;      // r 0..255
            const uint32_t dst = buf + 32768 + sw128(r * 128 + sg * 16);
            cp_async16(dst, Bh + (size_t)(col0 + r) * K + kchunk * 64 + sg * 8);
        }
    }
}

__global__ __launch_bounds__(256, 1) void gemm_fp16x2(
    const __half* __restrict__ Ah, const __half* __restrict__ Al,
    const __half* __restrict__ Bh,
    float* __restrict__ C, int M, int N, int K)
{
    extern __shared__ char smc[];
    const uint32_t sb = smem_u32(smc);
    const int tid = threadIdx.x;
    const int wid = tid >> 5;
    const int lane = tid & 31;
    const int row0 = blockIdx.y * 128;
    const int col0 = blockIdx.x * 256;
    const int nz = gridDim.z;
    const int K2 = K / nz;
    const int kb = blockIdx.z * (K2 / 64);

    const int wm0 = (wid >> 2) * 64;
    const int wn0 = (wid & 3) * 64;

    float acc[4][8][4];
    #pragma unroll
    for (int i = 0; i < 4; i++)
        #pragma unroll
        for (int j = 0; j < 8; j++)
            #pragma unroll
            for (int r = 0; r < 4; r++) acc[i][j][r] = 0.f;

    const int KT = K2 / 64;
    #pragma unroll
    for (int p = 0; p < 4; p++)
        load_stage_part(sb, Ah, Al, Bh, row0, col0, K, kb, tid, p);
    CP_COMMIT();

    for (int it = 0; it < KT; it++) {
        CP_WAIT_ALL();
        __syncthreads();
        const uint32_t buf = sb + (it & 1) * 65536;
        const uint32_t nbuf = sb + ((it + 1) & 1) * 65536;
        const bool more = (it + 1 < KT);

        const uint32_t aHb = buf;
        const uint32_t aLb = buf + 16384;
        const uint32_t bHb = buf + 32768;

        #pragma unroll
        for (int k16 = 0; k16 < 4; k16++) {
            if (more) {
                load_stage_part(nbuf, Ah, Al, Bh, row0, col0, K, kb + it + 1, tid, k16);
                if (k16 == 3) CP_COMMIT();
            }
            const int colb = k16 * 32 + (lane >> 4) * 16;
            uint32_t ah[4][4], al[4][4];
            #pragma unroll
            for (int mi = 0; mi < 4; mi++) {
                const uint32_t off = sw128((wm0 + mi * 16 + (lane & 15)) * 128 + colb);
                LDSM4(ah[mi], aHb + off);
                LDSM4(al[mi], aLb + off);
            }
            #pragma unroll
            for (int hb = 0; hb < 2; hb++) {
                uint32_t bh[2][4];
                #pragma unroll
                for (int np = 0; np < 2; np++) {
                    const uint32_t off =
                        sw128((wn0 + hb * 32 + np * 16 + (lane & 15)) * 128 + colb);
                    LDSM4(bh[np], bHb + off);
                }
                #pragma unroll
                for (int mi = 0; mi < 4; mi++)
                    #pragma unroll
                    for (int nj = 0; nj < 4; nj++) {
                        const int np = nj >> 1, h = nj & 1;
                        MMAH16816(acc[mi][hb * 4 + nj], ah[mi], bh[np][h], bh[np][2 + h]);
                    }
                #pragma unroll
                for (int mi = 0; mi < 4; mi++)
                    #pragma unroll
                    for (int nj = 0; nj < 4; nj++) {
                        const int np = nj >> 1, h = nj & 1;
                        MMAH16816(acc[mi][hb * 4 + nj], al[mi], bh[np][h], bh[np][2 + h]);
                    }
            }
        }
    }

    if (nz > 1) {
        #pragma unroll
        for (int mi = 0; mi < 4; mi++) {
            #pragma unroll
            for (int nj = 0; nj < 8; nj++) {
                const int row = row0 + wm0 + mi * 16 + (lane >> 2);
                const int col = col0 + wn0 + nj * 8 + (lane & 3) * 2;
                float* p0 = C + (size_t)row * N + col;
                float* p1 = C + (size_t)(row + 8) * N + col;
                atomicAdd(p0,     acc[mi][nj][0]);
                atomicAdd(p0 + 1, acc[mi][nj][1]);
                atomicAdd(p1,     acc[mi][nj][2]);
                atomicAdd(p1 + 1, acc[mi][nj][3]);
            }
        }
    } else {
        #pragma unroll
        for (int mi = 0; mi < 4; mi++) {
            #pragma unroll
            for (int nj = 0; nj < 8; nj++) {
                const int row = row0 + wm0 + mi * 16 + (lane >> 2);
                const int col = col0 + wn0 + nj * 8 + (lane & 3) * 2;
                *(float2*)(C + (size_t)row * N + col)       = make_float2(acc[mi][nj][0], acc[mi][nj][1]);
                *(float2*)(C + (size_t)(row + 8) * N + col) = make_float2(acc[mi][nj][2], acc[mi][nj][3]);
            }
        }
    }
}

// =============== fp32 -> fp16 hi/lo split (row-major) ===========
__global__ void split_rows_h(const float* __restrict__ X,
                             __half* __restrict__ Xh,
                             __half* __restrict__ Xl, int total4)
{
    int i = blockIdx.x * blockDim.x + threadIdx.x;
    if (i >= total4) return;
    float4 v = *(const float4*)(X + (size_t)i * 4);
    __half h[4], l[4];
    float vv[4] = {v.x, v.y, v.z, v.w};
    #pragma unroll
    for (int j = 0; j < 4; j++) {
        h[j] = __float2half_rn(vv[j]);
        l[j] = __float2half_rn(vv[j] - __half2float(h[j]));
    }
    *(uint2*)(Xh + (size_t)i * 4) = *(uint2*)h;
    *(uint2*)(Xl + (size_t)i * 4) = *(uint2*)l;
}

// =============== transpose + fp16 quantize: W[K,N] fp32 -> T [N,K] fp16 =====
__global__ __launch_bounds__(256) void transpose_h(
    const float* __restrict__ W, __half* __restrict__ Th, int Kd, int Nd)
{
    __shared__ float t[64][65];
    const int n0 = blockIdx.x * 64, k0 = blockIdx.y * 64;
    const int tid = threadIdx.x;
    #pragma unroll
    for (int i = 0; i < 4; i++) {
        int it = tid + i * 256;
        int r = it >> 4;
        int c4 = (it & 15) * 4;
        float4 v = *(const float4*)(W + (size_t)(k0 + r) * Nd + n0 + c4);
        t[r][c4] = v.x; t[r][c4 + 1] = v.y; t[r][c4 + 2] = v.z; t[r][c4 + 3] = v.w;
    }
    __syncthreads();
    #pragma unroll
    for (int i = 0; i < 4; i++) {
        int it = tid + i * 256;
        int n = it >> 4;
        int kc = (it & 15) * 4;
        __half h[4];
        #pragma unroll
        for (int j = 0; j < 4; j++) h[j] = __float2half_rn(t[kc + j][n]);
        *(uint2*)(Th + (size_t)(n0 + n) * Kd + k0 + kc) = *(uint2*)h;
    }
}

// =============== RoPE + fp16 hi/lo split (Q) =================================
__global__ void rope_q_h(const float* __restrict__ X,
                         const float* __restrict__ cosT,
                         const float* __restrict__ sinT,
                         __half* __restrict__ Xh,
                         __half* __restrict__ Xl)
{
    int idx = blockIdx.x * blockDim.x + threadIdx.x;
    int total = NT * NH * 32;
    if (idx >= total) return;
    int j = idx & 31;
    int hh = (idx >> 5) % NH;
    int t = idx / (32 * NH);
    int s = t & (SS - 1);
    int d = 2 * j;

    const float* p = X + (size_t)t * QDIM + hh * HD;
    float x0 = p[d], x1 = p[d + 1], y0 = p[d + 64], y1 = p[d + 65];
    const float* cp = cosT + s * HD;
    const float* sp = sinT + s * HD;
    float r0 = x0 * cp[d]      - y0 * sp[d];
    float r1 = x1 * cp[d + 1]  - y1 * sp[d + 1];
    float r2 = y0 * cp[d + 64] + x0 * sp[d + 64];
    float r3 = y1 * cp[d + 65] + x1 * sp[d + 65];

    size_t o0 = (size_t)t * QDIM + hh * HD + d;
    __half h0 = __float2half_rn(r0), h1 = __float2half_rn(r1);
    __half h2 = __float2half_rn(r2), h3 = __float2half_rn(r3);
    __half q0 = __float2half_rn(r0 - __half2float(h0));
    __half q1 = __float2half_rn(r1 - __half2float(h1));
    __half q2 = __float2half_rn(r2 - __half2float(h2));
    __half q3 = __float2half_rn(r3 - __half2float(h3));
    __half hp[2] = {h0, h1};  *(uint32_t*)(Xh + o0) = *(uint32_t*)hp;
    __half lp[2] = {q0, q1};  *(uint32_t*)(Xl + o0) = *(uint32_t*)lp;
    __half hp2[2] = {h2, h3}; *(uint32_t*)(Xh + o0 + 64) = *(uint32_t*)hp2;
    __half lp2[2] = {q2, q3}; *(uint32_t*)(Xl + o0 + 64) = *(uint32_t*)lp2;
}

// =============== RoPE single fp16 (K) ========================================
__global__ void rope_k_h(const float* __restrict__ X,
                         const float* __restrict__ cosT,
                         const float* __restrict__ sinT,
                         __half* __restrict__ Xh)
{
    int idx = blockIdx.x * blockDim.x + threadIdx.x;
    int total = NT * NKV * 32;
    if (idx >= total) return;
    int j = idx & 31;
    int hh = (idx >> 5) % NKV;
    int t = idx / (32 * NKV);
    int s = t & (SS - 1);
    int d = 2 * j;

    const float* p = X + (size_t)t * KDIM + hh * HD;
    float x0 = p[d], x1 = p[d + 1], y0 = p[d + 64], y1 = p[d + 65];
    const float* cp = cosT + s * HD;
    const float* sp = sinT + s * HD;
    float r0 = x0 * cp[d]      - y0 * sp[d];
    float r1 = x1 * cp[d + 1]  - y1 * sp[d + 1];
    float r2 = y0 * cp[d + 64] + x0 * sp[d + 64];
    float r3 = y1 * cp[d + 65] + x1 * sp[d + 65];

    size_t o0 = (size_t)t * KDIM + hh * HD + d;
    __half hp[2]  = {__float2half_rn(r0), __float2half_rn(r1)};
    __half hp2[2] = {__float2half_rn(r2), __float2half_rn(r3)};
    *(uint32_t*)(Xh + o0)      = *(uint32_t*)hp;
    *(uint32_t*)(Xh + o0 + 64) = *(uint32_t*)hp2;
}

// =============== V: fp32 [NT][KDIM] -> transposed fp16 [b][g][d][s] ==========
__global__ __launch_bounds__(256) void v_t_h(const float* __restrict__ V,
                                             __half* __restrict__ Vt)
{
    __shared__ float t[64][65];
    const int c0 = blockIdx.x * 64;
    const int r0 = blockIdx.y * 64;
    const int tid = threadIdx.x;
    #pragma unroll
    for (int i = 0; i < 4; i++) {
        int it = tid + i * 256;
        int r = it >> 4;
        int c4 = (it & 15) * 4;
        float4 v = *(const float4*)(V + (size_t)(r0 + r) * KDIM + c0 + c4);
        t[r][c4] = v.x; t[r][c4 + 1] = v.y; t[r][c4 + 2] = v.z; t[r][c4 + 3] = v.w;
    }
    __syncthreads();
    const int b = r0 >> 11;
    const int sbase = r0 & (SS - 1);
    #pragma unroll
    for (int i = 0; i < 4; i++) {
        int it = tid + i * 256;
        int n = it >> 4;
        int kc = (it & 15) * 4;
        int col = c0 + n;
        int g = col >> 7;
        int d = col & 127;
        __half h[4];
        #pragma unroll
        for (int j = 0; j < 4; j++) h[j] = __float2half_rn(t[kc + j][n]);
        size_t o = ((size_t)((b * NKV + g) * HD) + d) * SS + sbase + kc;
        *(uint2*)(Vt + o) = *(uint2*)h;
    }
}

// ---------------- fp16 2-term flash attention (causal, GQA) -----------------
// smem: Qh 32KB | Ql 32KB | 2 stages x (K 16KB + Vt 16KB) = 128KB
#define ASMEM_BYTES (131072)

__device__ __forceinline__ void attn_load_kv(
    uint32_t st, const __half* Kh, const __half* Vt,
    int b, int g, int kt, int tid)
{
    const int tk0 = b * SS + kt * 64;
    const size_t vrow0 = (size_t)((b * NKV + g) * HD) * SS;
    #pragma unroll 8
    for (int c = tid; c < 2048; c += 256) {
        if (c < 1024) {
            int r = c >> 4, sg = c & 15, half = sg >> 3, sgi = sg & 7;
            const void* src = Kh + (size_t)(tk0 + r) * KDIM + g * HD + half * 64 + sgi * 8;
            uint32_t dst = st + half * 8192 + sw128(r * 128 + sgi * 16);
            cp_async16(dst, src);
        } else {
            int idx = c - 1024;
            int d = idx >> 3, sg = idx & 7;
            const void* src = Vt + vrow0 + (size_t)d * SS + kt * 64 + sg * 8;
            uint32_t dst = st + 16384 + sw128(d * 128 + sg * 16);
            cp_async16(dst, src);
        }
    }
    CP_COMMIT();
}

__global__ __launch_bounds__(256, 1) void attn_mma(
    const __half* __restrict__ Qh, const __half* __restrict__ Ql,
    const __half* __restrict__ Kh, const __half* __restrict__ Vt,
    __half* __restrict__ Oh, __half* __restrict__ Ol)
{
    extern __shared__ char smc[];
    const uint32_t sb = smem_u32(smc);
    const int tid = threadIdx.x, wid = tid >> 5, lane = tid & 31;
    const int bid = blockIdx.x;
    const int qb = 15 - (bid >> 6);     // heavy-first
    const int bh = bid & 63;
    const int b = bh >> 5, h = bh & 31, g = h >> 2;
    const int tok0 = b * SS + qb * 128;
    const int KT = 2 * qb + 2;
    const float SCL = 0.08838834764831845f * 1.4426950408889634f;

    // Q load: hi/lo x 128 rows x 16 chunks = 4096 chunks
    #pragma unroll 4
    for (int c = tid; c < 4096; c += 256) {
        int hl = c >> 11, cc = c & 2047;
        int r = cc >> 4, sg = cc & 15, half = sg >> 3, sgi = sg & 7;
        const __half* base = hl ? Ql : Qh;
        const void* src = base + (size_t)(tok0 + r) * QDIM + h * HD + half * 64 + sgi * 8;
        uint32_t dst = sb + hl * 32768 + half * 16384 + sw128(r * 128 + sgi * 16);
        cp_async16(dst, src);
    }
    attn_load_kv(sb + 65536, Kh, Vt, b, g, 0, tid);

    float o[16][4];
    #pragma unroll
    for (int nd = 0; nd < 16; nd++)
        #pragma unroll
        for (int e = 0; e < 4; e++) o[nd][e] = 0.f;
    float m0 = -1e30f, m1 = -1e30f, l0 = 0.f, l1 = 0.f;

    const int qg0 = qb * 128 + wid * 16 + (lane >> 2);
    const int qg1 = qg0 + 8;

    for (int kt = 0; kt < KT; kt++) {
        CP_WAIT_ALL();
        __syncthreads();
        if (kt + 1 < KT)
            attn_load_kv(sb + 65536 + ((kt + 1) & 1) * 32768, Kh, Vt, b, g, kt + 1, tid);

        const uint32_t st = sb + 65536 + (kt & 1) * 32768;
        const bool skip = kt * 64 > qb * 128 + wid * 16 + 15;

        if (!skip) {
            float s[8][4];
            #pragma unroll
            for (int nj = 0; nj < 8; nj++)
                #pragma unroll
                for (int e = 0; e < 4; e++) s[nj][e] = 0.f;

            #pragma unroll
            for (int k16 = 0; k16 < 8; k16++) {
                const int half = k16 >> 2;
                const int cb = (k16 & 3) * 32 + (lane >> 4) * 16;
                const uint32_t qoff = sw128((wid * 16 + (lane & 15)) * 128 + cb);
                uint32_t ah[4], al[4];
                LDSM4(ah, sb + half * 16384 + qoff);
                LDSM4(al, sb + 32768 + half * 16384 + qoff);
                uint32_t bhf[4][4];
                #pragma unroll
                for (int c = 0; c < 4; c++) {
                    const uint32_t koff = sw128((c * 16 + (lane & 15)) * 128 + cb);
                    LDSM4(bhf[c], st + half * 8192 + koff);
                }
                #pragma unroll
                for (int nj = 0; nj < 8; nj++) {
                    const int np = nj >> 1, h2 = nj & 1;
                    MMAH16816(s[nj], ah, bhf[np][h2], bhf[np][2 + h2]);
                }
                #pragma unroll
                for (int nj = 0; nj < 8; nj++) {
                    const int np = nj >> 1, h2 = nj & 1;
                    MMAH16816(s[nj], al, bhf[np][h2], bhf[np][2 + h2]);
                }
            }

            const bool domask = (kt * 64 + 63) > qg0;
            #pragma unroll
            for (int nj = 0; nj < 8; nj++) {
                #pragma unroll
                for (int e = 0; e < 4; e++) s[nj][e] *= SCL;
                if (domask) {
                    const int kc = kt * 64 + nj * 8 + (lane & 3) * 2;
                    if (kc     > qg0) s[nj][0] = -1e30f;
                    if (kc + 1 > qg0) s[nj][1] = -1e30f;
                    if (kc     > qg1) s[nj][2] = -1e30f;
                    if (kc + 1 > qg1) s[nj][3] = -1e30f;
                }
            }
            float mx0 = -1e30f, mx1 = -1e30f;
            #pragma unroll
            for (int nj = 0; nj < 8; nj++) {
                mx0 = fmaxf(mx0, fmaxf(s[nj][0], s[nj][1]));
                mx1 = fmaxf(mx1, fmaxf(s[nj][2], s[nj][3]));
            }
            mx0 = fmaxf(mx0, __shfl_xor_sync(0xffffffffu, mx0, 1));
            mx0 = fmaxf(mx0, __shfl_xor_sync(0xffffffffu, mx0, 2));
            mx1 = fmaxf(mx1, __shfl_xor_sync(0xffffffffu, mx1, 1));
            mx1 = fmaxf(mx1, __shfl_xor_sync(0xffffffffu, mx1, 2));
            const float nm0 = fmaxf(m0, mx0), nm1 = fmaxf(m1, mx1);
            const float c0 = exp2a(m0 - nm0), c1 = exp2a(m1 - nm1);
            float rs0 = 0.f, rs1 = 0.f;
            #pragma unroll
            for (int nj = 0; nj < 8; nj++) {
                s[nj][0] = exp2a(s[nj][0] - nm0);
                s[nj][1] = exp2a(s[nj][1] - nm0);
                s[nj][2] = exp2a(s[nj][2] - nm1);
                s[nj][3] = exp2a(s[nj][3] - nm1);
                rs0 += s[nj][0] + s[nj][1];
                rs1 += s[nj][2] + s[nj][3];
            }
            rs0 += __shfl_xor_sync(0xffffffffu, rs0, 1);
            rs0 += __shfl_xor_sync(0xffffffffu, rs0, 2);
            rs1 += __shfl_xor_sync(0xffffffffu, rs1, 1);
            rs1 += __shfl_xor_sync(0xffffffffu, rs1, 2);
            m0 = nm0; m1 = nm1;
            l0 = l0 * c0 + rs0;
            l1 = l1 * c1 + rs1;
            #pragma unroll
            for (int nd = 0; nd < 16; nd++) {
                o[nd][0] *= c0; o[nd][1] *= c0;
                o[nd][2] *= c1; o[nd][3] *= c1;
            }

            // P*V: P exact fp16 hi/lo in registers, V single fp16
            #pragma unroll
            for (int j2 = 0; j2 < 4; j2++) {
                const int n0 = 2 * j2, n1 = 2 * j2 + 1;
                uint32_t aPh[4], aPl[4];
                __half2 t0 = __floats2half2_rn(s[n0][0], s[n0][1]);
                __half2 t1 = __floats2half2_rn(s[n0][2], s[n0][3]);
                __half2 t2 = __floats2half2_rn(s[n1][0], s[n1][1]);
                __half2 t3 = __floats2half2_rn(s[n1][2], s[n1][3]);
                aPh[0] = *(uint32_t*)&t0; aPh[1] = *(uint32_t*)&t1;
                aPh[2] = *(uint32_t*)&t2; aPh[3] = *(uint32_t*)&t3;
                __half2 u0 = __floats2half2_rn(s[n0][0] - __low2float(t0),
                                               s[n0][1] - __high2float(t0));
                __half2 u1 = __floats2half2_rn(s[n0][2] - __low2float(t1),
                                               s[n0][3] - __high2float(t1));
                __half2 u2 = __floats2half2_rn(s[n1][0] - __low2float(t2),
                                               s[n1][1] - __high2float(t2));
                __half2 u3 = __floats2half2_rn(s[n1][2] - __low2float(t3),
                                               s[n1][3] - __high2float(t3));
                aPl[0] = *(uint32_t*)&u0; aPl[1] = *(uint32_t*)&u1;
                aPl[2] = *(uint32_t*)&u2; aPl[3] = *(uint32_t*)&u3;

                #pragma unroll
                for (int c = 0; c < 8; c++) {
                    const uint32_t voff = sw128((c * 16 + (lane & 15)) * 128 + j2 * 32 + (lane >> 4) * 16);
                    uint32_t vh[4];
                    LDSM4(vh, st + 16384 + voff);
                    MMAH16816(o[2 * c],     aPh, vh[0], vh[2]);
                    MMAH16816(o[2 * c + 1], aPh, vh[1], vh[3]);
                    MMAH16816(o[2 * c],     aPl, vh[0], vh[2]);
                    MMAH16816(o[2 * c + 1], aPl, vh[1], vh[3]);
                }
            }
        }
    }

    // epilogue: normalize, split to fp16 hi/lo for the Wo fp16 GEMM
    const float il0 = 1.f / l0, il1 = 1.f / l1;
    const int row0g = tok0 + wid * 16 + (lane >> 2);
    #pragma unroll
    for (int nd = 0; nd < 16; nd++) {
        const int col = h * HD + nd * 8 + (lane & 3) * 2;
        float v00 = o[nd][0] * il0, v01 = o[nd][1] * il0;
        float v10 = o[nd][2] * il1, v11 = o[nd][3] * il1;
        __half2 h0 = __floats2half2_rn(v00, v01);
        __half2 h1 = __floats2half2_rn(v10, v11);
        __half2 q0 = __floats2half2_rn(v00 - __low2float(h0), v01 - __high2float(h0));
        __half2 q1 = __floats2half2_rn(v10 - __low2float(h1), v11 - __high2float(h1));
        *(uint32_t*)(Oh + (size_t)row0g * QDIM + col)       = *(uint32_t*)&h0;
        *(uint32_t*)(Ol + (size_t)row0g * QDIM + col)       = *(uint32_t*)&q0;
        *(uint32_t*)(Oh + (size_t)(row0g + 8) * QDIM + col) = *(uint32_t*)&h1;
        *(uint32_t*)(Ol + (size_t)(row0g + 8) * QDIM + col) = *(uint32_t*)&q1;
    }
}

// ---------------- launcher ---------------------------------------------------
extern "C" void kernel_launch(void* const* d_in, const int* in_sizes, int n_in,
                              void* d_out, int out_size)
{
    const float* x    = (const float*)d_in[0];
    const float* cosT = (const float*)d_in[1];
    const float* sinT = (const float*)d_in[2];
    const float* Wq   = (const float*)d_in[3];
    const float* Wk   = (const float*)d_in[4];
    const float* Wv   = (const float*)d_in[5];
    const float* Wo   = (const float*)d_in[6];
    float* out = (float*)d_out;

    float *Q, *K, *V;
    __half *xh, *xl, *Wqh, *Wkh, *Wvh, *Woh, *Ah, *Al;
    __half *Qah, *Qal, *Kah, *Vt;
    cudaGetSymbolAddress((void**)&Q, g_Q);
    cudaGetSymbolAddress((void**)&K, g_K);
    cudaGetSymbolAddress((void**)&V, g_V);
    cudaGetSymbolAddress((void**)&xh, g_xh);
    cudaGetSymbolAddress((void**)&xl, g_xl);
    cudaGetSymbolAddress((void**)&Wqh, g_Wqh);
    cudaGetSymbolAddress((void**)&Wkh, g_Wkh);
    cudaGetSymbolAddress((void**)&Wvh, g_Wvh);
    cudaGetSymbolAddress((void**)&Woh, g_Woh);
    cudaGetSymbolAddress((void**)&Ah, g_Ah);
    cudaGetSymbolAddress((void**)&Al, g_Al);
    cudaGetSymbolAddress((void**)&Qah, g_Qah);
    cudaGetSymbolAddress((void**)&Qal, g_Qal);
    cudaGetSymbolAddress((void**)&Kah, g_Kah);
    cudaGetSymbolAddress((void**)&Vt, g_Vt);

    cudaFuncSetAttribute(gemm_fp16x2, cudaFuncAttributeMaxDynamicSharedMemorySize, GSMEM_BYTES);
    cudaFuncSetAttribute(attn_mma, cudaFuncAttributeMaxDynamicSharedMemorySize, ASMEM_BYTES);

    // zero-init split-K targets (exactly 2 atomic contributors -> deterministic)
    cudaMemsetAsync(Q, 0, (size_t)NT * QDIM * sizeof(float));
    cudaMemsetAsync(out, 0, (size_t)NT * DIM * sizeof(float));

    // conversions
    split_rows_h<<<(NT * DIM / 4 + 255) / 256, 256>>>(x, xh, xl, NT * DIM / 4);
    transpose_h<<<dim3(QDIM / 64, DIM / 64), 256>>>(Wq, Wqh, DIM, QDIM);
    transpose_h<<<dim3(KDIM / 64, DIM / 64), 256>>>(Wk, Wkh, DIM, KDIM);
    transpose_h<<<dim3(KDIM / 64, DIM / 64), 256>>>(Wv, Wvh, DIM, KDIM);
    transpose_h<<<dim3(DIM / 64, QDIM / 64), 256>>>(Wo, Woh, QDIM, DIM);

    // QKV projections (fp16 2-term HMMA; Q with split-K=2)
    gemm_fp16x2<<<dim3(QDIM / 256, NT / 128, 2), 256, GSMEM_BYTES>>>(xh, xl, Wqh, Q, NT, QDIM, DIM);
    gemm_fp16x2<<<dim3(KDIM / 256, NT / 128, 1), 256, GSMEM_BYTES>>>(xh, xl, Wkh, K, NT, KDIM, DIM);
    gemm_fp16x2<<<dim3(KDIM / 256, NT / 128, 1), 256, GSMEM_BYTES>>>(xh, xl, Wvh, V, NT, KDIM, DIM);

    // RoPE + fp16 operands for attention
    rope_q_h<<<(NT * NH * 32 + 255) / 256, 256>>>(Q, cosT, sinT, Qah, Qal);
    rope_k_h<<<(NT * NKV * 32 + 255) / 256, 256>>>(K, cosT, sinT, Kah);
    v_t_h<<<dim3(KDIM / 64, NT / 64), 256>>>(V, Vt);

    // fp16 2-term flash attention -> fp16 hi/lo output
    attn_mma<<<1024, 256, ASMEM_BYTES>>>(Qah, Qal, Kah, Vt, Ah, Al);

    // Output projection (fp16 2-term, split-K=2)
    gemm_fp16x2<<<dim3(DIM / 256, NT / 128, 2), 256, GSMEM_BYTES>>>(Ah, Al, Woh, out, NT, DIM, QDIM);
}